// round 9
// baseline (speedup 1.0000x reference)
#include <cuda_runtime.h>
#include <cuda_fp16.h>
#include <math.h>
#include <stdint.h>

#define NS 8192
#define HHD 512
#define G3 1536
#define EE 128
#define VV 128
#define SSTEPS 32
#define NCTA 128
#define CROWS 64

// smem byte offsets
#define SM_A 0
#define A_SPLIT 66560          // 64*520*2 bytes per split
#define SM_B 133120            // B region: 73728 bytes
#define B_BUF 36864            // fc stage stride (2 splits of 72-pad rows)
#define B_SPL 18432            // 128*72*2
#define B_STG_G 30720          // fused gate stage stride: 3 * 128*80
#define SM_BHN 206848          // 512 floats: b_hh n-gate part
#define SM_SCH 208896          // 64 ints
#define SM_ARGV 209152         // 256 floats
#define SM_ARGI 210176         // 256 ints
#define SMEM_TOT 211200

// ---------------- persistent device scratch ----------------
__device__ float g_gctx[(size_t)NS * G3];    // [n][1536], b_ih (+ b_hh r,z) folded
__device__ float g_fcctx[(size_t)NS * VV];   // [n][128], fc_b folded
__device__ float g_embgi[VV * G3];           // [c][1536]
__device__ float g_fcemb[VV * VV];           // [c][128]
__device__ float g_h[(size_t)NS * HHD];      // h_new staging (fp32)
__device__ __align__(128) __half g_wpack[4 * 16 * 3 * 4096];    // [jt][kc32][gate][n][k] fp16
__device__ __align__(128) __half g_fcpack[8 * 2 * 8192];        // fc panels, hi/lo fp16
__device__ __align__(128) __half g_ctxpack[13 * 8 * 2 * 8192];  // ctx panels, hi/lo fp16

// ---------------- small helpers ----------------
__device__ __forceinline__ uint32_t smem_u32(const void* p) {
    uint32_t a;
    asm("{ .reg .u64 t; cvta.to.shared.u64 t, %1; cvt.u32.u64 %0, t; }" : "=r"(a) : "l"(p));
    return a;
}
__device__ __forceinline__ void ldsm4(uint32_t addr, uint32_t r[4]) {
    asm volatile("ldmatrix.sync.aligned.m8n8.x4.shared.b16 {%0,%1,%2,%3}, [%4];"
        : "=r"(r[0]), "=r"(r[1]), "=r"(r[2]), "=r"(r[3]) : "r"(addr));
}
__device__ __forceinline__ void mma16816(float* c, const uint32_t a[4], const uint32_t b[2]) {
    asm volatile("mma.sync.aligned.m16n8k16.row.col.f32.f16.f16.f32 "
        "{%0,%1,%2,%3}, {%4,%5,%6,%7}, {%8,%9}, {%0,%1,%2,%3};"
        : "+f"(c[0]), "+f"(c[1]), "+f"(c[2]), "+f"(c[3])
        : "r"(a[0]), "r"(a[1]), "r"(a[2]), "r"(a[3]), "r"(b[0]), "r"(b[1]));
}
__device__ __forceinline__ void cp16(uint32_t dst, const void* src) {
    asm volatile("cp.async.cg.shared.global [%0], [%1], 16;" :: "r"(dst), "l"(src));
}
__device__ __forceinline__ void hsplit(float v, unsigned short& h, unsigned short& l) {
    __half hh = __float2half(v);
    __half hl = __float2half(v - __half2float(hh));
    h = __half_as_ushort(hh);
    l = __half_as_ushort(hl);
}

// ---------------- prep kernels ----------------
// gh panels: [jt][kc32][gate][n 0..127][k 0..31], single fp16
__global__ void pack_w_kernel(const float* __restrict__ W_hh) {
    int idx = blockIdx.x * 256 + threadIdx.x;
    if (idx >= G3 * HHD) return;
    int R = idx >> 9, C = idx & 511;
    int g = R >> 9, j = R & 511, jt = j >> 7, n = j & 127;
    int kc = C >> 5, k = C & 31;
    size_t dst = ((size_t)(jt * 16 + kc) * 3 + g) * 4096 + n * 32 + k;
    g_wpack[dst] = __float2half(W_hh[idx]);
}

__global__ void pack_fc_kernel(const float* __restrict__ fc_W) {
    int idx = blockIdx.x * 256 + threadIdx.x;
    if (idx >= VV * HHD) return;
    int v = idx >> 9, C = idx & 511;
    int kc = C >> 6, k = C & 63;
    unsigned short h, l;
    hsplit(fc_W[(size_t)v * 1152 + 640 + C], h, l);
    size_t base = ((size_t)kc * 2) * 8192 + v * 64 + k;
    g_fcpack[base] = __ushort_as_half(h);
    g_fcpack[base + 8192] = __ushort_as_half(l);
}

// pack W_ih[:,128:640] (rows -> tiles 0..11) and fc_W[:,128:640] (tile 12)
__global__ void pack_ctx_kernel(const float* __restrict__ W_ih,
                                const float* __restrict__ fc_W) {
    int idx = blockIdx.x * 256 + threadIdx.x;
    if (idx >= 1664 * 512) return;
    int r = idx >> 9, k = idx & 511;
    float w = (r < G3) ? W_ih[(size_t)r * 640 + 128 + k]
                       : fc_W[(size_t)(r - G3) * 1152 + 128 + k];
    int tl = r >> 7, n = r & 127, kc = k >> 6, kk = k & 63;
    unsigned short h, l;
    hsplit(w, h, l);
    size_t base = ((size_t)(tl * 8 + kc) * 2) * 8192 + n * 64 + kk;
    g_ctxpack[base] = __ushort_as_half(h);
    g_ctxpack[base + 8192] = __ushort_as_half(l);
}

__global__ __launch_bounds__(128)
void emb_kernel(const float* __restrict__ emb_table,
                const float* __restrict__ W_ih,
                const float* __restrict__ fc_W) {
    __shared__ float er[EE];
    int c = blockIdx.y;
    int tx = threadIdx.x;
    er[tx] = emb_table[c * EE + tx];
    __syncthreads();
    int col = blockIdx.x * 128 + tx;   // [0, 1664)
    const float* brow = (col < G3) ? (W_ih + (size_t)col * 640)
                                   : (fc_W + (size_t)(col - G3) * 1152);
    float acc = 0.f;
#pragma unroll 8
    for (int e = 0; e < EE; e += 4) {
        float4 b = *reinterpret_cast<const float4*>(brow + e);
        acc += er[e] * b.x + er[e + 1] * b.y + er[e + 2] * b.z + er[e + 3] * b.w;
    }
    if (col < G3) g_embgi[c * G3 + col] = acc;
    else          g_fcemb[c * VV + (col - G3)] = acc;
}

// ---------------- HMMA machinery ----------------
// fused 3-gate chunk copy: 24KB = 1536 x 16B; smem rows padded 64B->80B
__device__ __forceinline__ void copy3(uint32_t smb, int buf, const __half* src, int t) {
    uint32_t dbase = smb + SM_B + buf * B_STG_G;
    const char* s = (const char*)src;
#pragma unroll
    for (int i = 0; i < 6; ++i) {
        int u = t + i * 256;                   // 0..1535
        int gate = u >> 9, rem = u & 511, n = rem >> 2, c = rem & 3;
        cp16(dbase + gate * 10240 + n * 80 + c * 16, s + (size_t)u * 16);
    }
}
// fc split copy (72-pad rows, 16KB per split)
__device__ __forceinline__ void copy_split(uint32_t dbase, const __half* src, int t) {
    const char* s = (const char*)src;
#pragma unroll
    for (int i = 0; i < 4; ++i) {
        int u = t + i * 256;
        int n = u >> 3, c = u & 7;
        cp16(dbase + n * 144 + c * 16, s + (size_t)u * 16);
    }
}
__device__ __forceinline__ void copy_chunk2(uint32_t smb, int buf, const __half* src, int t) {
    copy_split(smb + SM_B + buf * B_BUF, src, t);
    copy_split(smb + SM_B + buf * B_BUF + B_SPL, src + 8192, t);
}

// fused gates: 32-K chunk, A loaded once, 3 gate B-tiles, 2 products each
__device__ __forceinline__ void mma_chunk3(uint32_t smb, int buf, int kc,
                                           int wy, int wx, int lane,
                                           float* accr, float* accz, float* accn) {
    uint32_t abase = smb + SM_A;
    uint32_t bb = smb + SM_B + buf * B_STG_G;
    int arow = wy * 32 + (lane & 7) + ((lane >> 3) & 1) * 8;
    int akoff = ((lane >> 4) & 1) * 8;
    int brow = wx * 32 + ((lane >> 4) & 1) * 8 + (lane & 7);
    int bkoff = ((lane >> 3) & 1) * 8;
#pragma unroll
    for (int ks = 0; ks < 2; ++ks) {
        int kA = kc * 32 + ks * 16 + akoff;
        uint32_t ahi[2][4], alo[2][4];
#pragma unroll
        for (int mt = 0; mt < 2; ++mt) {
            uint32_t ad = abase + ((arow + mt * 16) * 520 + kA) * 2;
            ldsm4(ad, ahi[mt]);
            ldsm4(ad + A_SPLIT, alo[mt]);
        }
#pragma unroll
        for (int gate = 0; gate < 3; ++gate) {
            uint32_t bg = bb + gate * 10240;
            uint32_t b[4][2];
#pragma unroll
            for (int p = 0; p < 2; ++p) {
                uint32_t bd = bg + (brow + p * 16) * 80 + (ks * 16 + bkoff) * 2;
                uint32_t r4[4];
                ldsm4(bd, r4);
                b[2 * p][0] = r4[0]; b[2 * p][1] = r4[1];
                b[2 * p + 1][0] = r4[2]; b[2 * p + 1][1] = r4[3];
            }
            float* acc = (gate == 0) ? accr : (gate == 1) ? accz : accn;
#pragma unroll
            for (int mt = 0; mt < 2; ++mt)
#pragma unroll
                for (int nt = 0; nt < 4; ++nt) {
                    float* c = acc + (mt * 4 + nt) * 4;
                    mma16816(c, ahi[mt], b[nt]);
                    mma16816(c, alo[mt], b[nt]);
                }
        }
    }
}

// fc/ctx: 64-K chunk, A hi/lo x B hi/lo -> 3 products
__device__ __forceinline__ void mma_chunk_f(uint32_t smb, int buf, int kc,
                                            int wy, int wx, int lane, float* acc) {
    uint32_t abase = smb + SM_A;
    uint32_t bbase = smb + SM_B + buf * B_BUF;
    int arow = wy * 32 + (lane & 7) + ((lane >> 3) & 1) * 8;
    int akoff = ((lane >> 4) & 1) * 8;
    int brow = wx * 32 + ((lane >> 4) & 1) * 8 + (lane & 7);
    int bkoff = ((lane >> 3) & 1) * 8;
#pragma unroll
    for (int ks = 0; ks < 4; ++ks) {
        int kA = kc * 64 + ks * 16 + akoff;
        uint32_t ahi[2][4], alo[2][4];
#pragma unroll
        for (int mt = 0; mt < 2; ++mt) {
            uint32_t ad = abase + ((arow + mt * 16) * 520 + kA) * 2;
            ldsm4(ad, ahi[mt]);
            ldsm4(ad + A_SPLIT, alo[mt]);
        }
        uint32_t bhi[4][2], blo[4][2];
#pragma unroll
        for (int p = 0; p < 2; ++p) {
            uint32_t bd = bbase + ((brow + p * 16) * 72 + ks * 16 + bkoff) * 2;
            uint32_t r4[4];
            ldsm4(bd, r4);
            bhi[2 * p][0] = r4[0]; bhi[2 * p][1] = r4[1];
            bhi[2 * p + 1][0] = r4[2]; bhi[2 * p + 1][1] = r4[3];
            ldsm4(bd + B_SPL, r4);
            blo[2 * p][0] = r4[0]; blo[2 * p][1] = r4[1];
            blo[2 * p + 1][0] = r4[2]; blo[2 * p + 1][1] = r4[3];
        }
#pragma unroll
        for (int mt = 0; mt < 2; ++mt)
#pragma unroll
            for (int nt = 0; nt < 4; ++nt) {
                float* c = acc + (mt * 4 + nt) * 4;
                mma16816(c, ahi[mt], bhi[nt]);
                mma16816(c, ahi[mt], blo[nt]);
                mma16816(c, alo[mt], bhi[nt]);
            }
    }
}

__device__ __forceinline__ void compute_tile_f(const __half* Bsrc, float* acc,
                                               uint32_t smb, int wy, int wx, int lane, int t) {
#pragma unroll
    for (int i = 0; i < 32; ++i) acc[i] = 0.f;
    copy_chunk2(smb, 0, Bsrc, t);
    asm volatile("cp.async.commit_group;" ::: "memory");
#pragma unroll 1
    for (int kc = 0; kc < 8; ++kc) {
        if (kc < 7) {
            copy_chunk2(smb, (kc + 1) & 1, Bsrc + (size_t)(kc + 1) * 16384, t);
            asm volatile("cp.async.commit_group;" ::: "memory");
            asm volatile("cp.async.wait_group 1;" ::: "memory");
        } else {
            asm volatile("cp.async.wait_group 0;" ::: "memory");
        }
        __syncthreads();
        mma_chunk_f(smb, kc & 1, kc, wy, wx, lane, acc);
        __syncthreads();
    }
}

__device__ __forceinline__ void packA(char* sm, const float* __restrict__ src, int t) {
#pragma unroll 4
    for (int i = 0; i < 32; ++i) {
        int idx = t + i * 256;                 // 8192 float4
        int r = idx >> 7, kq = (idx & 127) * 4;
        float4 v = *(const float4*)(src + (size_t)r * HHD + kq);
        unsigned short h0, l0, h1, l1, h2, l2, h3, l3;
        hsplit(v.x, h0, l0); hsplit(v.y, h1, l1);
        hsplit(v.z, h2, l2); hsplit(v.w, h3, l3);
        char* d = sm + SM_A + (r * 520 + kq) * 2;
        *(uint32_t*)d = (uint32_t)h0 | ((uint32_t)h1 << 16);
        *(uint32_t*)(d + 4) = (uint32_t)h2 | ((uint32_t)h3 << 16);
        *(uint32_t*)(d + A_SPLIT) = (uint32_t)l0 | ((uint32_t)l1 << 16);
        *(uint32_t*)(d + A_SPLIT + 4) = (uint32_t)l2 | ((uint32_t)l3 << 16);
    }
}

// ---------------- ctx via HMMA: gctx/fcctx = enc @ W[:,128:640].T + bias ----------------
__global__ __launch_bounds__(256, 1)
void ctx_mma_kernel(const float* __restrict__ enc, const float* __restrict__ b_ih,
                    const float* __restrict__ b_hh, const float* __restrict__ fc_b) {
    extern __shared__ char smraw[];
    char* sm = smraw;
    uint32_t smb = smem_u32(sm);
    const int t = threadIdx.x, lane = t & 31, warp = t >> 5;
    const int wy = warp >> 2, wx = warp & 3;
    const int cta = blockIdx.x;

    packA(sm, enc + (size_t)cta * CROWS * HHD, t);
    __syncthreads();
    float acc[32];
#pragma unroll 1
    for (int tl = 0; tl < 13; ++tl) {
        compute_tile_f(g_ctxpack + (size_t)tl * 8 * 16384, acc, smb, wy, wx, lane, t);
#pragma unroll
        for (int mt = 0; mt < 2; ++mt)
#pragma unroll
            for (int nt = 0; nt < 4; ++nt)
#pragma unroll
                for (int hh = 0; hh < 2; ++hh) {
                    int row = wy * 32 + mt * 16 + (lane >> 2) + hh * 8;
                    int ng = cta * CROWS + row;
                    int jcol = wx * 32 + nt * 8 + (lane & 3) * 2;
                    int base = (mt * 4 + nt) * 4 + hh * 2;
                    if (tl < 12) {
                        int j = tl * 128 + jcol;
                        float2 bi = *(const float2*)(b_ih + j);
                        float b0 = bi.x, b1 = bi.y;
                        if (j < 1024) {
                            float2 bh = *(const float2*)(b_hh + j);
                            b0 += bh.x; b1 += bh.y;
                        }
                        float2 v;
                        v.x = acc[base] + b0;
                        v.y = acc[base + 1] + b1;
                        *(float2*)(g_gctx + (size_t)ng * G3 + j) = v;
                    } else {
                        float2 fb = *(const float2*)(fc_b + jcol);
                        float2 v;
                        v.x = acc[base] + fb.x;
                        v.y = acc[base + 1] + fb.y;
                        *(float2*)(g_fcctx + (size_t)ng * VV + jcol) = v;
                    }
                }
    }
}

// ---------------- persistent decode kernel ----------------
__global__ __launch_bounds__(256, 1)
void decode_kernel(const float* __restrict__ encoded, const int* __restrict__ init_char,
                   const float* __restrict__ b_hh, float* __restrict__ out) {
    extern __shared__ char smraw[];
    char* sm = smraw;
    uint32_t smb = smem_u32(sm);
    const int t = threadIdx.x, lane = t & 31, warp = t >> 5;
    const int wy = warp >> 2, wx = warp & 3;
    const int cta = blockIdx.x;
    int* sch = (int*)(sm + SM_SCH);
    float* sbhn = (float*)(sm + SM_BHN);
    float* sargv = (float*)(sm + SM_ARGV);
    int* sargi = (int*)(sm + SM_ARGI);

    for (int i = t; i < 512; i += 256) sbhn[i] = b_hh[1024 + i];
    if (t < CROWS) sch[t] = init_char[cta * CROWS + t];
    packA(sm, encoded + (size_t)cta * CROWS * HHD, t);
    __syncthreads();

    for (int step = 0; step < SSTEPS; ++step) {
        float accr[32], accz[32], accn[32];
#pragma unroll 1
        for (int jt = 0; jt < 4; ++jt) {
#pragma unroll
            for (int i = 0; i < 32; ++i) { accr[i] = 0.f; accz[i] = 0.f; accn[i] = 0.f; }
            const __half* base = g_wpack + (size_t)jt * 16 * 12288;
            copy3(smb, 0, base, t);
            asm volatile("cp.async.commit_group;" ::: "memory");
#pragma unroll 1
            for (int kc = 0; kc < 16; ++kc) {
                if (kc < 15) {
                    copy3(smb, (kc + 1) & 1, base + (size_t)(kc + 1) * 12288, t);
                    asm volatile("cp.async.commit_group;" ::: "memory");
                    asm volatile("cp.async.wait_group 1;" ::: "memory");
                } else {
                    asm volatile("cp.async.wait_group 0;" ::: "memory");
                }
                __syncthreads();
                mma_chunk3(smb, kc & 1, kc, wy, wx, lane, accr, accz, accn);
                __syncthreads();
            }
            // ---- gate epilogue for this j-tile ----
#pragma unroll
            for (int mt = 0; mt < 2; ++mt)
#pragma unroll
                for (int nt = 0; nt < 4; ++nt)
#pragma unroll
                    for (int hh = 0; hh < 2; ++hh) {
                        int row = wy * 32 + mt * 16 + (lane >> 2) + hh * 8;
                        int jcol = jt * 128 + wx * 32 + nt * 8 + (lane & 3) * 2;
                        int ng = cta * CROWS + row;
                        int cc = sch[row];
                        const float* gp = g_gctx + (size_t)ng * G3 + jcol;
                        const float* ep = g_embgi + (size_t)cc * G3 + jcol;
                        float2 gr = *(const float2*)gp;
                        float2 gz = *(const float2*)(gp + 512);
                        float2 gn = *(const float2*)(gp + 1024);
                        float2 er = *(const float2*)ep;
                        float2 ez = *(const float2*)(ep + 512);
                        float2 en = *(const float2*)(ep + 1024);
                        const char* ha = sm + SM_A + (row * 520 + jcol) * 2;
                        __half2 hv = *(const __half2*)ha;
                        __half2 lv = *(const __half2*)(ha + A_SPLIT);
                        float ho0 = __half2float(__low2half(hv)) + __half2float(__low2half(lv));
                        float ho1 = __half2float(__high2half(hv)) + __half2float(__high2half(lv));
                        int base2 = (mt * 4 + nt) * 4 + hh * 2;
                        float pr0 = gr.x + er.x + accr[base2];
                        float pr1 = gr.y + er.y + accr[base2 + 1];
                        float pz0 = gz.x + ez.x + accz[base2];
                        float pz1 = gz.y + ez.y + accz[base2 + 1];
                        float hn0 = accn[base2] + sbhn[jcol];
                        float hn1 = accn[base2 + 1] + sbhn[jcol + 1];
                        float r0 = 1.f / (1.f + expf(-pr0));
                        float r1 = 1.f / (1.f + expf(-pr1));
                        float z0 = 1.f / (1.f + expf(-pz0));
                        float z1 = 1.f / (1.f + expf(-pz1));
                        float n0 = tanhf(gn.x + en.x + r0 * hn0);
                        float n1 = tanhf(gn.y + en.y + r1 * hn1);
                        float2 hnew;
                        hnew.x = (1.f - z0) * n0 + z0 * ho0;
                        hnew.y = (1.f - z1) * n1 + z1 * ho1;
                        *(float2*)(g_h + (size_t)ng * HHD + jcol) = hnew;
                    }
        }
        __syncthreads();                       // g_h writes visible; A reads done
        packA(sm, g_h + (size_t)cta * CROWS * HHD, t);   // A <- h_new
        __syncthreads();

        // ---- fc GEMM (full 3-product fp16: argmax-critical) ----
        compute_tile_f(g_fcpack, accr, smb, wy, wx, lane, t);

        // ---- fc epilogue: logits, out, argmax ----
        float best[4]; int bidx[4];
#pragma unroll
        for (int s = 0; s < 4; ++s) { best[s] = -1e30f; bidx[s] = 0; }
#pragma unroll
        for (int mt = 0; mt < 2; ++mt)
#pragma unroll
            for (int hh = 0; hh < 2; ++hh) {
                int slot = mt * 2 + hh;
                int row = wy * 32 + mt * 16 + (lane >> 2) + hh * 8;
                int ng = cta * CROWS + row;
                int cc = sch[row];
#pragma unroll
                for (int nt = 0; nt < 4; ++nt) {
                    int v = wx * 32 + nt * 8 + (lane & 3) * 2;
                    int base2 = (mt * 4 + nt) * 4 + hh * 2;
                    float2 fc = *(const float2*)(g_fcctx + (size_t)ng * VV + v);
                    float2 fe = *(const float2*)(g_fcemb + (size_t)cc * VV + v);
                    float p0 = accr[base2] + fc.x + fe.x;
                    float p1 = accr[base2 + 1] + fc.y + fe.y;
                    float2 pv; pv.x = p0; pv.y = p1;
                    *(float2*)(out + ((size_t)ng * SSTEPS + step) * VV + v) = pv;
                    if (p0 > best[slot]) { best[slot] = p0; bidx[slot] = v; }
                    if (p1 > best[slot]) { best[slot] = p1; bidx[slot] = v + 1; }
                }
            }
#pragma unroll
        for (int s = 0; s < 4; ++s) {
#pragma unroll
            for (int off = 1; off <= 2; off <<= 1) {
                float ov = __shfl_xor_sync(0xffffffffu, best[s], off);
                int oi = __shfl_xor_sync(0xffffffffu, bidx[s], off);
                if (ov > best[s] || (ov == best[s] && oi < bidx[s])) { best[s] = ov; bidx[s] = oi; }
            }
        }
        if ((lane & 3) == 0) {
#pragma unroll
            for (int s = 0; s < 4; ++s) {
                int row = wy * 32 + (s >> 1) * 16 + (lane >> 2) + (s & 1) * 8;
                sargv[row * 4 + wx] = best[s];
                sargi[row * 4 + wx] = bidx[s];
            }
        }
        __syncthreads();
        if (t < CROWS) {
            float bv = sargv[t * 4]; int bi = sargi[t * 4];
#pragma unroll
            for (int wxi = 1; wxi < 4; ++wxi) {
                float ov = sargv[t * 4 + wxi]; int oi = sargi[t * 4 + wxi];
                if (ov > bv || (ov == bv && oi < bi)) { bv = ov; bi = oi; }
            }
            sch[t] = bi;
        }
        __syncthreads();
    }
}

// ---------------------------------------------------------------------------
extern "C" void kernel_launch(void* const* d_in, const int* in_sizes, int n_in,
                              void* d_out, int out_size) {
    const float *encoded = 0, *emb_table = 0, *W_ih = 0, *W_hh = 0,
                *b_ih = 0, *b_hh = 0, *fc_W = 0, *fc_b = 0;
    const int* init_char = 0;
    for (int i = 0; i < n_in; ++i) {
        switch (in_sizes[i]) {
            case 8192 * 512:  encoded   = (const float*)d_in[i]; break;
            case 8192:        init_char = (const int*)d_in[i];   break;
            case 128 * 128:   emb_table = (const float*)d_in[i]; break;
            case 1536 * 640:  W_ih      = (const float*)d_in[i]; break;
            case 1536 * 512:  W_hh      = (const float*)d_in[i]; break;
            case 1536:        if (!b_ih) b_ih = (const float*)d_in[i];
                              else       b_hh = (const float*)d_in[i]; break;
            case 128 * 1152:  fc_W      = (const float*)d_in[i]; break;
            case 128:         fc_b      = (const float*)d_in[i]; break;
            default: break;
        }
    }
    float* out = (float*)d_out;

    cudaFuncSetAttribute(ctx_mma_kernel, cudaFuncAttributeMaxDynamicSharedMemorySize, SMEM_TOT);
    cudaFuncSetAttribute(decode_kernel, cudaFuncAttributeMaxDynamicSharedMemorySize, SMEM_TOT);

    pack_w_kernel<<<(G3 * HHD + 255) / 256, 256>>>(W_hh);
    pack_fc_kernel<<<(VV * HHD + 255) / 256, 256>>>(fc_W);
    pack_ctx_kernel<<<(1664 * 512 + 255) / 256, 256>>>(W_ih, fc_W);
    emb_kernel<<<dim3(13, 128), 128>>>(emb_table, W_ih, fc_W);
    ctx_mma_kernel<<<NCTA, 256, SMEM_TOT>>>(encoded, b_ih, b_hh, fc_b);
    decode_kernel<<<NCTA, 256, SMEM_TOT>>>(encoded, init_char, b_hh, out);
}

// round 10
// speedup vs baseline: 1.0882x; 1.0882x over previous
#include <cuda_runtime.h>
#include <cuda_fp16.h>
#include <math.h>
#include <stdint.h>

#define NS 8192
#define HHD 512
#define G3 1536
#define EE 128
#define VV 128
#define SSTEPS 32
#define NCTA 128
#define CROWS 64

// smem byte offsets
#define SM_A 0
#define A_SPLIT 66560          // 64*520*2 bytes per split
#define SM_B 133120            // B region: 73728 bytes
#define B_STG 18432            // gh stage stride (3 stages = 55296)
#define B_BUF 36864            // fc stage stride (2 stages)
#define B_SPL 18432            // fc split stride within stage
#define SM_BHN 206848          // 512 floats: b_hh n-gate part
#define SM_SCH 208896          // 64 ints
#define SM_ARGV 209152         // 256 floats
#define SM_ARGI 210176         // 256 ints
#define SMEM_TOT 211200

// ---------------- persistent device scratch ----------------
__device__ float g_gctx[(size_t)NS * G3];    // [n][1536], b_ih (+ b_hh r,z) folded
__device__ float g_fcctx[(size_t)NS * VV];   // [n][128], fc_b folded
__device__ float g_embgi[VV * G3];           // [c][1536]
__device__ float g_fcemb[VV * VV];           // [c][128]
__device__ float g_h[(size_t)NS * HHD];      // h_new staging (fp32)
__device__ __align__(128) __half g_wpack[12 * 8 * 8192];        // gh panels [tile][kc], single fp16
__device__ __align__(128) __half g_fcpack[8 * 2 * 8192];        // fc panels, hi/lo fp16
__device__ __align__(128) __half g_ctxpack[13 * 8 * 2 * 8192];  // ctx panels, hi/lo fp16

// ---------------- small helpers ----------------
__device__ __forceinline__ uint32_t smem_u32(const void* p) {
    uint32_t a;
    asm("{ .reg .u64 t; cvta.to.shared.u64 t, %1; cvt.u32.u64 %0, t; }" : "=r"(a) : "l"(p));
    return a;
}
__device__ __forceinline__ void ldsm4(uint32_t addr, uint32_t r[4]) {
    asm volatile("ldmatrix.sync.aligned.m8n8.x4.shared.b16 {%0,%1,%2,%3}, [%4];"
        : "=r"(r[0]), "=r"(r[1]), "=r"(r[2]), "=r"(r[3]) : "r"(addr));
}
__device__ __forceinline__ void mma16816(float* c, const uint32_t a[4], const uint32_t b[2]) {
    asm volatile("mma.sync.aligned.m16n8k16.row.col.f32.f16.f16.f32 "
        "{%0,%1,%2,%3}, {%4,%5,%6,%7}, {%8,%9}, {%0,%1,%2,%3};"
        : "+f"(c[0]), "+f"(c[1]), "+f"(c[2]), "+f"(c[3])
        : "r"(a[0]), "r"(a[1]), "r"(a[2]), "r"(a[3]), "r"(b[0]), "r"(b[1]));
}
__device__ __forceinline__ void cp16(uint32_t dst, const void* src) {
    asm volatile("cp.async.cg.shared.global [%0], [%1], 16;" :: "r"(dst), "l"(src));
}
__device__ __forceinline__ void hsplit(float v, unsigned short& h, unsigned short& l) {
    __half hh = __float2half(v);
    __half hl = __float2half(v - __half2float(hh));
    h = __half_as_ushort(hh);
    l = __half_as_ushort(hl);
}
__device__ __forceinline__ float fast_sigmoid(float x) {
    return __fdividef(1.f, 1.f + __expf(-x));
}
__device__ __forceinline__ float fast_tanh(float y) {
    float a = fabsf(y);
    float e = __expf(-2.f * a);
    return copysignf(__fdividef(1.f - e, 1.f + e), y);
}

// ---------------- prep kernels ----------------
// gh panels: [tile = jt*3+g][kc] of 8192 halves, single fp16
__global__ void pack_w_kernel(const float* __restrict__ W_hh) {
    int idx = blockIdx.x * 256 + threadIdx.x;
    if (idx >= G3 * HHD) return;
    int R = idx >> 9, C = idx & 511;
    int g = R >> 9, rem = R & 511, jt = rem >> 7, n = rem & 127;
    int kc = C >> 6, k = C & 63;
    int tile = jt * 3 + g;
    size_t base = (size_t)(tile * 8 + kc) * 8192 + n * 64 + k;
    g_wpack[base] = __float2half(W_hh[idx]);
}

__global__ void pack_fc_kernel(const float* __restrict__ fc_W) {
    int idx = blockIdx.x * 256 + threadIdx.x;
    if (idx >= VV * HHD) return;
    int v = idx >> 9, C = idx & 511;
    int kc = C >> 6, k = C & 63;
    unsigned short h, l;
    hsplit(fc_W[(size_t)v * 1152 + 640 + C], h, l);
    size_t base = ((size_t)kc * 2) * 8192 + v * 64 + k;
    g_fcpack[base] = __ushort_as_half(h);
    g_fcpack[base + 8192] = __ushort_as_half(l);
}

// pack W_ih[:,128:640] (rows -> tiles 0..11) and fc_W[:,128:640] (tile 12)
__global__ void pack_ctx_kernel(const float* __restrict__ W_ih,
                                const float* __restrict__ fc_W) {
    int idx = blockIdx.x * 256 + threadIdx.x;
    if (idx >= 1664 * 512) return;
    int r = idx >> 9, k = idx & 511;
    float w = (r < G3) ? W_ih[(size_t)r * 640 + 128 + k]
                       : fc_W[(size_t)(r - G3) * 1152 + 128 + k];
    int tl = r >> 7, n = r & 127, kc = k >> 6, kk = k & 63;
    unsigned short h, l;
    hsplit(w, h, l);
    size_t base = ((size_t)(tl * 8 + kc) * 2) * 8192 + n * 64 + kk;
    g_ctxpack[base] = __ushort_as_half(h);
    g_ctxpack[base + 8192] = __ushort_as_half(l);
}

__global__ __launch_bounds__(128)
void emb_kernel(const float* __restrict__ emb_table,
                const float* __restrict__ W_ih,
                const float* __restrict__ fc_W) {
    __shared__ float er[EE];
    int c = blockIdx.y;
    int tx = threadIdx.x;
    er[tx] = emb_table[c * EE + tx];
    __syncthreads();
    int col = blockIdx.x * 128 + tx;   // [0, 1664)
    const float* brow = (col < G3) ? (W_ih + (size_t)col * 640)
                                   : (fc_W + (size_t)(col - G3) * 1152);
    float acc = 0.f;
#pragma unroll 8
    for (int e = 0; e < EE; e += 4) {
        float4 b = *reinterpret_cast<const float4*>(brow + e);
        acc += er[e] * b.x + er[e + 1] * b.y + er[e + 2] * b.z + er[e + 3] * b.w;
    }
    if (col < G3) g_embgi[c * G3 + col] = acc;
    else          g_fcemb[c * VV + (col - G3)] = acc;
}

// ---------------- HMMA machinery ----------------
// one 16KB gh chunk into a gh stage (144B-pad rows)
__device__ __forceinline__ void copy_g(uint32_t smb, int stage, const __half* src, int t) {
    uint32_t dbase = smb + SM_B + stage * B_STG;
    const char* s = (const char*)src;
#pragma unroll
    for (int i = 0; i < 4; ++i) {
        int u = t + i * 256;
        int n = u >> 3, c = u & 7;
        cp16(dbase + n * 144 + c * 16, s + (size_t)u * 16);
    }
}
// fc split copy
__device__ __forceinline__ void copy_split(uint32_t dbase, const __half* src, int t) {
    const char* s = (const char*)src;
#pragma unroll
    for (int i = 0; i < 4; ++i) {
        int u = t + i * 256;
        int n = u >> 3, c = u & 7;
        cp16(dbase + n * 144 + c * 16, s + (size_t)u * 16);
    }
}
__device__ __forceinline__ void copy_chunk2(uint32_t smb, int buf, const __half* src, int t) {
    copy_split(smb + SM_B + buf * B_BUF, src, t);
    copy_split(smb + SM_B + buf * B_BUF + B_SPL, src + 8192, t);
}

// gh: B single fp16, A hi/lo -> 2 products; 64-K chunk
__device__ __forceinline__ void mma_chunk_g(uint32_t smb, int stage, int kc,
                                            int wy, int wx, int lane, float* acc) {
    uint32_t abase = smb + SM_A;
    uint32_t bbase = smb + SM_B + stage * B_STG;
    int arow = wy * 32 + (lane & 7) + ((lane >> 3) & 1) * 8;
    int akoff = ((lane >> 4) & 1) * 8;
    int brow = wx * 32 + ((lane >> 4) & 1) * 8 + (lane & 7);
    int bkoff = ((lane >> 3) & 1) * 8;
#pragma unroll
    for (int ks = 0; ks < 4; ++ks) {
        int kA = kc * 64 + ks * 16 + akoff;
        uint32_t ahi[2][4], alo[2][4];
#pragma unroll
        for (int mt = 0; mt < 2; ++mt) {
            uint32_t ad = abase + ((arow + mt * 16) * 520 + kA) * 2;
            ldsm4(ad, ahi[mt]);
            ldsm4(ad + A_SPLIT, alo[mt]);
        }
        uint32_t b[4][2];
#pragma unroll
        for (int p = 0; p < 2; ++p) {
            uint32_t bd = bbase + ((brow + p * 16) * 72 + ks * 16 + bkoff) * 2;
            uint32_t r4[4];
            ldsm4(bd, r4);
            b[2 * p][0] = r4[0]; b[2 * p][1] = r4[1];
            b[2 * p + 1][0] = r4[2]; b[2 * p + 1][1] = r4[3];
        }
#pragma unroll
        for (int mt = 0; mt < 2; ++mt)
#pragma unroll
            for (int nt = 0; nt < 4; ++nt) {
                float* c = acc + (mt * 4 + nt) * 4;
                mma16816(c, ahi[mt], b[nt]);
                mma16816(c, alo[mt], b[nt]);
            }
    }
}

// one gate tile (8 chunks) within the continuous 96-chunk gh stream.
// u0 = global chunk index of this tile's first chunk. Single sync per chunk,
// 3-stage ring, prefetch distance 2 (copy issued AFTER the sync so stage
// (u+2)%3 cannot collide with in-flight mma of chunk u-1).
__device__ __forceinline__ void gate_tile(float* acc, int u0, uint32_t smb,
                                          int wy, int wx, int lane, int t) {
#pragma unroll
    for (int i = 0; i < 32; ++i) acc[i] = 0.f;
#pragma unroll 1
    for (int kc = 0; kc < 8; ++kc) {
        int u = u0 + kc;
        if (u == 95) asm volatile("cp.async.wait_group 0;" ::: "memory");
        else         asm volatile("cp.async.wait_group 1;" ::: "memory");
        __syncthreads();
        int un = u + 2;
        if (un < 96) {
            copy_g(smb, un % 3, g_wpack + (size_t)un * 8192, t);
            asm volatile("cp.async.commit_group;" ::: "memory");
        }
        mma_chunk_g(smb, u % 3, kc, wy, wx, lane, acc);
    }
}

// fc/ctx: 64-K chunk, A hi/lo x B hi/lo -> 3 products (round-8, 2-stage)
__device__ __forceinline__ void mma_chunk_f(uint32_t smb, int buf, int kc,
                                            int wy, int wx, int lane, float* acc) {
    uint32_t abase = smb + SM_A;
    uint32_t bbase = smb + SM_B + buf * B_BUF;
    int arow = wy * 32 + (lane & 7) + ((lane >> 3) & 1) * 8;
    int akoff = ((lane >> 4) & 1) * 8;
    int brow = wx * 32 + ((lane >> 4) & 1) * 8 + (lane & 7);
    int bkoff = ((lane >> 3) & 1) * 8;
#pragma unroll
    for (int ks = 0; ks < 4; ++ks) {
        int kA = kc * 64 + ks * 16 + akoff;
        uint32_t ahi[2][4], alo[2][4];
#pragma unroll
        for (int mt = 0; mt < 2; ++mt) {
            uint32_t ad = abase + ((arow + mt * 16) * 520 + kA) * 2;
            ldsm4(ad, ahi[mt]);
            ldsm4(ad + A_SPLIT, alo[mt]);
        }
        uint32_t bhi[4][2], blo[4][2];
#pragma unroll
        for (int p = 0; p < 2; ++p) {
            uint32_t bd = bbase + ((brow + p * 16) * 72 + ks * 16 + bkoff) * 2;
            uint32_t r4[4];
            ldsm4(bd, r4);
            bhi[2 * p][0] = r4[0]; bhi[2 * p][1] = r4[1];
            bhi[2 * p + 1][0] = r4[2]; bhi[2 * p + 1][1] = r4[3];
            ldsm4(bd + B_SPL, r4);
            blo[2 * p][0] = r4[0]; blo[2 * p][1] = r4[1];
            blo[2 * p + 1][0] = r4[2]; blo[2 * p + 1][1] = r4[3];
        }
#pragma unroll
        for (int mt = 0; mt < 2; ++mt)
#pragma unroll
            for (int nt = 0; nt < 4; ++nt) {
                float* c = acc + (mt * 4 + nt) * 4;
                mma16816(c, ahi[mt], bhi[nt]);
                mma16816(c, ahi[mt], blo[nt]);
                mma16816(c, alo[mt], bhi[nt]);
            }
    }
}

__device__ __forceinline__ void compute_tile_f(const __half* Bsrc, float* acc,
                                               uint32_t smb, int wy, int wx, int lane, int t) {
#pragma unroll
    for (int i = 0; i < 32; ++i) acc[i] = 0.f;
    copy_chunk2(smb, 0, Bsrc, t);
    asm volatile("cp.async.commit_group;" ::: "memory");
#pragma unroll 1
    for (int kc = 0; kc < 8; ++kc) {
        if (kc < 7) {
            copy_chunk2(smb, (kc + 1) & 1, Bsrc + (size_t)(kc + 1) * 16384, t);
            asm volatile("cp.async.commit_group;" ::: "memory");
            asm volatile("cp.async.wait_group 1;" ::: "memory");
        } else {
            asm volatile("cp.async.wait_group 0;" ::: "memory");
        }
        __syncthreads();
        mma_chunk_f(smb, kc & 1, kc, wy, wx, lane, acc);
        __syncthreads();
    }
}

__device__ __forceinline__ void packA(char* sm, const float* __restrict__ src, int t) {
#pragma unroll 4
    for (int i = 0; i < 32; ++i) {
        int idx = t + i * 256;                 // 8192 float4
        int r = idx >> 7, kq = (idx & 127) * 4;
        float4 v = *(const float4*)(src + (size_t)r * HHD + kq);
        unsigned short h0, l0, h1, l1, h2, l2, h3, l3;
        hsplit(v.x, h0, l0); hsplit(v.y, h1, l1);
        hsplit(v.z, h2, l2); hsplit(v.w, h3, l3);
        char* d = sm + SM_A + (r * 520 + kq) * 2;
        *(uint32_t*)d = (uint32_t)h0 | ((uint32_t)h1 << 16);
        *(uint32_t*)(d + 4) = (uint32_t)h2 | ((uint32_t)h3 << 16);
        *(uint32_t*)(d + A_SPLIT) = (uint32_t)l0 | ((uint32_t)l1 << 16);
        *(uint32_t*)(d + A_SPLIT + 4) = (uint32_t)l2 | ((uint32_t)l3 << 16);
    }
}

// ---------------- ctx via HMMA: gctx/fcctx = enc @ W[:,128:640].T + bias ----------------
__global__ __launch_bounds__(256, 1)
void ctx_mma_kernel(const float* __restrict__ enc, const float* __restrict__ b_ih,
                    const float* __restrict__ b_hh, const float* __restrict__ fc_b) {
    extern __shared__ char smraw[];
    char* sm = smraw;
    uint32_t smb = smem_u32(sm);
    const int t = threadIdx.x, lane = t & 31, warp = t >> 5;
    const int wy = warp >> 2, wx = warp & 3;
    const int cta = blockIdx.x;

    packA(sm, enc + (size_t)cta * CROWS * HHD, t);
    __syncthreads();
    float acc[32];
#pragma unroll 1
    for (int tl = 0; tl < 13; ++tl) {
        compute_tile_f(g_ctxpack + (size_t)tl * 8 * 16384, acc, smb, wy, wx, lane, t);
#pragma unroll
        for (int mt = 0; mt < 2; ++mt)
#pragma unroll
            for (int nt = 0; nt < 4; ++nt)
#pragma unroll
                for (int hh = 0; hh < 2; ++hh) {
                    int row = wy * 32 + mt * 16 + (lane >> 2) + hh * 8;
                    int ng = cta * CROWS + row;
                    int jcol = wx * 32 + nt * 8 + (lane & 3) * 2;
                    int base = (mt * 4 + nt) * 4 + hh * 2;
                    if (tl < 12) {
                        int j = tl * 128 + jcol;
                        float2 bi = *(const float2*)(b_ih + j);
                        float b0 = bi.x, b1 = bi.y;
                        if (j < 1024) {
                            float2 bh = *(const float2*)(b_hh + j);
                            b0 += bh.x; b1 += bh.y;
                        }
                        float2 v;
                        v.x = acc[base] + b0;
                        v.y = acc[base + 1] + b1;
                        *(float2*)(g_gctx + (size_t)ng * G3 + j) = v;
                    } else {
                        float2 fb = *(const float2*)(fc_b + jcol);
                        float2 v;
                        v.x = acc[base] + fb.x;
                        v.y = acc[base + 1] + fb.y;
                        *(float2*)(g_fcctx + (size_t)ng * VV + jcol) = v;
                    }
                }
    }
}

// ---------------- persistent decode kernel ----------------
__global__ __launch_bounds__(256, 1)
void decode_kernel(const float* __restrict__ encoded, const int* __restrict__ init_char,
                   const float* __restrict__ b_hh, float* __restrict__ out) {
    extern __shared__ char smraw[];
    char* sm = smraw;
    uint32_t smb = smem_u32(sm);
    const int t = threadIdx.x, lane = t & 31, warp = t >> 5;
    const int wy = warp >> 2, wx = warp & 3;
    const int cta = blockIdx.x;
    int* sch = (int*)(sm + SM_SCH);
    float* sbhn = (float*)(sm + SM_BHN);
    float* sargv = (float*)(sm + SM_ARGV);
    int* sargi = (int*)(sm + SM_ARGI);

    for (int i = t; i < 512; i += 256) sbhn[i] = b_hh[1024 + i];
    if (t < CROWS) sch[t] = init_char[cta * CROWS + t];
    packA(sm, encoded + (size_t)cta * CROWS * HHD, t);
    __syncthreads();

    for (int step = 0; step < SSTEPS; ++step) {
        float accr[32], accz[32], accn[32];
        // prologue: prefetch gh chunks 0,1
        copy_g(smb, 0, g_wpack, t);
        asm volatile("cp.async.commit_group;" ::: "memory");
        copy_g(smb, 1, g_wpack + 8192, t);
        asm volatile("cp.async.commit_group;" ::: "memory");
#pragma unroll 1
        for (int jt = 0; jt < 4; ++jt) {
            gate_tile(accr, (jt * 3 + 0) * 8, smb, wy, wx, lane, t);
            gate_tile(accz, (jt * 3 + 1) * 8, smb, wy, wx, lane, t);
            gate_tile(accn, (jt * 3 + 2) * 8, smb, wy, wx, lane, t);
            // ---- gate epilogue for this j-tile (no B access; copies may be in flight) ----
#pragma unroll
            for (int mt = 0; mt < 2; ++mt)
#pragma unroll
                for (int nt = 0; nt < 4; ++nt)
#pragma unroll
                    for (int hh = 0; hh < 2; ++hh) {
                        int row = wy * 32 + mt * 16 + (lane >> 2) + hh * 8;
                        int jcol = jt * 128 + wx * 32 + nt * 8 + (lane & 3) * 2;
                        int ng = cta * CROWS + row;
                        int cc = sch[row];
                        const float* gp = g_gctx + (size_t)ng * G3 + jcol;
                        const float* ep = g_embgi + (size_t)cc * G3 + jcol;
                        float2 gr = *(const float2*)gp;
                        float2 gz = *(const float2*)(gp + 512);
                        float2 gn = *(const float2*)(gp + 1024);
                        float2 er = *(const float2*)ep;
                        float2 ez = *(const float2*)(ep + 512);
                        float2 en = *(const float2*)(ep + 1024);
                        const char* ha = sm + SM_A + (row * 520 + jcol) * 2;
                        __half2 hv = *(const __half2*)ha;
                        __half2 lv = *(const __half2*)(ha + A_SPLIT);
                        float ho0 = __half2float(__low2half(hv)) + __half2float(__low2half(lv));
                        float ho1 = __half2float(__high2half(hv)) + __half2float(__high2half(lv));
                        int base2 = (mt * 4 + nt) * 4 + hh * 2;
                        float pr0 = gr.x + er.x + accr[base2];
                        float pr1 = gr.y + er.y + accr[base2 + 1];
                        float pz0 = gz.x + ez.x + accz[base2];
                        float pz1 = gz.y + ez.y + accz[base2 + 1];
                        float hn0 = accn[base2] + sbhn[jcol];
                        float hn1 = accn[base2 + 1] + sbhn[jcol + 1];
                        float r0 = fast_sigmoid(pr0);
                        float r1 = fast_sigmoid(pr1);
                        float z0 = fast_sigmoid(pz0);
                        float z1 = fast_sigmoid(pz1);
                        float n0 = fast_tanh(gn.x + en.x + r0 * hn0);
                        float n1 = fast_tanh(gn.y + en.y + r1 * hn1);
                        float2 hnew;
                        hnew.x = (1.f - z0) * n0 + z0 * ho0;
                        hnew.y = (1.f - z1) * n1 + z1 * ho1;
                        *(float2*)(g_h + (size_t)ng * HHD + jcol) = hnew;
                    }
        }
        __syncthreads();                       // g_h writes visible; A reads done
        packA(sm, g_h + (size_t)cta * CROWS * HHD, t);   // A <- h_new
        __syncthreads();

        // ---- fc GEMM (full 3-product fp16: argmax-critical) ----
        compute_tile_f(g_fcpack, accr, smb, wy, wx, lane, t);

        // ---- fc epilogue: logits, out, argmax ----
        float best[4]; int bidx[4];
#pragma unroll
        for (int s = 0; s < 4; ++s) { best[s] = -1e30f; bidx[s] = 0; }
#pragma unroll
        for (int mt = 0; mt < 2; ++mt)
#pragma unroll
            for (int hh = 0; hh < 2; ++hh) {
                int slot = mt * 2 + hh;
                int row = wy * 32 + mt * 16 + (lane >> 2) + hh * 8;
                int ng = cta * CROWS + row;
                int cc = sch[row];
#pragma unroll
                for (int nt = 0; nt < 4; ++nt) {
                    int v = wx * 32 + nt * 8 + (lane & 3) * 2;
                    int base2 = (mt * 4 + nt) * 4 + hh * 2;
                    float2 fc = *(const float2*)(g_fcctx + (size_t)ng * VV + v);
                    float2 fe = *(const float2*)(g_fcemb + (size_t)cc * VV + v);
                    float p0 = accr[base2] + fc.x + fe.x;
                    float p1 = accr[base2 + 1] + fc.y + fe.y;
                    float2 pv; pv.x = p0; pv.y = p1;
                    *(float2*)(out + ((size_t)ng * SSTEPS + step) * VV + v) = pv;
                    if (p0 > best[slot]) { best[slot] = p0; bidx[slot] = v; }
                    if (p1 > best[slot]) { best[slot] = p1; bidx[slot] = v + 1; }
                }
            }
#pragma unroll
        for (int s = 0; s < 4; ++s) {
#pragma unroll
            for (int off = 1; off <= 2; off <<= 1) {
                float ov = __shfl_xor_sync(0xffffffffu, best[s], off);
                int oi = __shfl_xor_sync(0xffffffffu, bidx[s], off);
                if (ov > best[s] || (ov == best[s] && oi < bidx[s])) { best[s] = ov; bidx[s] = oi; }
            }
        }
        if ((lane & 3) == 0) {
#pragma unroll
            for (int s = 0; s < 4; ++s) {
                int row = wy * 32 + (s >> 1) * 16 + (lane >> 2) + (s & 1) * 8;
                sargv[row * 4 + wx] = best[s];
                sargi[row * 4 + wx] = bidx[s];
            }
        }
        __syncthreads();
        if (t < CROWS) {
            float bv = sargv[t * 4]; int bi = sargi[t * 4];
#pragma unroll
            for (int wxi = 1; wxi < 4; ++wxi) {
                float ov = sargv[t * 4 + wxi]; int oi = sargi[t * 4 + wxi];
                if (ov > bv || (ov == bv && oi < bi)) { bv = ov; bi = oi; }
            }
            sch[t] = bi;
        }
        __syncthreads();
    }
}

// ---------------------------------------------------------------------------
extern "C" void kernel_launch(void* const* d_in, const int* in_sizes, int n_in,
                              void* d_out, int out_size) {
    const float *encoded = 0, *emb_table = 0, *W_ih = 0, *W_hh = 0,
                *b_ih = 0, *b_hh = 0, *fc_W = 0, *fc_b = 0;
    const int* init_char = 0;
    for (int i = 0; i < n_in; ++i) {
        switch (in_sizes[i]) {
            case 8192 * 512:  encoded   = (const float*)d_in[i]; break;
            case 8192:        init_char = (const int*)d_in[i];   break;
            case 128 * 128:   emb_table = (const float*)d_in[i]; break;
            case 1536 * 640:  W_ih      = (const float*)d_in[i]; break;
            case 1536 * 512:  W_hh      = (const float*)d_in[i]; break;
            case 1536:        if (!b_ih) b_ih = (const float*)d_in[i];
                              else       b_hh = (const float*)d_in[i]; break;
            case 128 * 1152:  fc_W      = (const float*)d_in[i]; break;
            case 128:         fc_b      = (const float*)d_in[i]; break;
            default: break;
        }
    }
    float* out = (float*)d_out;

    cudaFuncSetAttribute(ctx_mma_kernel, cudaFuncAttributeMaxDynamicSharedMemorySize, SMEM_TOT);
    cudaFuncSetAttribute(decode_kernel, cudaFuncAttributeMaxDynamicSharedMemorySize, SMEM_TOT);

    pack_w_kernel<<<(G3 * HHD + 255) / 256, 256>>>(W_hh);
    pack_fc_kernel<<<(VV * HHD + 255) / 256, 256>>>(fc_W);
    pack_ctx_kernel<<<(1664 * 512 + 255) / 256, 256>>>(W_ih, fc_W);
    emb_kernel<<<dim3(13, 128), 128>>>(emb_table, W_ih, fc_W);
    ctx_mma_kernel<<<NCTA, 256, SMEM_TOT>>>(encoded, b_ih, b_hh, fc_b);
    decode_kernel<<<NCTA, 256, SMEM_TOT>>>(encoded, init_char, b_hh, out);
}

// round 11
// speedup vs baseline: 1.1201x; 1.0294x over previous
#include <cuda_runtime.h>
#include <cuda_fp16.h>
#include <math.h>
#include <stdint.h>

#define NS 8192
#define HHD 512
#define G3 1536
#define EE 128
#define VV 128
#define SSTEPS 32
#define NCTA 128
#define CROWS 64

// smem byte offsets
#define SM_A 0
#define A_SPLIT 66560          // 64*520*2 bytes per split
#define SM_B 133120            // B region: 73728 bytes = 4 gh stages
#define B_STG 18432            // gh stage stride (4 stages)
#define B_BUF 36864            // fc stage stride (2 stages)
#define B_SPL 18432            // fc split stride within stage
#define SM_BHN 206848          // 512 floats: b_hh n-gate part
#define SM_SCH 208896          // 64 ints
#define SM_ARGV 209152         // 256 floats
#define SM_ARGI 210176         // 256 ints
#define SMEM_TOT 211200

// ---------------- persistent device scratch ----------------
__device__ float g_gctx[(size_t)NS * G3];    // [n][1536], b_ih (+ b_hh r,z) folded
__device__ float g_fcctx[(size_t)NS * VV];   // [n][128], fc_b folded
__device__ float g_embgi[VV * G3];           // [c][1536]
__device__ float g_fcemb[VV * VV];           // [c][128]
__device__ float g_h[(size_t)NS * HHD];      // h_new staging (fp32)
__device__ __align__(128) __half g_wpack[12 * 8 * 8192];        // gh panels [tile][kc], single fp16
__device__ __align__(128) __half g_fcpack[8 * 2 * 8192];        // fc panels, hi/lo fp16
__device__ __align__(128) __half g_ctxpack[13 * 8 * 2 * 8192];  // ctx panels, hi/lo fp16

// ---------------- small helpers ----------------
__device__ __forceinline__ uint32_t smem_u32(const void* p) {
    uint32_t a;
    asm("{ .reg .u64 t; cvta.to.shared.u64 t, %1; cvt.u32.u64 %0, t; }" : "=r"(a) : "l"(p));
    return a;
}
__device__ __forceinline__ void ldsm4(uint32_t addr, uint32_t r[4]) {
    asm volatile("ldmatrix.sync.aligned.m8n8.x4.shared.b16 {%0,%1,%2,%3}, [%4];"
        : "=r"(r[0]), "=r"(r[1]), "=r"(r[2]), "=r"(r[3]) : "r"(addr));
}
__device__ __forceinline__ void mma16816(float* c, const uint32_t a[4], const uint32_t b[2]) {
    asm volatile("mma.sync.aligned.m16n8k16.row.col.f32.f16.f16.f32 "
        "{%0,%1,%2,%3}, {%4,%5,%6,%7}, {%8,%9}, {%0,%1,%2,%3};"
        : "+f"(c[0]), "+f"(c[1]), "+f"(c[2]), "+f"(c[3])
        : "r"(a[0]), "r"(a[1]), "r"(a[2]), "r"(a[3]), "r"(b[0]), "r"(b[1]));
}
__device__ __forceinline__ void cp16(uint32_t dst, const void* src) {
    asm volatile("cp.async.cg.shared.global [%0], [%1], 16;" :: "r"(dst), "l"(src));
}
__device__ __forceinline__ void hsplit(float v, unsigned short& h, unsigned short& l) {
    __half hh = __float2half(v);
    __half hl = __float2half(v - __half2float(hh));
    h = __half_as_ushort(hh);
    l = __half_as_ushort(hl);
}
__device__ __forceinline__ float fast_sigmoid(float x) {
    return __fdividef(1.f, 1.f + __expf(-x));
}
__device__ __forceinline__ float fast_tanh(float y) {
    float a = fabsf(y);
    float e = __expf(-2.f * a);
    return copysignf(__fdividef(1.f - e, 1.f + e), y);
}

// ---------------- prep kernels ----------------
__global__ void pack_w_kernel(const float* __restrict__ W_hh) {
    int idx = blockIdx.x * 256 + threadIdx.x;
    if (idx >= G3 * HHD) return;
    int R = idx >> 9, C = idx & 511;
    int g = R >> 9, rem = R & 511, jt = rem >> 7, n = rem & 127;
    int kc = C >> 6, k = C & 63;
    int tile = jt * 3 + g;
    size_t base = (size_t)(tile * 8 + kc) * 8192 + n * 64 + k;
    g_wpack[base] = __float2half(W_hh[idx]);
}

__global__ void pack_fc_kernel(const float* __restrict__ fc_W) {
    int idx = blockIdx.x * 256 + threadIdx.x;
    if (idx >= VV * HHD) return;
    int v = idx >> 9, C = idx & 511;
    int kc = C >> 6, k = C & 63;
    unsigned short h, l;
    hsplit(fc_W[(size_t)v * 1152 + 640 + C], h, l);
    size_t base = ((size_t)kc * 2) * 8192 + v * 64 + k;
    g_fcpack[base] = __ushort_as_half(h);
    g_fcpack[base + 8192] = __ushort_as_half(l);
}

__global__ void pack_ctx_kernel(const float* __restrict__ W_ih,
                                const float* __restrict__ fc_W) {
    int idx = blockIdx.x * 256 + threadIdx.x;
    if (idx >= 1664 * 512) return;
    int r = idx >> 9, k = idx & 511;
    float w = (r < G3) ? W_ih[(size_t)r * 640 + 128 + k]
                       : fc_W[(size_t)(r - G3) * 1152 + 128 + k];
    int tl = r >> 7, n = r & 127, kc = k >> 6, kk = k & 63;
    unsigned short h, l;
    hsplit(w, h, l);
    size_t base = ((size_t)(tl * 8 + kc) * 2) * 8192 + n * 64 + kk;
    g_ctxpack[base] = __ushort_as_half(h);
    g_ctxpack[base + 8192] = __ushort_as_half(l);
}

__global__ __launch_bounds__(128)
void emb_kernel(const float* __restrict__ emb_table,
                const float* __restrict__ W_ih,
                const float* __restrict__ fc_W) {
    __shared__ float er[EE];
    int c = blockIdx.y;
    int tx = threadIdx.x;
    er[tx] = emb_table[c * EE + tx];
    __syncthreads();
    int col = blockIdx.x * 128 + tx;   // [0, 1664)
    const float* brow = (col < G3) ? (W_ih + (size_t)col * 640)
                                   : (fc_W + (size_t)(col - G3) * 1152);
    float acc = 0.f;
#pragma unroll 8
    for (int e = 0; e < EE; e += 4) {
        float4 b = *reinterpret_cast<const float4*>(brow + e);
        acc += er[e] * b.x + er[e + 1] * b.y + er[e + 2] * b.z + er[e + 3] * b.w;
    }
    if (col < G3) g_embgi[c * G3 + col] = acc;
    else          g_fcemb[c * VV + (col - G3)] = acc;
}

// ---------------- HMMA machinery ----------------
__device__ __forceinline__ void copy_g(uint32_t smb, int stage, const __half* src, int t) {
    uint32_t dbase = smb + SM_B + stage * B_STG;
    const char* s = (const char*)src;
#pragma unroll
    for (int i = 0; i < 4; ++i) {
        int u = t + i * 256;
        int n = u >> 3, c = u & 7;
        cp16(dbase + n * 144 + c * 16, s + (size_t)u * 16);
    }
}
__device__ __forceinline__ void copy_split(uint32_t dbase, const __half* src, int t) {
    const char* s = (const char*)src;
#pragma unroll
    for (int i = 0; i < 4; ++i) {
        int u = t + i * 256;
        int n = u >> 3, c = u & 7;
        cp16(dbase + n * 144 + c * 16, s + (size_t)u * 16);
    }
}
__device__ __forceinline__ void copy_chunk2(uint32_t smb, int buf, const __half* src, int t) {
    copy_split(smb + SM_B + buf * B_BUF, src, t);
    copy_split(smb + SM_B + buf * B_BUF + B_SPL, src + 8192, t);
}

// gh: B single fp16, A hi/lo -> 2 products; 64-K chunk.
// Products reordered: all ahi first, then all alo (dep distance 8).
__device__ __forceinline__ void mma_chunk_g(uint32_t smb, int stage, int kc,
                                            int wy, int wx, int lane, float* acc) {
    uint32_t abase = smb + SM_A;
    uint32_t bbase = smb + SM_B + stage * B_STG;
    int arow = wy * 32 + (lane & 7) + ((lane >> 3) & 1) * 8;
    int akoff = ((lane >> 4) & 1) * 8;
    int brow = wx * 32 + ((lane >> 4) & 1) * 8 + (lane & 7);
    int bkoff = ((lane >> 3) & 1) * 8;
#pragma unroll
    for (int ks = 0; ks < 4; ++ks) {
        int kA = kc * 64 + ks * 16 + akoff;
        uint32_t ahi[2][4], alo[2][4];
#pragma unroll
        for (int mt = 0; mt < 2; ++mt) {
            uint32_t ad = abase + ((arow + mt * 16) * 520 + kA) * 2;
            ldsm4(ad, ahi[mt]);
            ldsm4(ad + A_SPLIT, alo[mt]);
        }
        uint32_t b[4][2];
#pragma unroll
        for (int p = 0; p < 2; ++p) {
            uint32_t bd = bbase + ((brow + p * 16) * 72 + ks * 16 + bkoff) * 2;
            uint32_t r4[4];
            ldsm4(bd, r4);
            b[2 * p][0] = r4[0]; b[2 * p][1] = r4[1];
            b[2 * p + 1][0] = r4[2]; b[2 * p + 1][1] = r4[3];
        }
#pragma unroll
        for (int mt = 0; mt < 2; ++mt)
#pragma unroll
            for (int nt = 0; nt < 4; ++nt)
                mma16816(acc + (mt * 4 + nt) * 4, ahi[mt], b[nt]);
#pragma unroll
        for (int mt = 0; mt < 2; ++mt)
#pragma unroll
            for (int nt = 0; nt < 4; ++nt)
                mma16816(acc + (mt * 4 + nt) * 4, alo[mt], b[nt]);
    }
}

// one gate tile (8 chunks = 4 pairs) within the continuous 96-chunk gh stream.
// 4-stage ring, one sync per PAIR; prefetch the next pair into the two
// stages freed by the pair consumed before the sync.
__device__ __forceinline__ void gate_tile(float* acc, int u0, uint32_t smb,
                                          int wy, int wx, int lane, int t) {
#pragma unroll
    for (int i = 0; i < 32; ++i) acc[i] = 0.f;
#pragma unroll 1
    for (int kp = 0; kp < 4; ++kp) {
        int u = u0 + kp * 2;
        asm volatile("cp.async.wait_group 0;" ::: "memory");
        __syncthreads();
        int un = u + 2;
        if (un < 96) {
            copy_g(smb, un & 3, g_wpack + (size_t)un * 8192, t);
            copy_g(smb, (un + 1) & 3, g_wpack + (size_t)(un + 1) * 8192, t);
            asm volatile("cp.async.commit_group;" ::: "memory");
        }
        mma_chunk_g(smb, u & 3, kp * 2, wy, wx, lane, acc);
        mma_chunk_g(smb, (u + 1) & 3, kp * 2 + 1, wy, wx, lane, acc);
    }
}

// fc/ctx: 64-K chunk, 3 products, reordered into 3 independent passes
__device__ __forceinline__ void mma_chunk_f(uint32_t smb, int buf, int kc,
                                            int wy, int wx, int lane, float* acc) {
    uint32_t abase = smb + SM_A;
    uint32_t bbase = smb + SM_B + buf * B_BUF;
    int arow = wy * 32 + (lane & 7) + ((lane >> 3) & 1) * 8;
    int akoff = ((lane >> 4) & 1) * 8;
    int brow = wx * 32 + ((lane >> 4) & 1) * 8 + (lane & 7);
    int bkoff = ((lane >> 3) & 1) * 8;
#pragma unroll
    for (int ks = 0; ks < 4; ++ks) {
        int kA = kc * 64 + ks * 16 + akoff;
        uint32_t ahi[2][4], alo[2][4];
#pragma unroll
        for (int mt = 0; mt < 2; ++mt) {
            uint32_t ad = abase + ((arow + mt * 16) * 520 + kA) * 2;
            ldsm4(ad, ahi[mt]);
            ldsm4(ad + A_SPLIT, alo[mt]);
        }
        uint32_t bhi[4][2], blo[4][2];
#pragma unroll
        for (int p = 0; p < 2; ++p) {
            uint32_t bd = bbase + ((brow + p * 16) * 72 + ks * 16 + bkoff) * 2;
            uint32_t r4[4];
            ldsm4(bd, r4);
            bhi[2 * p][0] = r4[0]; bhi[2 * p][1] = r4[1];
            bhi[2 * p + 1][0] = r4[2]; bhi[2 * p + 1][1] = r4[3];
            ldsm4(bd + B_SPL, r4);
            blo[2 * p][0] = r4[0]; blo[2 * p][1] = r4[1];
            blo[2 * p + 1][0] = r4[2]; blo[2 * p + 1][1] = r4[3];
        }
#pragma unroll
        for (int mt = 0; mt < 2; ++mt)
#pragma unroll
            for (int nt = 0; nt < 4; ++nt)
                mma16816(acc + (mt * 4 + nt) * 4, ahi[mt], bhi[nt]);
#pragma unroll
        for (int mt = 0; mt < 2; ++mt)
#pragma unroll
            for (int nt = 0; nt < 4; ++nt)
                mma16816(acc + (mt * 4 + nt) * 4, ahi[mt], blo[nt]);
#pragma unroll
        for (int mt = 0; mt < 2; ++mt)
#pragma unroll
            for (int nt = 0; nt < 4; ++nt)
                mma16816(acc + (mt * 4 + nt) * 4, alo[mt], bhi[nt]);
    }
}

__device__ __forceinline__ void compute_tile_f(const __half* Bsrc, float* acc,
                                               uint32_t smb, int wy, int wx, int lane, int t) {
#pragma unroll
    for (int i = 0; i < 32; ++i) acc[i] = 0.f;
    copy_chunk2(smb, 0, Bsrc, t);
    asm volatile("cp.async.commit_group;" ::: "memory");
#pragma unroll 1
    for (int kc = 0; kc < 8; ++kc) {
        if (kc < 7) {
            copy_chunk2(smb, (kc + 1) & 1, Bsrc + (size_t)(kc + 1) * 16384, t);
            asm volatile("cp.async.commit_group;" ::: "memory");
            asm volatile("cp.async.wait_group 1;" ::: "memory");
        } else {
            asm volatile("cp.async.wait_group 0;" ::: "memory");
        }
        __syncthreads();
        mma_chunk_f(smb, kc & 1, kc, wy, wx, lane, acc);
        __syncthreads();
    }
}

__device__ __forceinline__ void packA(char* sm, const float* __restrict__ src, int t) {
#pragma unroll 4
    for (int i = 0; i < 32; ++i) {
        int idx = t + i * 256;                 // 8192 float4
        int r = idx >> 7, kq = (idx & 127) * 4;
        float4 v = *(const float4*)(src + (size_t)r * HHD + kq);
        unsigned short h0, l0, h1, l1, h2, l2, h3, l3;
        hsplit(v.x, h0, l0); hsplit(v.y, h1, l1);
        hsplit(v.z, h2, l2); hsplit(v.w, h3, l3);
        char* d = sm + SM_A + (r * 520 + kq) * 2;
        *(uint32_t*)d = (uint32_t)h0 | ((uint32_t)h1 << 16);
        *(uint32_t*)(d + 4) = (uint32_t)h2 | ((uint32_t)h3 << 16);
        *(uint32_t*)(d + A_SPLIT) = (uint32_t)l0 | ((uint32_t)l1 << 16);
        *(uint32_t*)(d + A_SPLIT + 4) = (uint32_t)l2 | ((uint32_t)l3 << 16);
    }
}

// ---------------- ctx via HMMA: gctx/fcctx = enc @ W[:,128:640].T + bias ----------------
__global__ __launch_bounds__(256, 1)
void ctx_mma_kernel(const float* __restrict__ enc, const float* __restrict__ b_ih,
                    const float* __restrict__ b_hh, const float* __restrict__ fc_b) {
    extern __shared__ char smraw[];
    char* sm = smraw;
    uint32_t smb = smem_u32(sm);
    const int t = threadIdx.x, lane = t & 31, warp = t >> 5;
    const int wy = warp >> 2, wx = warp & 3;
    const int cta = blockIdx.x;

    packA(sm, enc + (size_t)cta * CROWS * HHD, t);
    __syncthreads();
    float acc[32];
#pragma unroll 1
    for (int tl = 0; tl < 13; ++tl) {
        compute_tile_f(g_ctxpack + (size_t)tl * 8 * 16384, acc, smb, wy, wx, lane, t);
#pragma unroll
        for (int mt = 0; mt < 2; ++mt)
#pragma unroll
            for (int nt = 0; nt < 4; ++nt)
#pragma unroll
                for (int hh = 0; hh < 2; ++hh) {
                    int row = wy * 32 + mt * 16 + (lane >> 2) + hh * 8;
                    int ng = cta * CROWS + row;
                    int jcol = wx * 32 + nt * 8 + (lane & 3) * 2;
                    int base = (mt * 4 + nt) * 4 + hh * 2;
                    if (tl < 12) {
                        int j = tl * 128 + jcol;
                        float2 bi = *(const float2*)(b_ih + j);
                        float b0 = bi.x, b1 = bi.y;
                        if (j < 1024) {
                            float2 bh = *(const float2*)(b_hh + j);
                            b0 += bh.x; b1 += bh.y;
                        }
                        float2 v;
                        v.x = acc[base] + b0;
                        v.y = acc[base + 1] + b1;
                        *(float2*)(g_gctx + (size_t)ng * G3 + j) = v;
                    } else {
                        float2 fb = *(const float2*)(fc_b + jcol);
                        float2 v;
                        v.x = acc[base] + fb.x;
                        v.y = acc[base + 1] + fb.y;
                        *(float2*)(g_fcctx + (size_t)ng * VV + jcol) = v;
                    }
                }
    }
}

// ---------------- persistent decode kernel ----------------
__global__ __launch_bounds__(256, 1)
void decode_kernel(const float* __restrict__ encoded, const int* __restrict__ init_char,
                   const float* __restrict__ b_hh, float* __restrict__ out) {
    extern __shared__ char smraw[];
    char* sm = smraw;
    uint32_t smb = smem_u32(sm);
    const int t = threadIdx.x, lane = t & 31, warp = t >> 5;
    const int wy = warp >> 2, wx = warp & 3;
    const int cta = blockIdx.x;
    int* sch = (int*)(sm + SM_SCH);
    float* sbhn = (float*)(sm + SM_BHN);
    float* sargv = (float*)(sm + SM_ARGV);
    int* sargi = (int*)(sm + SM_ARGI);

    for (int i = t; i < 512; i += 256) sbhn[i] = b_hh[1024 + i];
    if (t < CROWS) sch[t] = init_char[cta * CROWS + t];
    packA(sm, encoded + (size_t)cta * CROWS * HHD, t);
    __syncthreads();

    for (int step = 0; step < SSTEPS; ++step) {
        float accr[32], accz[32], accn[32];
        // prologue: prefetch gh chunks 0,1 (one group)
        copy_g(smb, 0, g_wpack, t);
        copy_g(smb, 1, g_wpack + 8192, t);
        asm volatile("cp.async.commit_group;" ::: "memory");
#pragma unroll 1
        for (int jt = 0; jt < 4; ++jt) {
            gate_tile(accr, (jt * 3 + 0) * 8, smb, wy, wx, lane, t);
            gate_tile(accz, (jt * 3 + 1) * 8, smb, wy, wx, lane, t);
            gate_tile(accn, (jt * 3 + 2) * 8, smb, wy, wx, lane, t);
            // ---- gate epilogue for this j-tile (no B access; copies may be in flight) ----
#pragma unroll
            for (int mt = 0; mt < 2; ++mt)
#pragma unroll
                for (int nt = 0; nt < 4; ++nt)
#pragma unroll
                    for (int hh = 0; hh < 2; ++hh) {
                        int row = wy * 32 + mt * 16 + (lane >> 2) + hh * 8;
                        int jcol = jt * 128 + wx * 32 + nt * 8 + (lane & 3) * 2;
                        int ng = cta * CROWS + row;
                        int cc = sch[row];
                        const float* gp = g_gctx + (size_t)ng * G3 + jcol;
                        const float* ep = g_embgi + (size_t)cc * G3 + jcol;
                        float2 gr = *(const float2*)gp;
                        float2 gz = *(const float2*)(gp + 512);
                        float2 gn = *(const float2*)(gp + 1024);
                        float2 er = *(const float2*)ep;
                        float2 ez = *(const float2*)(ep + 512);
                        float2 en = *(const float2*)(ep + 1024);
                        const char* ha = sm + SM_A + (row * 520 + jcol) * 2;
                        __half2 hv = *(const __half2*)ha;
                        __half2 lv = *(const __half2*)(ha + A_SPLIT);
                        float ho0 = __half2float(__low2half(hv)) + __half2float(__low2half(lv));
                        float ho1 = __half2float(__high2half(hv)) + __half2float(__high2half(lv));
                        int base2 = (mt * 4 + nt) * 4 + hh * 2;
                        float pr0 = gr.x + er.x + accr[base2];
                        float pr1 = gr.y + er.y + accr[base2 + 1];
                        float pz0 = gz.x + ez.x + accz[base2];
                        float pz1 = gz.y + ez.y + accz[base2 + 1];
                        float hn0 = accn[base2] + sbhn[jcol];
                        float hn1 = accn[base2 + 1] + sbhn[jcol + 1];
                        float r0 = fast_sigmoid(pr0);
                        float r1 = fast_sigmoid(pr1);
                        float z0 = fast_sigmoid(pz0);
                        float z1 = fast_sigmoid(pz1);
                        float n0 = fast_tanh(gn.x + en.x + r0 * hn0);
                        float n1 = fast_tanh(gn.y + en.y + r1 * hn1);
                        float2 hnew;
                        hnew.x = (1.f - z0) * n0 + z0 * ho0;
                        hnew.y = (1.f - z1) * n1 + z1 * ho1;
                        *(float2*)(g_h + (size_t)ng * HHD + jcol) = hnew;
                    }
        }
        __syncthreads();                       // g_h writes visible; A reads done
        packA(sm, g_h + (size_t)cta * CROWS * HHD, t);   // A <- h_new
        __syncthreads();

        // ---- fc GEMM (full 3-product fp16: argmax-critical) ----
        compute_tile_f(g_fcpack, accr, smb, wy, wx, lane, t);

        // ---- fc epilogue: logits, out, argmax ----
        float best[4]; int bidx[4];
#pragma unroll
        for (int s = 0; s < 4; ++s) { best[s] = -1e30f; bidx[s] = 0; }
#pragma unroll
        for (int mt = 0; mt < 2; ++mt)
#pragma unroll
            for (int hh = 0; hh < 2; ++hh) {
                int slot = mt * 2 + hh;
                int row = wy * 32 + mt * 16 + (lane >> 2) + hh * 8;
                int ng = cta * CROWS + row;
                int cc = sch[row];
#pragma unroll
                for (int nt = 0; nt < 4; ++nt) {
                    int v = wx * 32 + nt * 8 + (lane & 3) * 2;
                    int base2 = (mt * 4 + nt) * 4 + hh * 2;
                    float2 fc = *(const float2*)(g_fcctx + (size_t)ng * VV + v);
                    float2 fe = *(const float2*)(g_fcemb + (size_t)cc * VV + v);
                    float p0 = accr[base2] + fc.x + fe.x;
                    float p1 = accr[base2 + 1] + fc.y + fe.y;
                    float2 pv; pv.x = p0; pv.y = p1;
                    *(float2*)(out + ((size_t)ng * SSTEPS + step) * VV + v) = pv;
                    if (p0 > best[slot]) { best[slot] = p0; bidx[slot] = v; }
                    if (p1 > best[slot]) { best[slot] = p1; bidx[slot] = v + 1; }
                }
            }
#pragma unroll
        for (int s = 0; s < 4; ++s) {
#pragma unroll
            for (int off = 1; off <= 2; off <<= 1) {
                float ov = __shfl_xor_sync(0xffffffffu, best[s], off);
                int oi = __shfl_xor_sync(0xffffffffu, bidx[s], off);
                if (ov > best[s] || (ov == best[s] && oi < bidx[s])) { best[s] = ov; bidx[s] = oi; }
            }
        }
        if ((lane & 3) == 0) {
#pragma unroll
            for (int s = 0; s < 4; ++s) {
                int row = wy * 32 + (s >> 1) * 16 + (lane >> 2) + (s & 1) * 8;
                sargv[row * 4 + wx] = best[s];
                sargi[row * 4 + wx] = bidx[s];
            }
        }
        __syncthreads();
        if (t < CROWS) {
            float bv = sargv[t * 4]; int bi = sargi[t * 4];
#pragma unroll
            for (int wxi = 1; wxi < 4; ++wxi) {
                float ov = sargv[t * 4 + wxi]; int oi = sargi[t * 4 + wxi];
                if (ov > bv || (ov == bv && oi < bi)) { bv = ov; bi = oi; }
            }
            sch[t] = bi;
        }
        __syncthreads();
    }
}

// ---------------------------------------------------------------------------
extern "C" void kernel_launch(void* const* d_in, const int* in_sizes, int n_in,
                              void* d_out, int out_size) {
    const float *encoded = 0, *emb_table = 0, *W_ih = 0, *W_hh = 0,
                *b_ih = 0, *b_hh = 0, *fc_W = 0, *fc_b = 0;
    const int* init_char = 0;
    for (int i = 0; i < n_in; ++i) {
        switch (in_sizes[i]) {
            case 8192 * 512:  encoded   = (const float*)d_in[i]; break;
            case 8192:        init_char = (const int*)d_in[i];   break;
            case 128 * 128:   emb_table = (const float*)d_in[i]; break;
            case 1536 * 640:  W_ih      = (const float*)d_in[i]; break;
            case 1536 * 512:  W_hh      = (const float*)d_in[i]; break;
            case 1536:        if (!b_ih) b_ih = (const float*)d_in[i];
                              else       b_hh = (const float*)d_in[i]; break;
            case 128 * 1152:  fc_W      = (const float*)d_in[i]; break;
            case 128:         fc_b      = (const float*)d_in[i]; break;
            default: break;
        }
    }
    float* out = (float*)d_out;

    cudaFuncSetAttribute(ctx_mma_kernel, cudaFuncAttributeMaxDynamicSharedMemorySize, SMEM_TOT);
    cudaFuncSetAttribute(decode_kernel, cudaFuncAttributeMaxDynamicSharedMemorySize, SMEM_TOT);

    pack_w_kernel<<<(G3 * HHD + 255) / 256, 256>>>(W_hh);
    pack_fc_kernel<<<(VV * HHD + 255) / 256, 256>>>(fc_W);
    pack_ctx_kernel<<<(1664 * 512 + 255) / 256, 256>>>(W_ih, fc_W);
    emb_kernel<<<dim3(13, 128), 128>>>(emb_table, W_ih, fc_W);
    ctx_mma_kernel<<<NCTA, 256, SMEM_TOT>>>(encoded, b_ih, b_hh, fc_b);
    decode_kernel<<<NCTA, 256, SMEM_TOT>>>(encoded, init_char, b_hh, out);
}

// round 12
// speedup vs baseline: 1.1804x; 1.0538x over previous
#include <cuda_runtime.h>
#include <cuda_fp16.h>
#include <math.h>
#include <stdint.h>

#define NS 8192
#define HHD 512
#define G3 1536
#define EE 128
#define VV 128
#define SSTEPS 32
#define NCTA 128
#define CROWS 64

// smem byte offsets
#define SM_A 0
#define A_SPLIT 66560          // 64*520*2 bytes per split
#define A_BYTES 133120         // both splits
#define SM_B 133120            // B region: 73728 bytes = 4 gh stages
#define B_STG 18432            // gh stage stride (4 stages)
#define B_BUF 36864            // fc stage stride (2 stages)
#define B_SPL 18432            // fc split stride within stage
#define SM_BHN 206848          // 512 floats: b_hh n-gate part
#define SM_SCH 208896          // 64 ints
#define SM_ARGV 209152         // 256 floats
#define SM_ARGI 210176         // 256 ints
#define SMEM_TOT 211200

// ---------------- persistent device scratch ----------------
__device__ float g_gctx[(size_t)NS * G3];    // [n][1536], b_ih (+ b_hh r,z) folded
__device__ float g_fcctx[(size_t)NS * VV];   // [n][128], fc_b folded
__device__ float g_embgi[VV * G3];           // [c][1536]
__device__ float g_fcemb[VV * VV];           // [c][128]
__device__ __align__(128) char g_hsplit[(size_t)NCTA * A_BYTES];  // gmem mirror of smem A
__device__ __align__(128) __half g_wpack[12 * 8 * 8192];        // gh panels [tile][kc], single fp16
__device__ __align__(128) __half g_fcpack[8 * 2 * 8192];        // fc panels, hi/lo fp16
__device__ __align__(128) __half g_ctxpack[13 * 8 * 2 * 8192];  // ctx panels, hi/lo fp16

// ---------------- small helpers ----------------
__device__ __forceinline__ uint32_t smem_u32(const void* p) {
    uint32_t a;
    asm("{ .reg .u64 t; cvta.to.shared.u64 t, %1; cvt.u32.u64 %0, t; }" : "=r"(a) : "l"(p));
    return a;
}
__device__ __forceinline__ void ldsm4(uint32_t addr, uint32_t r[4]) {
    asm volatile("ldmatrix.sync.aligned.m8n8.x4.shared.b16 {%0,%1,%2,%3}, [%4];"
        : "=r"(r[0]), "=r"(r[1]), "=r"(r[2]), "=r"(r[3]) : "r"(addr));
}
__device__ __forceinline__ void mma16816(float* c, const uint32_t a[4], const uint32_t b[2]) {
    asm volatile("mma.sync.aligned.m16n8k16.row.col.f32.f16.f16.f32 "
        "{%0,%1,%2,%3}, {%4,%5,%6,%7}, {%8,%9}, {%0,%1,%2,%3};"
        : "+f"(c[0]), "+f"(c[1]), "+f"(c[2]), "+f"(c[3])
        : "r"(a[0]), "r"(a[1]), "r"(a[2]), "r"(a[3]), "r"(b[0]), "r"(b[1]));
}
__device__ __forceinline__ void cp16(uint32_t dst, const void* src) {
    asm volatile("cp.async.cg.shared.global [%0], [%1], 16;" :: "r"(dst), "l"(src));
}
__device__ __forceinline__ void hsplit(float v, unsigned short& h, unsigned short& l) {
    __half hh = __float2half(v);
    __half hl = __float2half(v - __half2float(hh));
    h = __half_as_ushort(hh);
    l = __half_as_ushort(hl);
}
__device__ __forceinline__ float fast_sigmoid(float x) {
    return __fdividef(1.f, 1.f + __expf(-x));
}
__device__ __forceinline__ float fast_tanh(float y) {
    float a = fabsf(y);
    float e = __expf(-2.f * a);
    return copysignf(__fdividef(1.f - e, 1.f + e), y);
}

// ---------------- prep kernels ----------------
__global__ void pack_w_kernel(const float* __restrict__ W_hh) {
    int idx = blockIdx.x * 256 + threadIdx.x;
    if (idx >= G3 * HHD) return;
    int R = idx >> 9, C = idx & 511;
    int g = R >> 9, rem = R & 511, jt = rem >> 7, n = rem & 127;
    int kc = C >> 6, k = C & 63;
    int tile = jt * 3 + g;
    size_t base = (size_t)(tile * 8 + kc) * 8192 + n * 64 + k;
    g_wpack[base] = __float2half(W_hh[idx]);
}

__global__ void pack_fc_kernel(const float* __restrict__ fc_W) {
    int idx = blockIdx.x * 256 + threadIdx.x;
    if (idx >= VV * HHD) return;
    int v = idx >> 9, C = idx & 511;
    int kc = C >> 6, k = C & 63;
    unsigned short h, l;
    hsplit(fc_W[(size_t)v * 1152 + 640 + C], h, l);
    size_t base = ((size_t)kc * 2) * 8192 + v * 64 + k;
    g_fcpack[base] = __ushort_as_half(h);
    g_fcpack[base + 8192] = __ushort_as_half(l);
}

__global__ void pack_ctx_kernel(const float* __restrict__ W_ih,
                                const float* __restrict__ fc_W) {
    int idx = blockIdx.x * 256 + threadIdx.x;
    if (idx >= 1664 * 512) return;
    int r = idx >> 9, k = idx & 511;
    float w = (r < G3) ? W_ih[(size_t)r * 640 + 128 + k]
                       : fc_W[(size_t)(r - G3) * 1152 + 128 + k];
    int tl = r >> 7, n = r & 127, kc = k >> 6, kk = k & 63;
    unsigned short h, l;
    hsplit(w, h, l);
    size_t base = ((size_t)(tl * 8 + kc) * 2) * 8192 + n * 64 + kk;
    g_ctxpack[base] = __ushort_as_half(h);
    g_ctxpack[base + 8192] = __ushort_as_half(l);
}

__global__ __launch_bounds__(128)
void emb_kernel(const float* __restrict__ emb_table,
                const float* __restrict__ W_ih,
                const float* __restrict__ fc_W) {
    __shared__ float er[EE];
    int c = blockIdx.y;
    int tx = threadIdx.x;
    er[tx] = emb_table[c * EE + tx];
    __syncthreads();
    int col = blockIdx.x * 128 + tx;   // [0, 1664)
    const float* brow = (col < G3) ? (W_ih + (size_t)col * 640)
                                   : (fc_W + (size_t)(col - G3) * 1152);
    float acc = 0.f;
#pragma unroll 8
    for (int e = 0; e < EE; e += 4) {
        float4 b = *reinterpret_cast<const float4*>(brow + e);
        acc += er[e] * b.x + er[e + 1] * b.y + er[e + 2] * b.z + er[e + 3] * b.w;
    }
    if (col < G3) g_embgi[c * G3 + col] = acc;
    else          g_fcemb[c * VV + (col - G3)] = acc;
}

// ---------------- HMMA machinery ----------------
__device__ __forceinline__ void copy_g(uint32_t smb, int stage, const __half* src, int t) {
    uint32_t dbase = smb + SM_B + stage * B_STG;
    const char* s = (const char*)src;
#pragma unroll
    for (int i = 0; i < 4; ++i) {
        int u = t + i * 256;
        int n = u >> 3, c = u & 7;
        cp16(dbase + n * 144 + c * 16, s + (size_t)u * 16);
    }
}
__device__ __forceinline__ void copy_split(uint32_t dbase, const __half* src, int t) {
    const char* s = (const char*)src;
#pragma unroll
    for (int i = 0; i < 4; ++i) {
        int u = t + i * 256;
        int n = u >> 3, c = u & 7;
        cp16(dbase + n * 144 + c * 16, s + (size_t)u * 16);
    }
}
__device__ __forceinline__ void copy_chunk2(uint32_t smb, int buf, const __half* src, int t) {
    copy_split(smb + SM_B + buf * B_BUF, src, t);
    copy_split(smb + SM_B + buf * B_BUF + B_SPL, src + 8192, t);
}
// A refresh: straight copy of the gmem mirror into smem A (8320 quanta of 16B)
__device__ __forceinline__ void copyA_async(uint32_t smb, const char* src, int t) {
#pragma unroll
    for (int i = 0; i < 33; ++i) {
        int u = t + i * 256;
        if (u < 8320) cp16(smb + SM_A + u * 16, src + (size_t)u * 16);
    }
}

// gh: B single fp16, A hi/lo -> 2 products; 64-K chunk; products reordered
__device__ __forceinline__ void mma_chunk_g(uint32_t smb, int stage, int kc,
                                            int wy, int wx, int lane, float* acc) {
    uint32_t abase = smb + SM_A;
    uint32_t bbase = smb + SM_B + stage * B_STG;
    int arow = wy * 32 + (lane & 7) + ((lane >> 3) & 1) * 8;
    int akoff = ((lane >> 4) & 1) * 8;
    int brow = wx * 32 + ((lane >> 4) & 1) * 8 + (lane & 7);
    int bkoff = ((lane >> 3) & 1) * 8;
#pragma unroll
    for (int ks = 0; ks < 4; ++ks) {
        int kA = kc * 64 + ks * 16 + akoff;
        uint32_t ahi[2][4], alo[2][4];
#pragma unroll
        for (int mt = 0; mt < 2; ++mt) {
            uint32_t ad = abase + ((arow + mt * 16) * 520 + kA) * 2;
            ldsm4(ad, ahi[mt]);
            ldsm4(ad + A_SPLIT, alo[mt]);
        }
        uint32_t b[4][2];
#pragma unroll
        for (int p = 0; p < 2; ++p) {
            uint32_t bd = bbase + ((brow + p * 16) * 72 + ks * 16 + bkoff) * 2;
            uint32_t r4[4];
            ldsm4(bd, r4);
            b[2 * p][0] = r4[0]; b[2 * p][1] = r4[1];
            b[2 * p + 1][0] = r4[2]; b[2 * p + 1][1] = r4[3];
        }
#pragma unroll
        for (int mt = 0; mt < 2; ++mt)
#pragma unroll
            for (int nt = 0; nt < 4; ++nt)
                mma16816(acc + (mt * 4 + nt) * 4, ahi[mt], b[nt]);
#pragma unroll
        for (int mt = 0; mt < 2; ++mt)
#pragma unroll
            for (int nt = 0; nt < 4; ++nt)
                mma16816(acc + (mt * 4 + nt) * 4, alo[mt], b[nt]);
    }
}

// one gate tile (8 chunks = 4 pairs); 4-stage ring, one sync per pair
__device__ __forceinline__ void gate_tile(float* acc, int u0, uint32_t smb,
                                          int wy, int wx, int lane, int t) {
#pragma unroll
    for (int i = 0; i < 32; ++i) acc[i] = 0.f;
#pragma unroll 1
    for (int kp = 0; kp < 4; ++kp) {
        int u = u0 + kp * 2;
        asm volatile("cp.async.wait_group 0;" ::: "memory");
        __syncthreads();
        int un = u + 2;
        if (un < 96) {
            copy_g(smb, un & 3, g_wpack + (size_t)un * 8192, t);
            copy_g(smb, (un + 1) & 3, g_wpack + (size_t)(un + 1) * 8192, t);
            asm volatile("cp.async.commit_group;" ::: "memory");
        }
        mma_chunk_g(smb, u & 3, kp * 2, wy, wx, lane, acc);
        mma_chunk_g(smb, (u + 1) & 3, kp * 2 + 1, wy, wx, lane, acc);
    }
}

// fc/ctx: 64-K chunk, 3 products, 3 independent passes
__device__ __forceinline__ void mma_chunk_f(uint32_t smb, int buf, int kc,
                                            int wy, int wx, int lane, float* acc) {
    uint32_t abase = smb + SM_A;
    uint32_t bbase = smb + SM_B + buf * B_BUF;
    int arow = wy * 32 + (lane & 7) + ((lane >> 3) & 1) * 8;
    int akoff = ((lane >> 4) & 1) * 8;
    int brow = wx * 32 + ((lane >> 4) & 1) * 8 + (lane & 7);
    int bkoff = ((lane >> 3) & 1) * 8;
#pragma unroll
    for (int ks = 0; ks < 4; ++ks) {
        int kA = kc * 64 + ks * 16 + akoff;
        uint32_t ahi[2][4], alo[2][4];
#pragma unroll
        for (int mt = 0; mt < 2; ++mt) {
            uint32_t ad = abase + ((arow + mt * 16) * 520 + kA) * 2;
            ldsm4(ad, ahi[mt]);
            ldsm4(ad + A_SPLIT, alo[mt]);
        }
        uint32_t bhi[4][2], blo[4][2];
#pragma unroll
        for (int p = 0; p < 2; ++p) {
            uint32_t bd = bbase + ((brow + p * 16) * 72 + ks * 16 + bkoff) * 2;
            uint32_t r4[4];
            ldsm4(bd, r4);
            bhi[2 * p][0] = r4[0]; bhi[2 * p][1] = r4[1];
            bhi[2 * p + 1][0] = r4[2]; bhi[2 * p + 1][1] = r4[3];
            ldsm4(bd + B_SPL, r4);
            blo[2 * p][0] = r4[0]; blo[2 * p][1] = r4[1];
            blo[2 * p + 1][0] = r4[2]; blo[2 * p + 1][1] = r4[3];
        }
#pragma unroll
        for (int mt = 0; mt < 2; ++mt)
#pragma unroll
            for (int nt = 0; nt < 4; ++nt)
                mma16816(acc + (mt * 4 + nt) * 4, ahi[mt], bhi[nt]);
#pragma unroll
        for (int mt = 0; mt < 2; ++mt)
#pragma unroll
            for (int nt = 0; nt < 4; ++nt)
                mma16816(acc + (mt * 4 + nt) * 4, ahi[mt], blo[nt]);
#pragma unroll
        for (int mt = 0; mt < 2; ++mt)
#pragma unroll
            for (int nt = 0; nt < 4; ++nt)
                mma16816(acc + (mt * 4 + nt) * 4, alo[mt], bhi[nt]);
    }
}

// ctx-only tile driver (2-stage, as round 11)
__device__ __forceinline__ void compute_tile_f(const __half* Bsrc, float* acc,
                                               uint32_t smb, int wy, int wx, int lane, int t) {
#pragma unroll
    for (int i = 0; i < 32; ++i) acc[i] = 0.f;
    copy_chunk2(smb, 0, Bsrc, t);
    asm volatile("cp.async.commit_group;" ::: "memory");
#pragma unroll 1
    for (int kc = 0; kc < 8; ++kc) {
        if (kc < 7) {
            copy_chunk2(smb, (kc + 1) & 1, Bsrc + (size_t)(kc + 1) * 16384, t);
            asm volatile("cp.async.commit_group;" ::: "memory");
            asm volatile("cp.async.wait_group 1;" ::: "memory");
        } else {
            asm volatile("cp.async.wait_group 0;" ::: "memory");
        }
        __syncthreads();
        mma_chunk_f(smb, kc & 1, kc, wy, wx, lane, acc);
        __syncthreads();
    }
}

__device__ __forceinline__ void packA(char* sm, const float* __restrict__ src, int t) {
#pragma unroll 4
    for (int i = 0; i < 32; ++i) {
        int idx = t + i * 256;                 // 8192 float4
        int r = idx >> 7, kq = (idx & 127) * 4;
        float4 v = *(const float4*)(src + (size_t)r * HHD + kq);
        unsigned short h0, l0, h1, l1, h2, l2, h3, l3;
        hsplit(v.x, h0, l0); hsplit(v.y, h1, l1);
        hsplit(v.z, h2, l2); hsplit(v.w, h3, l3);
        char* d = sm + SM_A + (r * 520 + kq) * 2;
        *(uint32_t*)d = (uint32_t)h0 | ((uint32_t)h1 << 16);
        *(uint32_t*)(d + 4) = (uint32_t)h2 | ((uint32_t)h3 << 16);
        *(uint32_t*)(d + A_SPLIT) = (uint32_t)l0 | ((uint32_t)l1 << 16);
        *(uint32_t*)(d + A_SPLIT + 4) = (uint32_t)l2 | ((uint32_t)l3 << 16);
    }
}

// ---------------- ctx via HMMA ----------------
__global__ __launch_bounds__(256, 1)
void ctx_mma_kernel(const float* __restrict__ enc, const float* __restrict__ b_ih,
                    const float* __restrict__ b_hh, const float* __restrict__ fc_b) {
    extern __shared__ char smraw[];
    char* sm = smraw;
    uint32_t smb = smem_u32(sm);
    const int t = threadIdx.x, lane = t & 31, warp = t >> 5;
    const int wy = warp >> 2, wx = warp & 3;
    const int cta = blockIdx.x;

    packA(sm, enc + (size_t)cta * CROWS * HHD, t);
    __syncthreads();
    float acc[32];
#pragma unroll 1
    for (int tl = 0; tl < 13; ++tl) {
        compute_tile_f(g_ctxpack + (size_t)tl * 8 * 16384, acc, smb, wy, wx, lane, t);
#pragma unroll
        for (int mt = 0; mt < 2; ++mt)
#pragma unroll
            for (int nt = 0; nt < 4; ++nt)
#pragma unroll
                for (int hh = 0; hh < 2; ++hh) {
                    int row = wy * 32 + mt * 16 + (lane >> 2) + hh * 8;
                    int ng = cta * CROWS + row;
                    int jcol = wx * 32 + nt * 8 + (lane & 3) * 2;
                    int base = (mt * 4 + nt) * 4 + hh * 2;
                    if (tl < 12) {
                        int j = tl * 128 + jcol;
                        float2 bi = *(const float2*)(b_ih + j);
                        float b0 = bi.x, b1 = bi.y;
                        if (j < 1024) {
                            float2 bh = *(const float2*)(b_hh + j);
                            b0 += bh.x; b1 += bh.y;
                        }
                        float2 v;
                        v.x = acc[base] + b0;
                        v.y = acc[base + 1] + b1;
                        *(float2*)(g_gctx + (size_t)ng * G3 + j) = v;
                    } else {
                        float2 fb = *(const float2*)(fc_b + jcol);
                        float2 v;
                        v.x = acc[base] + fb.x;
                        v.y = acc[base + 1] + fb.y;
                        *(float2*)(g_fcctx + (size_t)ng * VV + jcol) = v;
                    }
                }
    }
}

// ---------------- persistent decode kernel ----------------
__global__ __launch_bounds__(256, 1)
void decode_kernel(const float* __restrict__ encoded, const int* __restrict__ init_char,
                   const float* __restrict__ b_hh, float* __restrict__ out) {
    extern __shared__ char smraw[];
    char* sm = smraw;
    uint32_t smb = smem_u32(sm);
    const int t = threadIdx.x, lane = t & 31, warp = t >> 5;
    const int wy = warp >> 2, wx = warp & 3;
    const int cta = blockIdx.x;
    int* sch = (int*)(sm + SM_SCH);
    float* sbhn = (float*)(sm + SM_BHN);
    float* sargv = (float*)(sm + SM_ARGV);
    int* sargi = (int*)(sm + SM_ARGI);
    char* ghs = g_hsplit + (size_t)cta * A_BYTES;

    for (int i = t; i < 512; i += 256) sbhn[i] = b_hh[1024 + i];
    if (t < CROWS) sch[t] = init_char[cta * CROWS + t];
    packA(sm, encoded + (size_t)cta * CROWS * HHD, t);
    __syncthreads();

    for (int step = 0; step < SSTEPS; ++step) {
        float accr[32], accz[32], accn[32];
        // prologue: prefetch gh chunks 0,1 (one group)
        copy_g(smb, 0, g_wpack, t);
        copy_g(smb, 1, g_wpack + 8192, t);
        asm volatile("cp.async.commit_group;" ::: "memory");
#pragma unroll 1
        for (int jt = 0; jt < 4; ++jt) {
            gate_tile(accr, (jt * 3 + 0) * 8, smb, wy, wx, lane, t);
            gate_tile(accz, (jt * 3 + 1) * 8, smb, wy, wx, lane, t);
            gate_tile(accn, (jt * 3 + 2) * 8, smb, wy, wx, lane, t);
            // ---- gate epilogue: write split h_new straight to the gmem A-mirror ----
#pragma unroll
            for (int mt = 0; mt < 2; ++mt)
#pragma unroll
                for (int nt = 0; nt < 4; ++nt)
#pragma unroll
                    for (int hh = 0; hh < 2; ++hh) {
                        int row = wy * 32 + mt * 16 + (lane >> 2) + hh * 8;
                        int jcol = jt * 128 + wx * 32 + nt * 8 + (lane & 3) * 2;
                        int ng = cta * CROWS + row;
                        int cc = sch[row];
                        const float* gp = g_gctx + (size_t)ng * G3 + jcol;
                        const float* ep = g_embgi + (size_t)cc * G3 + jcol;
                        float2 gr = *(const float2*)gp;
                        float2 gz = *(const float2*)(gp + 512);
                        float2 gn = *(const float2*)(gp + 1024);
                        float2 er = *(const float2*)ep;
                        float2 ez = *(const float2*)(ep + 512);
                        float2 en = *(const float2*)(ep + 1024);
                        const char* ha = sm + SM_A + (row * 520 + jcol) * 2;
                        __half2 hv = *(const __half2*)ha;
                        __half2 lv = *(const __half2*)(ha + A_SPLIT);
                        float ho0 = __half2float(__low2half(hv)) + __half2float(__low2half(lv));
                        float ho1 = __half2float(__high2half(hv)) + __half2float(__high2half(lv));
                        int base2 = (mt * 4 + nt) * 4 + hh * 2;
                        float pr0 = gr.x + er.x + accr[base2];
                        float pr1 = gr.y + er.y + accr[base2 + 1];
                        float pz0 = gz.x + ez.x + accz[base2];
                        float pz1 = gz.y + ez.y + accz[base2 + 1];
                        float hn0 = accn[base2] + sbhn[jcol];
                        float hn1 = accn[base2 + 1] + sbhn[jcol + 1];
                        float r0 = fast_sigmoid(pr0);
                        float r1 = fast_sigmoid(pr1);
                        float z0 = fast_sigmoid(pz0);
                        float z1 = fast_sigmoid(pz1);
                        float n0 = fast_tanh(gn.x + en.x + r0 * hn0);
                        float n1 = fast_tanh(gn.y + en.y + r1 * hn1);
                        float hnew0 = (1.f - z0) * n0 + z0 * ho0;
                        float hnew1 = (1.f - z1) * n1 + z1 * ho1;
                        unsigned short hh0, ll0, hh1, ll1;
                        hsplit(hnew0, hh0, ll0);
                        hsplit(hnew1, hh1, ll1);
                        char* gb = ghs + (row * 520 + jcol) * 2;
                        *(uint32_t*)gb = (uint32_t)hh0 | ((uint32_t)hh1 << 16);
                        *(uint32_t*)(gb + A_SPLIT) = (uint32_t)ll0 | ((uint32_t)ll1 << 16);
                    }
        }
        __syncthreads();                       // epilogue gmem writes visible; A reads done
        // ---- A refresh (cp.async copy of the mirror) fused with fc pipeline ----
        copyA_async(smb, ghs, t);
        copy_chunk2(smb, 0, g_fcpack, t);
        asm volatile("cp.async.commit_group;" ::: "memory");
#pragma unroll
        for (int i = 0; i < 32; ++i) accr[i] = 0.f;
#pragma unroll 1
        for (int kc = 0; kc < 8; ++kc) {
            asm volatile("cp.async.wait_group 0;" ::: "memory");
            __syncthreads();
            if (kc < 7) {
                copy_chunk2(smb, (kc + 1) & 1, g_fcpack + (size_t)(kc + 1) * 16384, t);
                asm volatile("cp.async.commit_group;" ::: "memory");
            }
            mma_chunk_f(smb, kc & 1, kc, wy, wx, lane, accr);
        }

        // ---- fc epilogue: logits, out, argmax ----
        float best[4]; int bidx[4];
#pragma unroll
        for (int s = 0; s < 4; ++s) { best[s] = -1e30f; bidx[s] = 0; }
#pragma unroll
        for (int mt = 0; mt < 2; ++mt)
#pragma unroll
            for (int hh = 0; hh < 2; ++hh) {
                int slot = mt * 2 + hh;
                int row = wy * 32 + mt * 16 + (lane >> 2) + hh * 8;
                int ng = cta * CROWS + row;
                int cc = sch[row];
#pragma unroll
                for (int nt = 0; nt < 4; ++nt) {
                    int v = wx * 32 + nt * 8 + (lane & 3) * 2;
                    int base2 = (mt * 4 + nt) * 4 + hh * 2;
                    float2 fc = *(const float2*)(g_fcctx + (size_t)ng * VV + v);
                    float2 fe = *(const float2*)(g_fcemb + (size_t)cc * VV + v);
                    float p0 = accr[base2] + fc.x + fe.x;
                    float p1 = accr[base2 + 1] + fc.y + fe.y;
                    float2 pv; pv.x = p0; pv.y = p1;
                    *(float2*)(out + ((size_t)ng * SSTEPS + step) * VV + v) = pv;
                    if (p0 > best[slot]) { best[slot] = p0; bidx[slot] = v; }
                    if (p1 > best[slot]) { best[slot] = p1; bidx[slot] = v + 1; }
                }
            }
#pragma unroll
        for (int s = 0; s < 4; ++s) {
#pragma unroll
            for (int off = 1; off <= 2; off <<= 1) {
                float ov = __shfl_xor_sync(0xffffffffu, best[s], off);
                int oi = __shfl_xor_sync(0xffffffffu, bidx[s], off);
                if (ov > best[s] || (ov == best[s] && oi < bidx[s])) { best[s] = ov; bidx[s] = oi; }
            }
        }
        if ((lane & 3) == 0) {
#pragma unroll
            for (int s = 0; s < 4; ++s) {
                int row = wy * 32 + (s >> 1) * 16 + (lane >> 2) + (s & 1) * 8;
                sargv[row * 4 + wx] = best[s];
                sargi[row * 4 + wx] = bidx[s];
            }
        }
        __syncthreads();
        if (t < CROWS) {
            float bv = sargv[t * 4]; int bi = sargi[t * 4];
#pragma unroll
            for (int wxi = 1; wxi < 4; ++wxi) {
                float ov = sargv[t * 4 + wxi]; int oi = sargi[t * 4 + wxi];
                if (ov > bv || (ov == bv && oi < bi)) { bv = ov; bi = oi; }
            }
            sch[t] = bi;
        }
        __syncthreads();
    }
}

// ---------------------------------------------------------------------------
extern "C" void kernel_launch(void* const* d_in, const int* in_sizes, int n_in,
                              void* d_out, int out_size) {
    const float *encoded = 0, *emb_table = 0, *W_ih = 0, *W_hh = 0,
                *b_ih = 0, *b_hh = 0, *fc_W = 0, *fc_b = 0;
    const int* init_char = 0;
    for (int i = 0; i < n_in; ++i) {
        switch (in_sizes[i]) {
            case 8192 * 512:  encoded   = (const float*)d_in[i]; break;
            case 8192:        init_char = (const int*)d_in[i];   break;
            case 128 * 128:   emb_table = (const float*)d_in[i]; break;
            case 1536 * 640:  W_ih      = (const float*)d_in[i]; break;
            case 1536 * 512:  W_hh      = (const float*)d_in[i]; break;
            case 1536:        if (!b_ih) b_ih = (const float*)d_in[i];
                              else       b_hh = (const float*)d_in[i]; break;
            case 128 * 1152:  fc_W      = (const float*)d_in[i]; break;
            case 128:         fc_b      = (const float*)d_in[i]; break;
            default: break;
        }
    }
    float* out = (float*)d_out;

    cudaFuncSetAttribute(ctx_mma_kernel, cudaFuncAttributeMaxDynamicSharedMemorySize, SMEM_TOT);
    cudaFuncSetAttribute(decode_kernel, cudaFuncAttributeMaxDynamicSharedMemorySize, SMEM_TOT);

    pack_w_kernel<<<(G3 * HHD + 255) / 256, 256>>>(W_hh);
    pack_fc_kernel<<<(VV * HHD + 255) / 256, 256>>>(fc_W);
    pack_ctx_kernel<<<(1664 * 512 + 255) / 256, 256>>>(W_ih, fc_W);
    emb_kernel<<<dim3(13, 128), 128>>>(emb_table, W_ih, fc_W);
    ctx_mma_kernel<<<NCTA, 256, SMEM_TOT>>>(encoded, b_ih, b_hh, fc_b);
    decode_kernel<<<NCTA, 256, SMEM_TOT>>>(encoded, init_char, b_hh, out);
}

// round 13
// speedup vs baseline: 1.1879x; 1.0064x over previous
#include <cuda_runtime.h>
#include <cuda_fp16.h>
#include <math.h>
#include <stdint.h>

#define NS 8192
#define HHD 512
#define G3 1536
#define EE 128
#define VV 128
#define SSTEPS 32
#define NCTA 128
#define CROWS 64

// smem byte offsets
#define SM_A 0
#define A_SPLIT 66560          // 64*520*2 bytes per split
#define A_BYTES 133120         // both splits
#define SM_B 133120            // B region: 73728 bytes = 4 gh stages
#define B_STG 18432            // gh stage stride (4 stages)
#define B_BUF 36864            // fc stage stride (2 stages)
#define B_SPL 18432            // fc split stride within stage
#define SM_BHN 206848          // 512 floats: b_hh n-gate part
#define SM_SCH 208896          // 64 ints
#define SM_ARGV 209152         // 256 floats
#define SM_ARGI 210176         // 256 ints
#define SMEM_TOT 211200

// ---------------- persistent device scratch ----------------
__device__ float g_gctx[(size_t)NS * G3];
__device__ float g_fcctx[(size_t)NS * VV];
__device__ float g_embgi[VV * G3];
__device__ float g_fcemb[VV * VV];
__device__ __align__(128) char g_hsplit[(size_t)NCTA * A_BYTES];  // gmem mirror of smem A
__device__ __align__(128) __half g_wpack[12 * 8 * 8192];
__device__ __align__(128) __half g_fcpack[8 * 2 * 8192];
__device__ __align__(128) __half g_ctxpack[13 * 8 * 2 * 8192];

// ---------------- small helpers ----------------
__device__ __forceinline__ uint32_t smem_u32(const void* p) {
    uint32_t a;
    asm("{ .reg .u64 t; cvta.to.shared.u64 t, %1; cvt.u32.u64 %0, t; }" : "=r"(a) : "l"(p));
    return a;
}
__device__ __forceinline__ void ldsm4(uint32_t addr, uint32_t r[4]) {
    asm volatile("ldmatrix.sync.aligned.m8n8.x4.shared.b16 {%0,%1,%2,%3}, [%4];"
        : "=r"(r[0]), "=r"(r[1]), "=r"(r[2]), "=r"(r[3]) : "r"(addr));
}
__device__ __forceinline__ void mma16816(float* c, const uint32_t a[4], const uint32_t b[2]) {
    asm volatile("mma.sync.aligned.m16n8k16.row.col.f32.f16.f16.f32 "
        "{%0,%1,%2,%3}, {%4,%5,%6,%7}, {%8,%9}, {%0,%1,%2,%3};"
        : "+f"(c[0]), "+f"(c[1]), "+f"(c[2]), "+f"(c[3])
        : "r"(a[0]), "r"(a[1]), "r"(a[2]), "r"(a[3]), "r"(b[0]), "r"(b[1]));
}
__device__ __forceinline__ void cp16(uint32_t dst, const void* src) {
    asm volatile("cp.async.cg.shared.global [%0], [%1], 16;" :: "r"(dst), "l"(src));
}
__device__ __forceinline__ void hsplit(float v, unsigned short& h, unsigned short& l) {
    __half hh = __float2half(v);
    __half hl = __float2half(v - __half2float(hh));
    h = __half_as_ushort(hh);
    l = __half_as_ushort(hl);
}
__device__ __forceinline__ float fast_sigmoid(float x) {
    return __fdividef(1.f, 1.f + __expf(-x));
}
__device__ __forceinline__ float fast_tanh(float y) {
    float a = fabsf(y);
    float e = __expf(-2.f * a);
    return copysignf(__fdividef(1.f - e, 1.f + e), y);
}

// ---------------- prep kernels ----------------
__global__ void pack_w_kernel(const float* __restrict__ W_hh) {
    int idx = blockIdx.x * 256 + threadIdx.x;
    if (idx >= G3 * HHD) return;
    int R = idx >> 9, C = idx & 511;
    int g = R >> 9, rem = R & 511, jt = rem >> 7, n = rem & 127;
    int kc = C >> 6, k = C & 63;
    int tile = jt * 3 + g;
    size_t base = (size_t)(tile * 8 + kc) * 8192 + n * 64 + k;
    g_wpack[base] = __float2half(W_hh[idx]);
}

__global__ void pack_fc_kernel(const float* __restrict__ fc_W) {
    int idx = blockIdx.x * 256 + threadIdx.x;
    if (idx >= VV * HHD) return;
    int v = idx >> 9, C = idx & 511;
    int kc = C >> 6, k = C & 63;
    unsigned short h, l;
    hsplit(fc_W[(size_t)v * 1152 + 640 + C], h, l);
    size_t base = ((size_t)kc * 2) * 8192 + v * 64 + k;
    g_fcpack[base] = __ushort_as_half(h);
    g_fcpack[base + 8192] = __ushort_as_half(l);
}

__global__ void pack_ctx_kernel(const float* __restrict__ W_ih,
                                const float* __restrict__ fc_W) {
    int idx = blockIdx.x * 256 + threadIdx.x;
    if (idx >= 1664 * 512) return;
    int r = idx >> 9, k = idx & 511;
    float w = (r < G3) ? W_ih[(size_t)r * 640 + 128 + k]
                       : fc_W[(size_t)(r - G3) * 1152 + 128 + k];
    int tl = r >> 7, n = r & 127, kc = k >> 6, kk = k & 63;
    unsigned short h, l;
    hsplit(w, h, l);
    size_t base = ((size_t)(tl * 8 + kc) * 2) * 8192 + n * 64 + kk;
    g_ctxpack[base] = __ushort_as_half(h);
    g_ctxpack[base + 8192] = __ushort_as_half(l);
}

__global__ __launch_bounds__(128)
void emb_kernel(const float* __restrict__ emb_table,
                const float* __restrict__ W_ih,
                const float* __restrict__ fc_W) {
    __shared__ float er[EE];
    int c = blockIdx.y;
    int tx = threadIdx.x;
    er[tx] = emb_table[c * EE + tx];
    __syncthreads();
    int col = blockIdx.x * 128 + tx;
    const float* brow = (col < G3) ? (W_ih + (size_t)col * 640)
                                   : (fc_W + (size_t)(col - G3) * 1152);
    float acc = 0.f;
#pragma unroll 8
    for (int e = 0; e < EE; e += 4) {
        float4 b = *reinterpret_cast<const float4*>(brow + e);
        acc += er[e] * b.x + er[e + 1] * b.y + er[e + 2] * b.z + er[e + 3] * b.w;
    }
    if (col < G3) g_embgi[c * G3 + col] = acc;
    else          g_fcemb[c * VV + (col - G3)] = acc;
}

// ---------------- copy helpers (templated on thread count) ----------------
template<int NT>
__device__ __forceinline__ void copy_16k(uint32_t dbase, const char* s, int t) {
#pragma unroll
    for (int i = 0; i < 1024 / NT; ++i) {
        int u = t + i * NT;
        int n = u >> 3, c = u & 7;
        cp16(dbase + n * 144 + c * 16, s + (size_t)u * 16);
    }
}
template<int NT>
__device__ __forceinline__ void copy_g(uint32_t smb, int stage, const __half* src, int t) {
    copy_16k<NT>(smb + SM_B + stage * B_STG, (const char*)src, t);
}
template<int NT>
__device__ __forceinline__ void copy_chunk2(uint32_t smb, int buf, const __half* src, int t) {
    copy_16k<NT>(smb + SM_B + buf * B_BUF, (const char*)src, t);
    copy_16k<NT>(smb + SM_B + buf * B_BUF + B_SPL, (const char*)(src + 8192), t);
}
template<int NT>
__device__ __forceinline__ void copyA_async(uint32_t smb, const char* src, int t) {
#pragma unroll
    for (int i = 0; i <= 8320 / NT; ++i) {
        int u = t + i * NT;
        if (u < 8320) cp16(smb + SM_A + u * 16, src + (size_t)u * 16);
    }
}
template<int NT>
__device__ __forceinline__ void packA(char* sm, const float* __restrict__ src, int t) {
#pragma unroll 4
    for (int i = 0; i < 8192 / NT; ++i) {
        int idx = t + i * NT;
        int r = idx >> 7, kq = (idx & 127) * 4;
        float4 v = *(const float4*)(src + (size_t)r * HHD + kq);
        unsigned short h0, l0, h1, l1, h2, l2, h3, l3;
        hsplit(v.x, h0, l0); hsplit(v.y, h1, l1);
        hsplit(v.z, h2, l2); hsplit(v.w, h3, l3);
        char* d = sm + SM_A + (r * 520 + kq) * 2;
        *(uint32_t*)d = (uint32_t)h0 | ((uint32_t)h1 << 16);
        *(uint32_t*)(d + 4) = (uint32_t)h2 | ((uint32_t)h3 << 16);
        *(uint32_t*)(d + A_SPLIT) = (uint32_t)l0 | ((uint32_t)l1 << 16);
        *(uint32_t*)(d + A_SPLIT + 4) = (uint32_t)l2 | ((uint32_t)l3 << 16);
    }
}

// ---------------- 256-thread mma (ctx kernel, M=32/warp) ----------------
__device__ __forceinline__ void mma_chunk_f256(uint32_t smb, int buf, int kc,
                                               int wy, int wx, int lane, float* acc) {
    uint32_t abase = smb + SM_A;
    uint32_t bbase = smb + SM_B + buf * B_BUF;
    int arow = wy * 32 + (lane & 7) + ((lane >> 3) & 1) * 8;
    int akoff = ((lane >> 4) & 1) * 8;
    int brow = wx * 32 + ((lane >> 4) & 1) * 8 + (lane & 7);
    int bkoff = ((lane >> 3) & 1) * 8;
#pragma unroll
    for (int ks = 0; ks < 4; ++ks) {
        int kA = kc * 64 + ks * 16 + akoff;
        uint32_t ahi[2][4], alo[2][4];
#pragma unroll
        for (int mt = 0; mt < 2; ++mt) {
            uint32_t ad = abase + ((arow + mt * 16) * 520 + kA) * 2;
            ldsm4(ad, ahi[mt]);
            ldsm4(ad + A_SPLIT, alo[mt]);
        }
        uint32_t bhi[4][2], blo[4][2];
#pragma unroll
        for (int p = 0; p < 2; ++p) {
            uint32_t bd = bbase + ((brow + p * 16) * 72 + ks * 16 + bkoff) * 2;
            uint32_t r4[4];
            ldsm4(bd, r4);
            bhi[2 * p][0] = r4[0]; bhi[2 * p][1] = r4[1];
            bhi[2 * p + 1][0] = r4[2]; bhi[2 * p + 1][1] = r4[3];
            ldsm4(bd + B_SPL, r4);
            blo[2 * p][0] = r4[0]; blo[2 * p][1] = r4[1];
            blo[2 * p + 1][0] = r4[2]; blo[2 * p + 1][1] = r4[3];
        }
#pragma unroll
        for (int mt = 0; mt < 2; ++mt)
#pragma unroll
            for (int nt = 0; nt < 4; ++nt)
                mma16816(acc + (mt * 4 + nt) * 4, ahi[mt], bhi[nt]);
#pragma unroll
        for (int mt = 0; mt < 2; ++mt)
#pragma unroll
            for (int nt = 0; nt < 4; ++nt)
                mma16816(acc + (mt * 4 + nt) * 4, ahi[mt], blo[nt]);
#pragma unroll
        for (int mt = 0; mt < 2; ++mt)
#pragma unroll
            for (int nt = 0; nt < 4; ++nt)
                mma16816(acc + (mt * 4 + nt) * 4, alo[mt], bhi[nt]);
    }
}

__device__ __forceinline__ void compute_tile_f256(const __half* Bsrc, float* acc,
                                                  uint32_t smb, int wy, int wx, int lane, int t) {
#pragma unroll
    for (int i = 0; i < 32; ++i) acc[i] = 0.f;
    copy_chunk2<256>(smb, 0, Bsrc, t);
    asm volatile("cp.async.commit_group;" ::: "memory");
#pragma unroll 1
    for (int kc = 0; kc < 8; ++kc) {
        if (kc < 7) {
            copy_chunk2<256>(smb, (kc + 1) & 1, Bsrc + (size_t)(kc + 1) * 16384, t);
            asm volatile("cp.async.commit_group;" ::: "memory");
            asm volatile("cp.async.wait_group 1;" ::: "memory");
        } else {
            asm volatile("cp.async.wait_group 0;" ::: "memory");
        }
        __syncthreads();
        mma_chunk_f256(smb, kc & 1, kc, wy, wx, lane, acc);
        __syncthreads();
    }
}

// ---------------- 512-thread mma (decode, M=16/warp) ----------------
__device__ __forceinline__ void mma_chunk_g512(uint32_t smb, int stage, int kc,
                                               int wy, int wx, int lane, float* acc) {
    uint32_t abase = smb + SM_A;
    uint32_t bbase = smb + SM_B + stage * B_STG;
    int arow = wy * 16 + (lane & 7) + ((lane >> 3) & 1) * 8;
    int akoff = ((lane >> 4) & 1) * 8;
    int brow = wx * 32 + ((lane >> 4) & 1) * 8 + (lane & 7);
    int bkoff = ((lane >> 3) & 1) * 8;
#pragma unroll
    for (int ks = 0; ks < 4; ++ks) {
        int kA = kc * 64 + ks * 16 + akoff;
        uint32_t ahi[4], alo[4];
        uint32_t ad = abase + (arow * 520 + kA) * 2;
        ldsm4(ad, ahi);
        ldsm4(ad + A_SPLIT, alo);
        uint32_t b[4][2];
#pragma unroll
        for (int p = 0; p < 2; ++p) {
            uint32_t bd = bbase + ((brow + p * 16) * 72 + ks * 16 + bkoff) * 2;
            uint32_t r4[4];
            ldsm4(bd, r4);
            b[2 * p][0] = r4[0]; b[2 * p][1] = r4[1];
            b[2 * p + 1][0] = r4[2]; b[2 * p + 1][1] = r4[3];
        }
#pragma unroll
        for (int nt = 0; nt < 4; ++nt)
            mma16816(acc + nt * 4, ahi, b[nt]);
#pragma unroll
        for (int nt = 0; nt < 4; ++nt)
            mma16816(acc + nt * 4, alo, b[nt]);
    }
}

__device__ __forceinline__ void gate_tile512(float* acc, int u0, uint32_t smb,
                                             int wy, int wx, int lane, int t) {
#pragma unroll
    for (int i = 0; i < 16; ++i) acc[i] = 0.f;
#pragma unroll 1
    for (int kp = 0; kp < 4; ++kp) {
        int u = u0 + kp * 2;
        asm volatile("cp.async.wait_group 0;" ::: "memory");
        __syncthreads();
        int un = u + 2;
        if (un < 96) {
            copy_g<512>(smb, un & 3, g_wpack + (size_t)un * 8192, t);
            copy_g<512>(smb, (un + 1) & 3, g_wpack + (size_t)(un + 1) * 8192, t);
            asm volatile("cp.async.commit_group;" ::: "memory");
        }
        mma_chunk_g512(smb, u & 3, kp * 2, wy, wx, lane, acc);
        mma_chunk_g512(smb, (u + 1) & 3, kp * 2 + 1, wy, wx, lane, acc);
    }
}

__device__ __forceinline__ void mma_chunk_f512(uint32_t smb, int buf, int kc,
                                               int wy, int wx, int lane, float* acc) {
    uint32_t abase = smb + SM_A;
    uint32_t bbase = smb + SM_B + buf * B_BUF;
    int arow = wy * 16 + (lane & 7) + ((lane >> 3) & 1) * 8;
    int akoff = ((lane >> 4) & 1) * 8;
    int brow = wx * 32 + ((lane >> 4) & 1) * 8 + (lane & 7);
    int bkoff = ((lane >> 3) & 1) * 8;
#pragma unroll
    for (int ks = 0; ks < 4; ++ks) {
        int kA = kc * 64 + ks * 16 + akoff;
        uint32_t ahi[4], alo[4];
        uint32_t ad = abase + (arow * 520 + kA) * 2;
        ldsm4(ad, ahi);
        ldsm4(ad + A_SPLIT, alo);
        uint32_t bhi[4][2], blo[4][2];
#pragma unroll
        for (int p = 0; p < 2; ++p) {
            uint32_t bd = bbase + ((brow + p * 16) * 72 + ks * 16 + bkoff) * 2;
            uint32_t r4[4];
            ldsm4(bd, r4);
            bhi[2 * p][0] = r4[0]; bhi[2 * p][1] = r4[1];
            bhi[2 * p + 1][0] = r4[2]; bhi[2 * p + 1][1] = r4[3];
            ldsm4(bd + B_SPL, r4);
            blo[2 * p][0] = r4[0]; blo[2 * p][1] = r4[1];
            blo[2 * p + 1][0] = r4[2]; blo[2 * p + 1][1] = r4[3];
        }
#pragma unroll
        for (int nt = 0; nt < 4; ++nt)
            mma16816(acc + nt * 4, ahi, bhi[nt]);
#pragma unroll
        for (int nt = 0; nt < 4; ++nt)
            mma16816(acc + nt * 4, ahi, blo[nt]);
#pragma unroll
        for (int nt = 0; nt < 4; ++nt)
            mma16816(acc + nt * 4, alo, bhi[nt]);
    }
}

// ---------------- ctx via HMMA (256 threads, unchanged) ----------------
__global__ __launch_bounds__(256, 1)
void ctx_mma_kernel(const float* __restrict__ enc, const float* __restrict__ b_ih,
                    const float* __restrict__ b_hh, const float* __restrict__ fc_b) {
    extern __shared__ char smraw[];
    char* sm = smraw;
    uint32_t smb = smem_u32(sm);
    const int t = threadIdx.x, lane = t & 31, warp = t >> 5;
    const int wy = warp >> 2, wx = warp & 3;
    const int cta = blockIdx.x;

    packA<256>(sm, enc + (size_t)cta * CROWS * HHD, t);
    __syncthreads();
    float acc[32];
#pragma unroll 1
    for (int tl = 0; tl < 13; ++tl) {
        compute_tile_f256(g_ctxpack + (size_t)tl * 8 * 16384, acc, smb, wy, wx, lane, t);
#pragma unroll
        for (int mt = 0; mt < 2; ++mt)
#pragma unroll
            for (int nt = 0; nt < 4; ++nt)
#pragma unroll
                for (int hh = 0; hh < 2; ++hh) {
                    int row = wy * 32 + mt * 16 + (lane >> 2) + hh * 8;
                    int ng = cta * CROWS + row;
                    int jcol = wx * 32 + nt * 8 + (lane & 3) * 2;
                    int base = (mt * 4 + nt) * 4 + hh * 2;
                    if (tl < 12) {
                        int j = tl * 128 + jcol;
                        float2 bi = *(const float2*)(b_ih + j);
                        float b0 = bi.x, b1 = bi.y;
                        if (j < 1024) {
                            float2 bh = *(const float2*)(b_hh + j);
                            b0 += bh.x; b1 += bh.y;
                        }
                        float2 v;
                        v.x = acc[base] + b0;
                        v.y = acc[base + 1] + b1;
                        *(float2*)(g_gctx + (size_t)ng * G3 + j) = v;
                    } else {
                        float2 fb = *(const float2*)(fc_b + jcol);
                        float2 v;
                        v.x = acc[base] + fb.x;
                        v.y = acc[base + 1] + fb.y;
                        *(float2*)(g_fcctx + (size_t)ng * VV + jcol) = v;
                    }
                }
    }
}

// ---------------- persistent decode kernel (512 threads) ----------------
__global__ __launch_bounds__(512, 1)
void decode_kernel(const float* __restrict__ encoded, const int* __restrict__ init_char,
                   const float* __restrict__ b_hh, float* __restrict__ out) {
    extern __shared__ char smraw[];
    char* sm = smraw;
    uint32_t smb = smem_u32(sm);
    const int t = threadIdx.x, lane = t & 31, warp = t >> 5;
    const int wy = warp >> 2, wx = warp & 3;   // wy 0..3 (16 rows), wx 0..3
    const int cta = blockIdx.x;
    int* sch = (int*)(sm + SM_SCH);
    float* sbhn = (float*)(sm + SM_BHN);
    float* sargv = (float*)(sm + SM_ARGV);
    int* sargi = (int*)(sm + SM_ARGI);
    char* ghs = g_hsplit + (size_t)cta * A_BYTES;

    if (t < 512) sbhn[t] = b_hh[1024 + t];
    if (t < CROWS) sch[t] = init_char[cta * CROWS + t];
    packA<512>(sm, encoded + (size_t)cta * CROWS * HHD, t);
    __syncthreads();

    for (int step = 0; step < SSTEPS; ++step) {
        float accr[16], accz[16], accn[16];
        copy_g<512>(smb, 0, g_wpack, t);
        copy_g<512>(smb, 1, g_wpack + 8192, t);
        asm volatile("cp.async.commit_group;" ::: "memory");
#pragma unroll 1
        for (int jt = 0; jt < 4; ++jt) {
            gate_tile512(accr, (jt * 3 + 0) * 8, smb, wy, wx, lane, t);
            gate_tile512(accz, (jt * 3 + 1) * 8, smb, wy, wx, lane, t);
            gate_tile512(accn, (jt * 3 + 2) * 8, smb, wy, wx, lane, t);
            // ---- gate epilogue: write split h_new straight to gmem A-mirror ----
#pragma unroll
            for (int nt = 0; nt < 4; ++nt)
#pragma unroll
                for (int hh = 0; hh < 2; ++hh) {
                    int row = wy * 16 + (lane >> 2) + hh * 8;
                    int jcol = jt * 128 + wx * 32 + nt * 8 + (lane & 3) * 2;
                    int ng = cta * CROWS + row;
                    int cc = sch[row];
                    const float* gp = g_gctx + (size_t)ng * G3 + jcol;
                    const float* ep = g_embgi + (size_t)cc * G3 + jcol;
                    float2 gr = *(const float2*)gp;
                    float2 gz = *(const float2*)(gp + 512);
                    float2 gn = *(const float2*)(gp + 1024);
                    float2 er = *(const float2*)ep;
                    float2 ez = *(const float2*)(ep + 512);
                    float2 en = *(const float2*)(ep + 1024);
                    const char* ha = sm + SM_A + (row * 520 + jcol) * 2;
                    __half2 hv = *(const __half2*)ha;
                    __half2 lv = *(const __half2*)(ha + A_SPLIT);
                    float ho0 = __half2float(__low2half(hv)) + __half2float(__low2half(lv));
                    float ho1 = __half2float(__high2half(hv)) + __half2float(__high2half(lv));
                    int base2 = nt * 4 + hh * 2;
                    float pr0 = gr.x + er.x + accr[base2];
                    float pr1 = gr.y + er.y + accr[base2 + 1];
                    float pz0 = gz.x + ez.x + accz[base2];
                    float pz1 = gz.y + ez.y + accz[base2 + 1];
                    float hn0 = accn[base2] + sbhn[jcol];
                    float hn1 = accn[base2 + 1] + sbhn[jcol + 1];
                    float r0 = fast_sigmoid(pr0);
                    float r1 = fast_sigmoid(pr1);
                    float z0 = fast_sigmoid(pz0);
                    float z1 = fast_sigmoid(pz1);
                    float n0 = fast_tanh(gn.x + en.x + r0 * hn0);
                    float n1 = fast_tanh(gn.y + en.y + r1 * hn1);
                    float hnew0 = (1.f - z0) * n0 + z0 * ho0;
                    float hnew1 = (1.f - z1) * n1 + z1 * ho1;
                    unsigned short hh0, ll0, hh1, ll1;
                    hsplit(hnew0, hh0, ll0);
                    hsplit(hnew1, hh1, ll1);
                    char* gb = ghs + (row * 520 + jcol) * 2;
                    *(uint32_t*)gb = (uint32_t)hh0 | ((uint32_t)hh1 << 16);
                    *(uint32_t*)(gb + A_SPLIT) = (uint32_t)ll0 | ((uint32_t)ll1 << 16);
                }
        }
        __syncthreads();                       // epilogue gmem writes visible; A reads done
        // ---- A refresh (cp.async copy of the mirror) fused with fc pipeline ----
        copyA_async<512>(smb, ghs, t);
        copy_chunk2<512>(smb, 0, g_fcpack, t);
        asm volatile("cp.async.commit_group;" ::: "memory");
        float accf[16];
#pragma unroll
        for (int i = 0; i < 16; ++i) accf[i] = 0.f;
#pragma unroll 1
        for (int kc = 0; kc < 8; ++kc) {
            asm volatile("cp.async.wait_group 0;" ::: "memory");
            __syncthreads();
            if (kc < 7) {
                copy_chunk2<512>(smb, (kc + 1) & 1, g_fcpack + (size_t)(kc + 1) * 16384, t);
                asm volatile("cp.async.commit_group;" ::: "memory");
            }
            mma_chunk_f512(smb, kc & 1, kc, wy, wx, lane, accf);
        }

        // ---- fc epilogue: logits, out, argmax ----
        float best[2]; int bidx[2];
#pragma unroll
        for (int s = 0; s < 2; ++s) { best[s] = -1e30f; bidx[s] = 0; }
#pragma unroll
        for (int hh = 0; hh < 2; ++hh) {
            int row = wy * 16 + (lane >> 2) + hh * 8;
            int ng = cta * CROWS + row;
            int cc = sch[row];
#pragma unroll
            for (int nt = 0; nt < 4; ++nt) {
                int v = wx * 32 + nt * 8 + (lane & 3) * 2;
                int base2 = nt * 4 + hh * 2;
                float2 fc = *(const float2*)(g_fcctx + (size_t)ng * VV + v);
                float2 fe = *(const float2*)(g_fcemb + (size_t)cc * VV + v);
                float p0 = accf[base2] + fc.x + fe.x;
                float p1 = accf[base2 + 1] + fc.y + fe.y;
                float2 pv; pv.x = p0; pv.y = p1;
                *(float2*)(out + ((size_t)ng * SSTEPS + step) * VV + v) = pv;
                if (p0 > best[hh]) { best[hh] = p0; bidx[hh] = v; }
                if (p1 > best[hh]) { best[hh] = p1; bidx[hh] = v + 1; }
            }
        }
#pragma unroll
        for (int s = 0; s < 2; ++s) {
#pragma unroll
            for (int off = 1; off <= 2; off <<= 1) {
                float ov = __shfl_xor_sync(0xffffffffu, best[s], off);
                int oi = __shfl_xor_sync(0xffffffffu, bidx[s], off);
                if (ov > best[s] || (ov == best[s] && oi < bidx[s])) { best[s] = ov; bidx[s] = oi; }
            }
        }
        if ((lane & 3) == 0) {
#pragma unroll
            for (int s = 0; s < 2; ++s) {
                int row = wy * 16 + (lane >> 2) + s * 8;
                sargv[row * 4 + wx] = best[s];
                sargi[row * 4 + wx] = bidx[s];
            }
        }
        __syncthreads();
        if (t < CROWS) {
            float bv = sargv[t * 4]; int bi = sargi[t * 4];
#pragma unroll
            for (int wxi = 1; wxi < 4; ++wxi) {
                float ov = sargv[t * 4 + wxi]; int oi = sargi[t * 4 + wxi];
                if (ov > bv || (ov == bv && oi < bi)) { bv = ov; bi = oi; }
            }
            sch[t] = bi;
        }
        __syncthreads();
    }
}

// ---------------------------------------------------------------------------
extern "C" void kernel_launch(void* const* d_in, const int* in_sizes, int n_in,
                              void* d_out, int out_size) {
    const float *encoded = 0, *emb_table = 0, *W_ih = 0, *W_hh = 0,
                *b_ih = 0, *b_hh = 0, *fc_W = 0, *fc_b = 0;
    const int* init_char = 0;
    for (int i = 0; i < n_in; ++i) {
        switch (in_sizes[i]) {
            case 8192 * 512:  encoded   = (const float*)d_in[i]; break;
            case 8192:        init_char = (const int*)d_in[i];   break;
            case 128 * 128:   emb_table = (const float*)d_in[i]; break;
            case 1536 * 640:  W_ih      = (const float*)d_in[i]; break;
            case 1536 * 512:  W_hh      = (const float*)d_in[i]; break;
            case 1536:        if (!b_ih) b_ih = (const float*)d_in[i];
                              else       b_hh = (const float*)d_in[i]; break;
            case 128 * 1152:  fc_W      = (const float*)d_in[i]; break;
            case 128:         fc_b      = (const float*)d_in[i]; break;
            default: break;
        }
    }
    float* out = (float*)d_out;

    cudaFuncSetAttribute(ctx_mma_kernel, cudaFuncAttributeMaxDynamicSharedMemorySize, SMEM_TOT);
    cudaFuncSetAttribute(decode_kernel, cudaFuncAttributeMaxDynamicSharedMemorySize, SMEM_TOT);

    pack_w_kernel<<<(G3 * HHD + 255) / 256, 256>>>(W_hh);
    pack_fc_kernel<<<(VV * HHD + 255) / 256, 256>>>(fc_W);
    pack_ctx_kernel<<<(1664 * 512 + 255) / 256, 256>>>(W_ih, fc_W);
    emb_kernel<<<dim3(13, 128), 128>>>(emb_table, W_ih, fc_W);
    ctx_mma_kernel<<<NCTA, 256, SMEM_TOT>>>(encoded, b_ih, b_hh, fc_b);
    decode_kernel<<<NCTA, 512, SMEM_TOT>>>(encoded, init_char, b_hh, out);
}

// round 14
// speedup vs baseline: 1.4091x; 1.1861x over previous
#include <cuda_runtime.h>
#include <cuda_fp16.h>
#include <math.h>
#include <stdint.h>

#define NS 8192
#define HHD 512
#define G3 1536
#define EE 128
#define VV 128
#define SSTEPS 32
#define NCTA 128
#define CROWS 64

// smem byte offsets
#define SM_A 0
#define A_SPLIT 66560          // 64*520*2 bytes per split
#define A_BYTES 133120         // both splits
#define SM_B 133120            // B region: 73728 bytes = 4 gh stages
#define B_STG 18432            // gh stage stride (4 stages)
#define B_BUF 36864            // fc stage stride (2 stages)
#define B_SPL 18432            // fc split stride within stage
#define SM_BHN 206848          // 512 floats: b_hh n-gate part
#define SM_SCH 208896          // 64 ints
#define SM_ARGV 209152         // 256 floats
#define SM_ARGI 210176         // 256 ints
#define SMEM_TOT 211200

// ---------------- persistent device scratch ----------------
__device__ float g_gctx[(size_t)NS * G3];
__device__ float g_fcctx[(size_t)NS * VV];
__device__ float g_embgi[VV * G3];
__device__ float g_fcemb[VV * VV];
__device__ __align__(128) char g_hsplit[(size_t)NCTA * A_BYTES];  // gmem mirror of smem A
__device__ __align__(128) __half g_wpack[12 * 8 * 8192];
__device__ __align__(128) __half g_fcpack[8 * 2 * 8192];
__device__ __align__(128) __half g_ctxpack[13 * 8 * 2 * 8192];

// ---------------- small helpers ----------------
__device__ __forceinline__ uint32_t smem_u32(const void* p) {
    uint32_t a;
    asm("{ .reg .u64 t; cvta.to.shared.u64 t, %1; cvt.u32.u64 %0, t; }" : "=r"(a) : "l"(p));
    return a;
}
__device__ __forceinline__ void ldsm4(uint32_t addr, uint32_t r[4]) {
    asm volatile("ldmatrix.sync.aligned.m8n8.x4.shared.b16 {%0,%1,%2,%3}, [%4];"
        : "=r"(r[0]), "=r"(r[1]), "=r"(r[2]), "=r"(r[3]) : "r"(addr));
}
__device__ __forceinline__ void mma16816(float* c, const uint32_t a[4], const uint32_t b[2]) {
    asm volatile("mma.sync.aligned.m16n8k16.row.col.f32.f16.f16.f32 "
        "{%0,%1,%2,%3}, {%4,%5,%6,%7}, {%8,%9}, {%0,%1,%2,%3};"
        : "+f"(c[0]), "+f"(c[1]), "+f"(c[2]), "+f"(c[3])
        : "r"(a[0]), "r"(a[1]), "r"(a[2]), "r"(a[3]), "r"(b[0]), "r"(b[1]));
}
__device__ __forceinline__ void cp16(uint32_t dst, const void* src) {
    asm volatile("cp.async.cg.shared.global [%0], [%1], 16;" :: "r"(dst), "l"(src));
}
__device__ __forceinline__ void hsplit(float v, unsigned short& h, unsigned short& l) {
    __half hh = __float2half(v);
    __half hl = __float2half(v - __half2float(hh));
    h = __half_as_ushort(hh);
    l = __half_as_ushort(hl);
}
__device__ __forceinline__ float fast_sigmoid(float x) {
    return __fdividef(1.f, 1.f + __expf(-x));
}
__device__ __forceinline__ float fast_tanh(float y) {
    float a = fabsf(y);
    float e = __expf(-2.f * a);
    return copysignf(__fdividef(1.f - e, 1.f + e), y);
}

// ---------------- prep kernels ----------------
__global__ void pack_w_kernel(const float* __restrict__ W_hh) {
    int idx = blockIdx.x * 256 + threadIdx.x;
    if (idx >= G3 * HHD) return;
    int R = idx >> 9, C = idx & 511;
    int g = R >> 9, rem = R & 511, jt = rem >> 7, n = rem & 127;
    int kc = C >> 6, k = C & 63;
    int tile = jt * 3 + g;
    size_t base = (size_t)(tile * 8 + kc) * 8192 + n * 64 + k;
    g_wpack[base] = __float2half(W_hh[idx]);
}

__global__ void pack_fc_kernel(const float* __restrict__ fc_W) {
    int idx = blockIdx.x * 256 + threadIdx.x;
    if (idx >= VV * HHD) return;
    int v = idx >> 9, C = idx & 511;
    int kc = C >> 6, k = C & 63;
    unsigned short h, l;
    hsplit(fc_W[(size_t)v * 1152 + 640 + C], h, l);
    size_t base = ((size_t)kc * 2) * 8192 + v * 64 + k;
    g_fcpack[base] = __ushort_as_half(h);
    g_fcpack[base + 8192] = __ushort_as_half(l);
}

__global__ void pack_ctx_kernel(const float* __restrict__ W_ih,
                                const float* __restrict__ fc_W) {
    int idx = blockIdx.x * 256 + threadIdx.x;
    if (idx >= 1664 * 512) return;
    int r = idx >> 9, k = idx & 511;
    float w = (r < G3) ? W_ih[(size_t)r * 640 + 128 + k]
                       : fc_W[(size_t)(r - G3) * 1152 + 128 + k];
    int tl = r >> 7, n = r & 127, kc = k >> 6, kk = k & 63;
    unsigned short h, l;
    hsplit(w, h, l);
    size_t base = ((size_t)(tl * 8 + kc) * 2) * 8192 + n * 64 + kk;
    g_ctxpack[base] = __ushort_as_half(h);
    g_ctxpack[base + 8192] = __ushort_as_half(l);
}

__global__ __launch_bounds__(128)
void emb_kernel(const float* __restrict__ emb_table,
                const float* __restrict__ W_ih,
                const float* __restrict__ fc_W) {
    __shared__ float er[EE];
    int c = blockIdx.y;
    int tx = threadIdx.x;
    er[tx] = emb_table[c * EE + tx];
    __syncthreads();
    int col = blockIdx.x * 128 + tx;
    const float* brow = (col < G3) ? (W_ih + (size_t)col * 640)
                                   : (fc_W + (size_t)(col - G3) * 1152);
    float acc = 0.f;
#pragma unroll 8
    for (int e = 0; e < EE; e += 4) {
        float4 b = *reinterpret_cast<const float4*>(brow + e);
        acc += er[e] * b.x + er[e + 1] * b.y + er[e + 2] * b.z + er[e + 3] * b.w;
    }
    if (col < G3) g_embgi[c * G3 + col] = acc;
    else          g_fcemb[c * VV + (col - G3)] = acc;
}

// ---------------- copy helpers (templated on thread count) ----------------
template<int NT>
__device__ __forceinline__ void copy_16k(uint32_t dbase, const char* s, int t) {
#pragma unroll
    for (int i = 0; i < 1024 / NT; ++i) {
        int u = t + i * NT;
        int n = u >> 3, c = u & 7;
        cp16(dbase + n * 144 + c * 16, s + (size_t)u * 16);
    }
}
template<int NT>
__device__ __forceinline__ void copy_g(uint32_t smb, int stage, const __half* src, int t) {
    copy_16k<NT>(smb + SM_B + stage * B_STG, (const char*)src, t);
}
template<int NT>
__device__ __forceinline__ void copy_chunk2(uint32_t smb, int buf, const __half* src, int t) {
    copy_16k<NT>(smb + SM_B + buf * B_BUF, (const char*)src, t);
    copy_16k<NT>(smb + SM_B + buf * B_BUF + B_SPL, (const char*)(src + 8192), t);
}
template<int NT>
__device__ __forceinline__ void copyA_async(uint32_t smb, const char* src, int t) {
#pragma unroll
    for (int i = 0; i <= 8320 / NT; ++i) {
        int u = t + i * NT;
        if (u < 8320) cp16(smb + SM_A + u * 16, src + (size_t)u * 16);
    }
}
template<int NT>
__device__ __forceinline__ void packA(char* sm, const float* __restrict__ src, int t) {
#pragma unroll 4
    for (int i = 0; i < 8192 / NT; ++i) {
        int idx = t + i * NT;
        int r = idx >> 7, kq = (idx & 127) * 4;
        float4 v = *(const float4*)(src + (size_t)r * HHD + kq);
        unsigned short h0, l0, h1, l1, h2, l2, h3, l3;
        hsplit(v.x, h0, l0); hsplit(v.y, h1, l1);
        hsplit(v.z, h2, l2); hsplit(v.w, h3, l3);
        char* d = sm + SM_A + (r * 520 + kq) * 2;
        *(uint32_t*)d = (uint32_t)h0 | ((uint32_t)h1 << 16);
        *(uint32_t*)(d + 4) = (uint32_t)h2 | ((uint32_t)h3 << 16);
        *(uint32_t*)(d + A_SPLIT) = (uint32_t)l0 | ((uint32_t)l1 << 16);
        *(uint32_t*)(d + A_SPLIT + 4) = (uint32_t)l2 | ((uint32_t)l3 << 16);
    }
}

// ---------------- 256-thread mma (ctx kernel, M=32/warp) ----------------
__device__ __forceinline__ void mma_chunk_f256(uint32_t smb, int buf, int kc,
                                               int wy, int wx, int lane, float* acc) {
    uint32_t abase = smb + SM_A;
    uint32_t bbase = smb + SM_B + buf * B_BUF;
    int arow = wy * 32 + (lane & 7) + ((lane >> 3) & 1) * 8;
    int akoff = ((lane >> 4) & 1) * 8;
    int brow = wx * 32 + ((lane >> 4) & 1) * 8 + (lane & 7);
    int bkoff = ((lane >> 3) & 1) * 8;
#pragma unroll
    for (int ks = 0; ks < 4; ++ks) {
        int kA = kc * 64 + ks * 16 + akoff;
        uint32_t ahi[2][4], alo[2][4];
#pragma unroll
        for (int mt = 0; mt < 2; ++mt) {
            uint32_t ad = abase + ((arow + mt * 16) * 520 + kA) * 2;
            ldsm4(ad, ahi[mt]);
            ldsm4(ad + A_SPLIT, alo[mt]);
        }
        uint32_t bhi[4][2], blo[4][2];
#pragma unroll
        for (int p = 0; p < 2; ++p) {
            uint32_t bd = bbase + ((brow + p * 16) * 72 + ks * 16 + bkoff) * 2;
            uint32_t r4[4];
            ldsm4(bd, r4);
            bhi[2 * p][0] = r4[0]; bhi[2 * p][1] = r4[1];
            bhi[2 * p + 1][0] = r4[2]; bhi[2 * p + 1][1] = r4[3];
            ldsm4(bd + B_SPL, r4);
            blo[2 * p][0] = r4[0]; blo[2 * p][1] = r4[1];
            blo[2 * p + 1][0] = r4[2]; blo[2 * p + 1][1] = r4[3];
        }
#pragma unroll
        for (int mt = 0; mt < 2; ++mt)
#pragma unroll
            for (int nt = 0; nt < 4; ++nt)
                mma16816(acc + (mt * 4 + nt) * 4, ahi[mt], bhi[nt]);
#pragma unroll
        for (int mt = 0; mt < 2; ++mt)
#pragma unroll
            for (int nt = 0; nt < 4; ++nt)
                mma16816(acc + (mt * 4 + nt) * 4, ahi[mt], blo[nt]);
#pragma unroll
        for (int mt = 0; mt < 2; ++mt)
#pragma unroll
            for (int nt = 0; nt < 4; ++nt)
                mma16816(acc + (mt * 4 + nt) * 4, alo[mt], bhi[nt]);
    }
}

__device__ __forceinline__ void compute_tile_f256(const __half* Bsrc, float* acc,
                                                  uint32_t smb, int wy, int wx, int lane, int t) {
#pragma unroll
    for (int i = 0; i < 32; ++i) acc[i] = 0.f;
    copy_chunk2<256>(smb, 0, Bsrc, t);
    asm volatile("cp.async.commit_group;" ::: "memory");
#pragma unroll 1
    for (int kc = 0; kc < 8; ++kc) {
        if (kc < 7) {
            copy_chunk2<256>(smb, (kc + 1) & 1, Bsrc + (size_t)(kc + 1) * 16384, t);
            asm volatile("cp.async.commit_group;" ::: "memory");
            asm volatile("cp.async.wait_group 1;" ::: "memory");
        } else {
            asm volatile("cp.async.wait_group 0;" ::: "memory");
        }
        __syncthreads();
        mma_chunk_f256(smb, kc & 1, kc, wy, wx, lane, acc);
        __syncthreads();
    }
}

// ---------------- 512-thread mma (decode, M=16/warp) ----------------
// gates: SINGLE product ahi*b (alo dropped; error ~2^-12, see theory)
__device__ __forceinline__ void mma_chunk_g512(uint32_t smb, int stage, int kc,
                                               int wy, int wx, int lane, float* acc) {
    uint32_t abase = smb + SM_A;
    uint32_t bbase = smb + SM_B + stage * B_STG;
    int arow = wy * 16 + (lane & 7) + ((lane >> 3) & 1) * 8;
    int akoff = ((lane >> 4) & 1) * 8;
    int brow = wx * 32 + ((lane >> 4) & 1) * 8 + (lane & 7);
    int bkoff = ((lane >> 3) & 1) * 8;
#pragma unroll
    for (int ks = 0; ks < 4; ++ks) {
        int kA = kc * 64 + ks * 16 + akoff;
        uint32_t ahi[4];
        ldsm4(abase + (arow * 520 + kA) * 2, ahi);
        uint32_t b[4][2];
#pragma unroll
        for (int p = 0; p < 2; ++p) {
            uint32_t bd = bbase + ((brow + p * 16) * 72 + ks * 16 + bkoff) * 2;
            uint32_t r4[4];
            ldsm4(bd, r4);
            b[2 * p][0] = r4[0]; b[2 * p][1] = r4[1];
            b[2 * p + 1][0] = r4[2]; b[2 * p + 1][1] = r4[3];
        }
#pragma unroll
        for (int nt = 0; nt < 4; ++nt)
            mma16816(acc + nt * 4, ahi, b[nt]);
    }
}

__device__ __forceinline__ void gate_tile512(float* acc, int u0, uint32_t smb,
                                             int wy, int wx, int lane, int t) {
#pragma unroll
    for (int i = 0; i < 16; ++i) acc[i] = 0.f;
#pragma unroll 1
    for (int kp = 0; kp < 4; ++kp) {
        int u = u0 + kp * 2;
        asm volatile("cp.async.wait_group 0;" ::: "memory");
        __syncthreads();
        int un = u + 2;
        if (un < 96) {
            copy_g<512>(smb, un & 3, g_wpack + (size_t)un * 8192, t);
            copy_g<512>(smb, (un + 1) & 3, g_wpack + (size_t)(un + 1) * 8192, t);
            asm volatile("cp.async.commit_group;" ::: "memory");
        }
        mma_chunk_g512(smb, u & 3, kp * 2, wy, wx, lane, acc);
        mma_chunk_g512(smb, (u + 1) & 3, kp * 2 + 1, wy, wx, lane, acc);
    }
}

// fc: full 3-product (argmax-critical)
__device__ __forceinline__ void mma_chunk_f512(uint32_t smb, int buf, int kc,
                                               int wy, int wx, int lane, float* acc) {
    uint32_t abase = smb + SM_A;
    uint32_t bbase = smb + SM_B + buf * B_BUF;
    int arow = wy * 16 + (lane & 7) + ((lane >> 3) & 1) * 8;
    int akoff = ((lane >> 4) & 1) * 8;
    int brow = wx * 32 + ((lane >> 4) & 1) * 8 + (lane & 7);
    int bkoff = ((lane >> 3) & 1) * 8;
#pragma unroll
    for (int ks = 0; ks < 4; ++ks) {
        int kA = kc * 64 + ks * 16 + akoff;
        uint32_t ahi[4], alo[4];
        uint32_t ad = abase + (arow * 520 + kA) * 2;
        ldsm4(ad, ahi);
        ldsm4(ad + A_SPLIT, alo);
        uint32_t bhi[4][2], blo[4][2];
#pragma unroll
        for (int p = 0; p < 2; ++p) {
            uint32_t bd = bbase + ((brow + p * 16) * 72 + ks * 16 + bkoff) * 2;
            uint32_t r4[4];
            ldsm4(bd, r4);
            bhi[2 * p][0] = r4[0]; bhi[2 * p][1] = r4[1];
            bhi[2 * p + 1][0] = r4[2]; bhi[2 * p + 1][1] = r4[3];
            ldsm4(bd + B_SPL, r4);
            blo[2 * p][0] = r4[0]; blo[2 * p][1] = r4[1];
            blo[2 * p + 1][0] = r4[2]; blo[2 * p + 1][1] = r4[3];
        }
#pragma unroll
        for (int nt = 0; nt < 4; ++nt)
            mma16816(acc + nt * 4, ahi, bhi[nt]);
#pragma unroll
        for (int nt = 0; nt < 4; ++nt)
            mma16816(acc + nt * 4, ahi, blo[nt]);
#pragma unroll
        for (int nt = 0; nt < 4; ++nt)
            mma16816(acc + nt * 4, alo, bhi[nt]);
    }
}

// ---------------- ctx via HMMA (256 threads, unchanged) ----------------
__global__ __launch_bounds__(256, 1)
void ctx_mma_kernel(const float* __restrict__ enc, const float* __restrict__ b_ih,
                    const float* __restrict__ b_hh, const float* __restrict__ fc_b) {
    extern __shared__ char smraw[];
    char* sm = smraw;
    uint32_t smb = smem_u32(sm);
    const int t = threadIdx.x, lane = t & 31, warp = t >> 5;
    const int wy = warp >> 2, wx = warp & 3;
    const int cta = blockIdx.x;

    packA<256>(sm, enc + (size_t)cta * CROWS * HHD, t);
    __syncthreads();
    float acc[32];
#pragma unroll 1
    for (int tl = 0; tl < 13; ++tl) {
        compute_tile_f256(g_ctxpack + (size_t)tl * 8 * 16384, acc, smb, wy, wx, lane, t);
#pragma unroll
        for (int mt = 0; mt < 2; ++mt)
#pragma unroll
            for (int nt = 0; nt < 4; ++nt)
#pragma unroll
                for (int hh = 0; hh < 2; ++hh) {
                    int row = wy * 32 + mt * 16 + (lane >> 2) + hh * 8;
                    int ng = cta * CROWS + row;
                    int jcol = wx * 32 + nt * 8 + (lane & 3) * 2;
                    int base = (mt * 4 + nt) * 4 + hh * 2;
                    if (tl < 12) {
                        int j = tl * 128 + jcol;
                        float2 bi = *(const float2*)(b_ih + j);
                        float b0 = bi.x, b1 = bi.y;
                        if (j < 1024) {
                            float2 bh = *(const float2*)(b_hh + j);
                            b0 += bh.x; b1 += bh.y;
                        }
                        float2 v;
                        v.x = acc[base] + b0;
                        v.y = acc[base + 1] + b1;
                        *(float2*)(g_gctx + (size_t)ng * G3 + j) = v;
                    } else {
                        float2 fb = *(const float2*)(fc_b + jcol);
                        float2 v;
                        v.x = acc[base] + fb.x;
                        v.y = acc[base + 1] + fb.y;
                        *(float2*)(g_fcctx + (size_t)ng * VV + jcol) = v;
                    }
                }
    }
}

// ---------------- persistent decode kernel (512 threads) ----------------
__global__ __launch_bounds__(512, 1)
void decode_kernel(const float* __restrict__ encoded, const int* __restrict__ init_char,
                   const float* __restrict__ b_hh, float* __restrict__ out) {
    extern __shared__ char smraw[];
    char* sm = smraw;
    uint32_t smb = smem_u32(sm);
    const int t = threadIdx.x, lane = t & 31, warp = t >> 5;
    const int wy = warp >> 2, wx = warp & 3;
    const int cta = blockIdx.x;
    int* sch = (int*)(sm + SM_SCH);
    float* sbhn = (float*)(sm + SM_BHN);
    float* sargv = (float*)(sm + SM_ARGV);
    int* sargi = (int*)(sm + SM_ARGI);
    char* ghs = g_hsplit + (size_t)cta * A_BYTES;

    if (t < 512) sbhn[t] = b_hh[1024 + t];
    if (t < CROWS) sch[t] = init_char[cta * CROWS + t];
    packA<512>(sm, encoded + (size_t)cta * CROWS * HHD, t);
    __syncthreads();

    for (int step = 0; step < SSTEPS; ++step) {
        float accr[16], accz[16], accn[16];
        copy_g<512>(smb, 0, g_wpack, t);
        copy_g<512>(smb, 1, g_wpack + 8192, t);
        asm volatile("cp.async.commit_group;" ::: "memory");
#pragma unroll 1
        for (int jt = 0; jt < 4; ++jt) {
            gate_tile512(accr, (jt * 3 + 0) * 8, smb, wy, wx, lane, t);
            gate_tile512(accz, (jt * 3 + 1) * 8, smb, wy, wx, lane, t);
            gate_tile512(accn, (jt * 3 + 2) * 8, smb, wy, wx, lane, t);
            // ---- gate epilogue: write split h_new straight to gmem A-mirror ----
#pragma unroll
            for (int nt = 0; nt < 4; ++nt)
#pragma unroll
                for (int hh = 0; hh < 2; ++hh) {
                    int row = wy * 16 + (lane >> 2) + hh * 8;
                    int jcol = jt * 128 + wx * 32 + nt * 8 + (lane & 3) * 2;
                    int ng = cta * CROWS + row;
                    int cc = sch[row];
                    const float* gp = g_gctx + (size_t)ng * G3 + jcol;
                    const float* ep = g_embgi + (size_t)cc * G3 + jcol;
                    float2 gr = *(const float2*)gp;
                    float2 gz = *(const float2*)(gp + 512);
                    float2 gn = *(const float2*)(gp + 1024);
                    float2 er = *(const float2*)ep;
                    float2 ez = *(const float2*)(ep + 512);
                    float2 en = *(const float2*)(ep + 1024);
                    const char* ha = sm + SM_A + (row * 520 + jcol) * 2;
                    __half2 hv = *(const __half2*)ha;
                    __half2 lv = *(const __half2*)(ha + A_SPLIT);
                    float ho0 = __half2float(__low2half(hv)) + __half2float(__low2half(lv));
                    float ho1 = __half2float(__high2half(hv)) + __half2float(__high2half(lv));
                    int base2 = nt * 4 + hh * 2;
                    float pr0 = gr.x + er.x + accr[base2];
                    float pr1 = gr.y + er.y + accr[base2 + 1];
                    float pz0 = gz.x + ez.x + accz[base2];
                    float pz1 = gz.y + ez.y + accz[base2 + 1];
                    float hn0 = accn[base2] + sbhn[jcol];
                    float hn1 = accn[base2 + 1] + sbhn[jcol + 1];
                    float r0 = fast_sigmoid(pr0);
                    float r1 = fast_sigmoid(pr1);
                    float z0 = fast_sigmoid(pz0);
                    float z1 = fast_sigmoid(pz1);
                    float n0 = fast_tanh(gn.x + en.x + r0 * hn0);
                    float n1 = fast_tanh(gn.y + en.y + r1 * hn1);
                    float hnew0 = (1.f - z0) * n0 + z0 * ho0;
                    float hnew1 = (1.f - z1) * n1 + z1 * ho1;
                    unsigned short hh0, ll0, hh1, ll1;
                    hsplit(hnew0, hh0, ll0);
                    hsplit(hnew1, hh1, ll1);
                    char* gb = ghs + (row * 520 + jcol) * 2;
                    *(uint32_t*)gb = (uint32_t)hh0 | ((uint32_t)hh1 << 16);
                    *(uint32_t*)(gb + A_SPLIT) = (uint32_t)ll0 | ((uint32_t)ll1 << 16);
                }
        }
        __syncthreads();
        // ---- A refresh (cp.async copy of the mirror) fused with fc pipeline ----
        copyA_async<512>(smb, ghs, t);
        copy_chunk2<512>(smb, 0, g_fcpack, t);
        asm volatile("cp.async.commit_group;" ::: "memory");
        float accf[16];
#pragma unroll
        for (int i = 0; i < 16; ++i) accf[i] = 0.f;
#pragma unroll 1
        for (int kc = 0; kc < 8; ++kc) {
            asm volatile("cp.async.wait_group 0;" ::: "memory");
            __syncthreads();
            if (kc < 7) {
                copy_chunk2<512>(smb, (kc + 1) & 1, g_fcpack + (size_t)(kc + 1) * 16384, t);
                asm volatile("cp.async.commit_group;" ::: "memory");
            }
            mma_chunk_f512(smb, kc & 1, kc, wy, wx, lane, accf);
        }

        // ---- fc epilogue: logits, out, argmax ----
        float best[2]; int bidx[2];
#pragma unroll
        for (int s = 0; s < 2; ++s) { best[s] = -1e30f; bidx[s] = 0; }
#pragma unroll
        for (int hh = 0; hh < 2; ++hh) {
            int row = wy * 16 + (lane >> 2) + hh * 8;
            int ng = cta * CROWS + row;
            int cc = sch[row];
#pragma unroll
            for (int nt = 0; nt < 4; ++nt) {
                int v = wx * 32 + nt * 8 + (lane & 3) * 2;
                int base2 = nt * 4 + hh * 2;
                float2 fc = *(const float2*)(g_fcctx + (size_t)ng * VV + v);
                float2 fe = *(const float2*)(g_fcemb + (size_t)cc * VV + v);
                float p0 = accf[base2] + fc.x + fe.x;
                float p1 = accf[base2 + 1] + fc.y + fe.y;
                float2 pv; pv.x = p0; pv.y = p1;
                *(float2*)(out + ((size_t)ng * SSTEPS + step) * VV + v) = pv;
                if (p0 > best[hh]) { best[hh] = p0; bidx[hh] = v; }
                if (p1 > best[hh]) { best[hh] = p1; bidx[hh] = v + 1; }
            }
        }
#pragma unroll
        for (int s = 0; s < 2; ++s) {
#pragma unroll
            for (int off = 1; off <= 2; off <<= 1) {
                float ov = __shfl_xor_sync(0xffffffffu, best[s], off);
                int oi = __shfl_xor_sync(0xffffffffu, bidx[s], off);
                if (ov > best[s] || (ov == best[s] && oi < bidx[s])) { best[s] = ov; bidx[s] = oi; }
            }
        }
        if ((lane & 3) == 0) {
#pragma unroll
            for (int s = 0; s < 2; ++s) {
                int row = wy * 16 + (lane >> 2) + s * 8;
                sargv[row * 4 + wx] = best[s];
                sargi[row * 4 + wx] = bidx[s];
            }
        }
        __syncthreads();
        if (t < CROWS) {
            float bv = sargv[t * 4]; int bi = sargi[t * 4];
#pragma unroll
            for (int wxi = 1; wxi < 4; ++wxi) {
                float ov = sargv[t * 4 + wxi]; int oi = sargi[t * 4 + wxi];
                if (ov > bv || (ov == bv && oi < bi)) { bv = ov; bi = oi; }
            }
            sch[t] = bi;
        }
        __syncthreads();
    }
}

// ---------------------------------------------------------------------------
extern "C" void kernel_launch(void* const* d_in, const int* in_sizes, int n_in,
                              void* d_out, int out_size) {
    const float *encoded = 0, *emb_table = 0, *W_ih = 0, *W_hh = 0,
                *b_ih = 0, *b_hh = 0, *fc_W = 0, *fc_b = 0;
    const int* init_char = 0;
    for (int i = 0; i < n_in; ++i) {
        switch (in_sizes[i]) {
            case 8192 * 512:  encoded   = (const float*)d_in[i]; break;
            case 8192:        init_char = (const int*)d_in[i];   break;
            case 128 * 128:   emb_table = (const float*)d_in[i]; break;
            case 1536 * 640:  W_ih      = (const float*)d_in[i]; break;
            case 1536 * 512:  W_hh      = (const float*)d_in[i]; break;
            case 1536:        if (!b_ih) b_ih = (const float*)d_in[i];
                              else       b_hh = (const float*)d_in[i]; break;
            case 128 * 1152:  fc_W      = (const float*)d_in[i]; break;
            case 128:         fc_b      = (const float*)d_in[i]; break;
            default: break;
        }
    }
    float* out = (float*)d_out;

    cudaFuncSetAttribute(ctx_mma_kernel, cudaFuncAttributeMaxDynamicSharedMemorySize, SMEM_TOT);
    cudaFuncSetAttribute(decode_kernel, cudaFuncAttributeMaxDynamicSharedMemorySize, SMEM_TOT);

    pack_w_kernel<<<(G3 * HHD + 255) / 256, 256>>>(W_hh);
    pack_fc_kernel<<<(VV * HHD + 255) / 256, 256>>>(fc_W);
    pack_ctx_kernel<<<(1664 * 512 + 255) / 256, 256>>>(W_ih, fc_W);
    emb_kernel<<<dim3(13, 128), 128>>>(emb_table, W_ih, fc_W);
    ctx_mma_kernel<<<NCTA, 256, SMEM_TOT>>>(encoded, b_ih, b_hh, fc_b);
    decode_kernel<<<NCTA, 512, SMEM_TOT>>>(encoded, init_char, b_hh, out);
}

// round 15
// speedup vs baseline: 1.5542x; 1.1030x over previous
#include <cuda_runtime.h>
#include <cuda_fp16.h>
#include <math.h>
#include <stdint.h>

#define NS 8192
#define HHD 512
#define G3 1536
#define EE 128
#define VV 128
#define SSTEPS 32
#define NCTA 128
#define CROWS 64

// smem byte offsets
#define SM_A 0
#define A_SPLIT 66560
#define A_BYTES 133120
#define SM_B 133120            // B region: 4 stages of 18432
#define B_STG 18432
#define B_BUF 36864            // fc: 2 stages
#define B_SPL 18432
#define SM_BHN 206848
#define SM_SCH 208896
#define SM_ARGV 209152
#define SM_ARGI 210176
#define SMEM_TOT 211200

// ---------------- persistent device scratch ----------------
__device__ __align__(128) __half g_gctxP[(size_t)NS * 256 * 8];   // packed {r0,r1,z0,z1,n0,n1,_,_} per j-pair
__device__ __align__(128) __half g_embgiP[VV * 256 * 8];          // same layout per char
__device__ float g_fcctx[(size_t)NS * VV];
__device__ float g_fcemb[VV * VV];
__device__ __align__(128) char g_hsplit[(size_t)NCTA * A_BYTES];
__device__ __align__(128) __half g_wpack[12 * 8 * 8192];
__device__ __align__(128) __half g_fcpack[8 * 2 * 8192];
__device__ __align__(128) __half g_ctxpack[13 * 8 * 2 * 8192];

// ---------------- small helpers ----------------
__device__ __forceinline__ uint32_t smem_u32(const void* p) {
    uint32_t a;
    asm("{ .reg .u64 t; cvta.to.shared.u64 t, %1; cvt.u32.u64 %0, t; }" : "=r"(a) : "l"(p));
    return a;
}
__device__ __forceinline__ void ldsm4(uint32_t addr, uint32_t r[4]) {
    asm volatile("ldmatrix.sync.aligned.m8n8.x4.shared.b16 {%0,%1,%2,%3}, [%4];"
        : "=r"(r[0]), "=r"(r[1]), "=r"(r[2]), "=r"(r[3]) : "r"(addr));
}
__device__ __forceinline__ void mma16816(float* c, const uint32_t a[4], const uint32_t b[2]) {
    asm volatile("mma.sync.aligned.m16n8k16.row.col.f32.f16.f16.f32 "
        "{%0,%1,%2,%3}, {%4,%5,%6,%7}, {%8,%9}, {%0,%1,%2,%3};"
        : "+f"(c[0]), "+f"(c[1]), "+f"(c[2]), "+f"(c[3])
        : "r"(a[0]), "r"(a[1]), "r"(a[2]), "r"(a[3]), "r"(b[0]), "r"(b[1]));
}
__device__ __forceinline__ void cp16(uint32_t dst, const void* src) {
    asm volatile("cp.async.cg.shared.global [%0], [%1], 16;" :: "r"(dst), "l"(src));
}
__device__ __forceinline__ void hsplit(float v, unsigned short& h, unsigned short& l) {
    __half hh = __float2half(v);
    __half hl = __float2half(v - __half2float(hh));
    h = __half_as_ushort(hh);
    l = __half_as_ushort(hl);
}
__device__ __forceinline__ float fast_sigmoid(float x) {
    return __fdividef(1.f, 1.f + __expf(-x));
}
__device__ __forceinline__ float fast_tanh(float y) {
    float a = fabsf(y);
    float e = __expf(-2.f * a);
    return copysignf(__fdividef(1.f - e, 1.f + e), y);
}

// ---------------- prep kernels ----------------
__global__ void pack_w_kernel(const float* __restrict__ W_hh) {
    int idx = blockIdx.x * 256 + threadIdx.x;
    if (idx >= G3 * HHD) return;
    int R = idx >> 9, C = idx & 511;
    int g = R >> 9, rem = R & 511, jt = rem >> 7, n = rem & 127;
    int kc = C >> 6, k = C & 63;
    int tile = jt * 3 + g;
    size_t base = (size_t)(tile * 8 + kc) * 8192 + n * 64 + k;
    g_wpack[base] = __float2half(W_hh[idx]);
}

__global__ void pack_fc_kernel(const float* __restrict__ fc_W) {
    int idx = blockIdx.x * 256 + threadIdx.x;
    if (idx >= VV * HHD) return;
    int v = idx >> 9, C = idx & 511;
    int kc = C >> 6, k = C & 63;
    unsigned short h, l;
    hsplit(fc_W[(size_t)v * 1152 + 640 + C], h, l);
    size_t base = ((size_t)kc * 2) * 8192 + v * 64 + k;
    g_fcpack[base] = __ushort_as_half(h);
    g_fcpack[base + 8192] = __ushort_as_half(l);
}

__global__ void pack_ctx_kernel(const float* __restrict__ W_ih,
                                const float* __restrict__ fc_W) {
    int idx = blockIdx.x * 256 + threadIdx.x;
    if (idx >= 1664 * 512) return;
    int r = idx >> 9, k = idx & 511;
    float w = (r < G3) ? W_ih[(size_t)r * 640 + 128 + k]
                       : fc_W[(size_t)(r - G3) * 1152 + 128 + k];
    int tl = r >> 7, n = r & 127, kc = k >> 6, kk = k & 63;
    unsigned short h, l;
    hsplit(w, h, l);
    size_t base = ((size_t)(tl * 8 + kc) * 2) * 8192 + n * 64 + kk;
    g_ctxpack[base] = __ushort_as_half(h);
    g_ctxpack[base + 8192] = __ushort_as_half(l);
}

// emb: writes PACKED embgi halves + fp32 fcemb
__global__ __launch_bounds__(128)
void emb_kernel(const float* __restrict__ emb_table,
                const float* __restrict__ W_ih,
                const float* __restrict__ fc_W) {
    __shared__ float er[EE];
    int c = blockIdx.y;
    int tx = threadIdx.x;
    er[tx] = emb_table[c * EE + tx];
    __syncthreads();
    int col = blockIdx.x * 128 + tx;   // [0, 1664)
    const float* brow = (col < G3) ? (W_ih + (size_t)col * 640)
                                   : (fc_W + (size_t)(col - G3) * 1152);
    float acc = 0.f;
#pragma unroll 8
    for (int e = 0; e < EE; e += 4) {
        float4 b = *reinterpret_cast<const float4*>(brow + e);
        acc += er[e] * b.x + er[e + 1] * b.y + er[e + 2] * b.z + er[e + 3] * b.w;
    }
    if (col < G3) {
        int g = col >> 9, j = col & 511;
        g_embgiP[((size_t)c * 256 + (j >> 1)) * 8 + g * 2 + (j & 1)] = __float2half(acc);
    } else {
        g_fcemb[c * VV + (col - G3)] = acc;
    }
}

// ---------------- copy helpers ----------------
template<int NT>
__device__ __forceinline__ void copy_16k(uint32_t dbase, const char* s, int t) {
#pragma unroll
    for (int i = 0; i < 1024 / NT; ++i) {
        int u = t + i * NT;
        int n = u >> 3, c = u & 7;
        cp16(dbase + n * 144 + c * 16, s + (size_t)u * 16);
    }
}
template<int NT>
__device__ __forceinline__ void copy_g(uint32_t smb, int stage, const __half* src, int t) {
    copy_16k<NT>(smb + SM_B + stage * B_STG, (const char*)src, t);
}
template<int NT>
__device__ __forceinline__ void copy_chunk2(uint32_t smb, int buf, const __half* src, int t) {
    copy_16k<NT>(smb + SM_B + buf * B_BUF, (const char*)src, t);
    copy_16k<NT>(smb + SM_B + buf * B_BUF + B_SPL, (const char*)(src + 8192), t);
}
template<int NT>
__device__ __forceinline__ void copyA_async(uint32_t smb, const char* src, int t) {
#pragma unroll
    for (int i = 0; i <= 8320 / NT; ++i) {
        int u = t + i * NT;
        if (u < 8320) cp16(smb + SM_A + u * 16, src + (size_t)u * 16);
    }
}
template<int NT>
__device__ __forceinline__ void packA(char* sm, const float* __restrict__ src, int t) {
#pragma unroll 4
    for (int i = 0; i < 8192 / NT; ++i) {
        int idx = t + i * NT;
        int r = idx >> 7, kq = (idx & 127) * 4;
        float4 v = *(const float4*)(src + (size_t)r * HHD + kq);
        unsigned short h0, l0, h1, l1, h2, l2, h3, l3;
        hsplit(v.x, h0, l0); hsplit(v.y, h1, l1);
        hsplit(v.z, h2, l2); hsplit(v.w, h3, l3);
        char* d = sm + SM_A + (r * 520 + kq) * 2;
        *(uint32_t*)d = (uint32_t)h0 | ((uint32_t)h1 << 16);
        *(uint32_t*)(d + 4) = (uint32_t)h2 | ((uint32_t)h3 << 16);
        *(uint32_t*)(d + A_SPLIT) = (uint32_t)l0 | ((uint32_t)l1 << 16);
        *(uint32_t*)(d + A_SPLIT + 4) = (uint32_t)l2 | ((uint32_t)l3 << 16);
    }
}

// ---------------- 256-thread mma (ctx kernel) ----------------
__device__ __forceinline__ void mma_chunk_f256(uint32_t smb, int buf, int kc,
                                               int wy, int wx, int lane, float* acc) {
    uint32_t abase = smb + SM_A;
    uint32_t bbase = smb + SM_B + buf * B_BUF;
    int arow = wy * 32 + (lane & 7) + ((lane >> 3) & 1) * 8;
    int akoff = ((lane >> 4) & 1) * 8;
    int brow = wx * 32 + ((lane >> 4) & 1) * 8 + (lane & 7);
    int bkoff = ((lane >> 3) & 1) * 8;
#pragma unroll
    for (int ks = 0; ks < 4; ++ks) {
        int kA = kc * 64 + ks * 16 + akoff;
        uint32_t ahi[2][4], alo[2][4];
#pragma unroll
        for (int mt = 0; mt < 2; ++mt) {
            uint32_t ad = abase + ((arow + mt * 16) * 520 + kA) * 2;
            ldsm4(ad, ahi[mt]);
            ldsm4(ad + A_SPLIT, alo[mt]);
        }
        uint32_t bhi[4][2], blo[4][2];
#pragma unroll
        for (int p = 0; p < 2; ++p) {
            uint32_t bd = bbase + ((brow + p * 16) * 72 + ks * 16 + bkoff) * 2;
            uint32_t r4[4];
            ldsm4(bd, r4);
            bhi[2 * p][0] = r4[0]; bhi[2 * p][1] = r4[1];
            bhi[2 * p + 1][0] = r4[2]; bhi[2 * p + 1][1] = r4[3];
            ldsm4(bd + B_SPL, r4);
            blo[2 * p][0] = r4[0]; blo[2 * p][1] = r4[1];
            blo[2 * p + 1][0] = r4[2]; blo[2 * p + 1][1] = r4[3];
        }
#pragma unroll
        for (int mt = 0; mt < 2; ++mt)
#pragma unroll
            for (int nt = 0; nt < 4; ++nt)
                mma16816(acc + (mt * 4 + nt) * 4, ahi[mt], bhi[nt]);
#pragma unroll
        for (int mt = 0; mt < 2; ++mt)
#pragma unroll
            for (int nt = 0; nt < 4; ++nt)
                mma16816(acc + (mt * 4 + nt) * 4, ahi[mt], blo[nt]);
#pragma unroll
        for (int mt = 0; mt < 2; ++mt)
#pragma unroll
            for (int nt = 0; nt < 4; ++nt)
                mma16816(acc + (mt * 4 + nt) * 4, alo[mt], bhi[nt]);
    }
}

__device__ __forceinline__ void compute_tile_f256(const __half* Bsrc, float* acc,
                                                  uint32_t smb, int wy, int wx, int lane, int t) {
#pragma unroll
    for (int i = 0; i < 32; ++i) acc[i] = 0.f;
    copy_chunk2<256>(smb, 0, Bsrc, t);
    asm volatile("cp.async.commit_group;" ::: "memory");
#pragma unroll 1
    for (int kc = 0; kc < 8; ++kc) {
        if (kc < 7) {
            copy_chunk2<256>(smb, (kc + 1) & 1, Bsrc + (size_t)(kc + 1) * 16384, t);
            asm volatile("cp.async.commit_group;" ::: "memory");
            asm volatile("cp.async.wait_group 1;" ::: "memory");
        } else {
            asm volatile("cp.async.wait_group 0;" ::: "memory");
        }
        __syncthreads();
        mma_chunk_f256(smb, kc & 1, kc, wy, wx, lane, acc);
        __syncthreads();
    }
}

// ---------------- 512-thread mma (decode, M=16/warp) ----------------
__device__ __forceinline__ void mma_chunk_g512(uint32_t smb, int stage, int kc,
                                               int wy, int wx, int lane, float* acc) {
    uint32_t abase = smb + SM_A;
    uint32_t bbase = smb + SM_B + stage * B_STG;
    int arow = wy * 16 + (lane & 7) + ((lane >> 3) & 1) * 8;
    int akoff = ((lane >> 4) & 1) * 8;
    int brow = wx * 32 + ((lane >> 4) & 1) * 8 + (lane & 7);
    int bkoff = ((lane >> 3) & 1) * 8;
#pragma unroll
    for (int ks = 0; ks < 4; ++ks) {
        int kA = kc * 64 + ks * 16 + akoff;
        uint32_t ahi[4];
        ldsm4(abase + (arow * 520 + kA) * 2, ahi);
        uint32_t b[4][2];
#pragma unroll
        for (int p = 0; p < 2; ++p) {
            uint32_t bd = bbase + ((brow + p * 16) * 72 + ks * 16 + bkoff) * 2;
            uint32_t r4[4];
            ldsm4(bd, r4);
            b[2 * p][0] = r4[0]; b[2 * p][1] = r4[1];
            b[2 * p + 1][0] = r4[2]; b[2 * p + 1][1] = r4[3];
        }
#pragma unroll
        for (int nt = 0; nt < 4; ++nt)
            mma16816(acc + nt * 4, ahi, b[nt]);
    }
}

// one gate tile (8 chunks), 4-stage ring, prefetch distance 3, one sync per chunk
__device__ __forceinline__ void gate_tile512(float* acc, int u0, uint32_t smb,
                                             int wy, int wx, int lane, int t) {
#pragma unroll
    for (int i = 0; i < 16; ++i) acc[i] = 0.f;
#pragma unroll 1
    for (int kc = 0; kc < 8; ++kc) {
        int u = u0 + kc;
        if (u < 94)       asm volatile("cp.async.wait_group 2;" ::: "memory");
        else if (u == 94) asm volatile("cp.async.wait_group 1;" ::: "memory");
        else              asm volatile("cp.async.wait_group 0;" ::: "memory");
        __syncthreads();
        int un = u + 3;
        if (un < 96) {
            copy_g<512>(smb, un & 3, g_wpack + (size_t)un * 8192, t);
            asm volatile("cp.async.commit_group;" ::: "memory");
        }
        mma_chunk_g512(smb, u & 3, kc, wy, wx, lane, acc);
    }
}

// fc: full 3-product (argmax-critical)
__device__ __forceinline__ void mma_chunk_f512(uint32_t smb, int buf, int kc,
                                               int wy, int wx, int lane, float* acc) {
    uint32_t abase = smb + SM_A;
    uint32_t bbase = smb + SM_B + buf * B_BUF;
    int arow = wy * 16 + (lane & 7) + ((lane >> 3) & 1) * 8;
    int akoff = ((lane >> 4) & 1) * 8;
    int brow = wx * 32 + ((lane >> 4) & 1) * 8 + (lane & 7);
    int bkoff = ((lane >> 3) & 1) * 8;
#pragma unroll
    for (int ks = 0; ks < 4; ++ks) {
        int kA = kc * 64 + ks * 16 + akoff;
        uint32_t ahi[4], alo[4];
        uint32_t ad = abase + (arow * 520 + kA) * 2;
        ldsm4(ad, ahi);
        ldsm4(ad + A_SPLIT, alo);
        uint32_t bhi[4][2], blo[4][2];
#pragma unroll
        for (int p = 0; p < 2; ++p) {
            uint32_t bd = bbase + ((brow + p * 16) * 72 + ks * 16 + bkoff) * 2;
            uint32_t r4[4];
            ldsm4(bd, r4);
            bhi[2 * p][0] = r4[0]; bhi[2 * p][1] = r4[1];
            bhi[2 * p + 1][0] = r4[2]; bhi[2 * p + 1][1] = r4[3];
            ldsm4(bd + B_SPL, r4);
            blo[2 * p][0] = r4[0]; blo[2 * p][1] = r4[1];
            blo[2 * p + 1][0] = r4[2]; blo[2 * p + 1][1] = r4[3];
        }
#pragma unroll
        for (int nt = 0; nt < 4; ++nt)
            mma16816(acc + nt * 4, ahi, bhi[nt]);
#pragma unroll
        for (int nt = 0; nt < 4; ++nt)
            mma16816(acc + nt * 4, ahi, blo[nt]);
#pragma unroll
        for (int nt = 0; nt < 4; ++nt)
            mma16816(acc + nt * 4, alo, bhi[nt]);
    }
}

// ---------------- ctx via HMMA (writes packed gctx) ----------------
__global__ __launch_bounds__(256, 1)
void ctx_mma_kernel(const float* __restrict__ enc, const float* __restrict__ b_ih,
                    const float* __restrict__ b_hh, const float* __restrict__ fc_b) {
    extern __shared__ char smraw[];
    char* sm = smraw;
    uint32_t smb = smem_u32(sm);
    const int t = threadIdx.x, lane = t & 31, warp = t >> 5;
    const int wy = warp >> 2, wx = warp & 3;
    const int cta = blockIdx.x;

    packA<256>(sm, enc + (size_t)cta * CROWS * HHD, t);
    __syncthreads();
    float acc[32];
#pragma unroll 1
    for (int tl = 0; tl < 13; ++tl) {
        compute_tile_f256(g_ctxpack + (size_t)tl * 8 * 16384, acc, smb, wy, wx, lane, t);
#pragma unroll
        for (int mt = 0; mt < 2; ++mt)
#pragma unroll
            for (int nt = 0; nt < 4; ++nt)
#pragma unroll
                for (int hh = 0; hh < 2; ++hh) {
                    int row = wy * 32 + mt * 16 + (lane >> 2) + hh * 8;
                    int ng = cta * CROWS + row;
                    int jcol = wx * 32 + nt * 8 + (lane & 3) * 2;
                    int base = (mt * 4 + nt) * 4 + hh * 2;
                    if (tl < 12) {
                        int j = tl * 128 + jcol;           // global row in [0,1536)
                        float2 bi = *(const float2*)(b_ih + j);
                        float b0 = bi.x, b1 = bi.y;
                        if (j < 1024) {
                            float2 bh = *(const float2*)(b_hh + j);
                            b0 += bh.x; b1 += bh.y;
                        }
                        float v0 = acc[base] + b0;
                        float v1 = acc[base + 1] + b1;
                        int g = j >> 9, jj = j & 511;
                        uint32_t pk = (uint32_t)__half_as_ushort(__float2half(v0))
                                    | ((uint32_t)__half_as_ushort(__float2half(v1)) << 16);
                        *(uint32_t*)((char*)g_gctxP
                            + ((size_t)ng * 256 + (jj >> 1)) * 16 + g * 4) = pk;
                    } else {
                        float2 fb = *(const float2*)(fc_b + jcol);
                        float2 v;
                        v.x = acc[base] + fb.x;
                        v.y = acc[base + 1] + fb.y;
                        *(float2*)(g_fcctx + (size_t)ng * VV + jcol) = v;
                    }
                }
    }
}

// ---------------- persistent decode kernel (512 threads) ----------------
__global__ __launch_bounds__(512, 1)
void decode_kernel(const float* __restrict__ encoded, const int* __restrict__ init_char,
                   const float* __restrict__ b_hh, float* __restrict__ out) {
    extern __shared__ char smraw[];
    char* sm = smraw;
    uint32_t smb = smem_u32(sm);
    const int t = threadIdx.x, lane = t & 31, warp = t >> 5;
    const int wy = warp >> 2, wx = warp & 3;
    const int cta = blockIdx.x;
    int* sch = (int*)(sm + SM_SCH);
    float* sbhn = (float*)(sm + SM_BHN);
    float* sargv = (float*)(sm + SM_ARGV);
    int* sargi = (int*)(sm + SM_ARGI);
    char* ghs = g_hsplit + (size_t)cta * A_BYTES;

    if (t < 512) sbhn[t] = b_hh[1024 + t];
    if (t < CROWS) sch[t] = init_char[cta * CROWS + t];
    packA<512>(sm, encoded + (size_t)cta * CROWS * HHD, t);
    __syncthreads();

    for (int step = 0; step < SSTEPS; ++step) {
        float accr[16], accz[16], accn[16];
        // prologue: 3 chunks, 3 groups (prefetch distance 3)
        copy_g<512>(smb, 0, g_wpack, t);
        asm volatile("cp.async.commit_group;" ::: "memory");
        copy_g<512>(smb, 1, g_wpack + 8192, t);
        asm volatile("cp.async.commit_group;" ::: "memory");
        copy_g<512>(smb, 2, g_wpack + 16384, t);
        asm volatile("cp.async.commit_group;" ::: "memory");
#pragma unroll 1
        for (int jt = 0; jt < 4; ++jt) {
            gate_tile512(accr, (jt * 3 + 0) * 8, smb, wy, wx, lane, t);
            gate_tile512(accz, (jt * 3 + 1) * 8, smb, wy, wx, lane, t);
            gate_tile512(accn, (jt * 3 + 2) * 8, smb, wy, wx, lane, t);
            // ---- gate epilogue: packed fp16 operand loads ----
#pragma unroll
            for (int nt = 0; nt < 4; ++nt)
#pragma unroll
                for (int hh = 0; hh < 2; ++hh) {
                    int row = wy * 16 + (lane >> 2) + hh * 8;
                    int jcol = jt * 128 + wx * 32 + nt * 8 + (lane & 3) * 2;
                    int jp = jcol >> 1;
                    int ng = cta * CROWS + row;
                    int cc = sch[row];
                    uint4 gq = *(const uint4*)(g_gctxP + ((size_t)ng * 256 + jp) * 8);
                    uint4 eq = *(const uint4*)(g_embgiP + ((size_t)cc * 256 + jp) * 8);
                    float2 gr = __half22float2(*(const __half2*)&gq.x);
                    float2 gz = __half22float2(*(const __half2*)&gq.y);
                    float2 gn = __half22float2(*(const __half2*)&gq.z);
                    float2 er = __half22float2(*(const __half2*)&eq.x);
                    float2 ez = __half22float2(*(const __half2*)&eq.y);
                    float2 en = __half22float2(*(const __half2*)&eq.z);
                    const char* ha = sm + SM_A + (row * 520 + jcol) * 2;
                    __half2 hv = *(const __half2*)ha;
                    __half2 lv = *(const __half2*)(ha + A_SPLIT);
                    float ho0 = __half2float(__low2half(hv)) + __half2float(__low2half(lv));
                    float ho1 = __half2float(__high2half(hv)) + __half2float(__high2half(lv));
                    int base2 = nt * 4 + hh * 2;
                    float pr0 = gr.x + er.x + accr[base2];
                    float pr1 = gr.y + er.y + accr[base2 + 1];
                    float pz0 = gz.x + ez.x + accz[base2];
                    float pz1 = gz.y + ez.y + accz[base2 + 1];
                    float hn0 = accn[base2] + sbhn[jcol];
                    float hn1 = accn[base2 + 1] + sbhn[jcol + 1];
                    float r0 = fast_sigmoid(pr0);
                    float r1 = fast_sigmoid(pr1);
                    float z0 = fast_sigmoid(pz0);
                    float z1 = fast_sigmoid(pz1);
                    float n0 = fast_tanh(gn.x + en.x + r0 * hn0);
                    float n1 = fast_tanh(gn.y + en.y + r1 * hn1);
                    float hnew0 = (1.f - z0) * n0 + z0 * ho0;
                    float hnew1 = (1.f - z1) * n1 + z1 * ho1;
                    unsigned short hh0, ll0, hh1, ll1;
                    hsplit(hnew0, hh0, ll0);
                    hsplit(hnew1, hh1, ll1);
                    char* gb = ghs + (row * 520 + jcol) * 2;
                    *(uint32_t*)gb = (uint32_t)hh0 | ((uint32_t)hh1 << 16);
                    *(uint32_t*)(gb + A_SPLIT) = (uint32_t)ll0 | ((uint32_t)ll1 << 16);
                }
        }
        __syncthreads();
        // ---- A refresh fused with fc pipeline ----
        copyA_async<512>(smb, ghs, t);
        copy_chunk2<512>(smb, 0, g_fcpack, t);
        asm volatile("cp.async.commit_group;" ::: "memory");
        float accf[16];
#pragma unroll
        for (int i = 0; i < 16; ++i) accf[i] = 0.f;
#pragma unroll 1
        for (int kc = 0; kc < 8; ++kc) {
            asm volatile("cp.async.wait_group 0;" ::: "memory");
            __syncthreads();
            if (kc < 7) {
                copy_chunk2<512>(smb, (kc + 1) & 1, g_fcpack + (size_t)(kc + 1) * 16384, t);
                asm volatile("cp.async.commit_group;" ::: "memory");
            }
            mma_chunk_f512(smb, kc & 1, kc, wy, wx, lane, accf);
        }

        // ---- fc epilogue: logits, out, argmax ----
        float best[2]; int bidx[2];
#pragma unroll
        for (int s = 0; s < 2; ++s) { best[s] = -1e30f; bidx[s] = 0; }
#pragma unroll
        for (int hh = 0; hh < 2; ++hh) {
            int row = wy * 16 + (lane >> 2) + hh * 8;
            int ng = cta * CROWS + row;
            int cc = sch[row];
#pragma unroll
            for (int nt = 0; nt < 4; ++nt) {
                int v = wx * 32 + nt * 8 + (lane & 3) * 2;
                int base2 = nt * 4 + hh * 2;
                float2 fc = *(const float2*)(g_fcctx + (size_t)ng * VV + v);
                float2 fe = *(const float2*)(g_fcemb + (size_t)cc * VV + v);
                float p0 = accf[base2] + fc.x + fe.x;
                float p1 = accf[base2 + 1] + fc.y + fe.y;
                float2 pv; pv.x = p0; pv.y = p1;
                *(float2*)(out + ((size_t)ng * SSTEPS + step) * VV + v) = pv;
                if (p0 > best[hh]) { best[hh] = p0; bidx[hh] = v; }
                if (p1 > best[hh]) { best[hh] = p1; bidx[hh] = v + 1; }
            }
        }
#pragma unroll
        for (int s = 0; s < 2; ++s) {
#pragma unroll
            for (int off = 1; off <= 2; off <<= 1) {
                float ov = __shfl_xor_sync(0xffffffffu, best[s], off);
                int oi = __shfl_xor_sync(0xffffffffu, bidx[s], off);
                if (ov > best[s] || (ov == best[s] && oi < bidx[s])) { best[s] = ov; bidx[s] = oi; }
            }
        }
        if ((lane & 3) == 0) {
#pragma unroll
            for (int s = 0; s < 2; ++s) {
                int row = wy * 16 + (lane >> 2) + s * 8;
                sargv[row * 4 + wx] = best[s];
                sargi[row * 4 + wx] = bidx[s];
            }
        }
        __syncthreads();
        if (t < CROWS) {
            float bv = sargv[t * 4]; int bi = sargi[t * 4];
#pragma unroll
            for (int wxi = 1; wxi < 4; ++wxi) {
                float ov = sargv[t * 4 + wxi]; int oi = sargi[t * 4 + wxi];
                if (ov > bv || (ov == bv && oi < bi)) { bv = ov; bi = oi; }
            }
            sch[t] = bi;
        }
        __syncthreads();
    }
}

// ---------------------------------------------------------------------------
extern "C" void kernel_launch(void* const* d_in, const int* in_sizes, int n_in,
                              void* d_out, int out_size) {
    const float *encoded = 0, *emb_table = 0, *W_ih = 0, *W_hh = 0,
                *b_ih = 0, *b_hh = 0, *fc_W = 0, *fc_b = 0;
    const int* init_char = 0;
    for (int i = 0; i < n_in; ++i) {
        switch (in_sizes[i]) {
            case 8192 * 512:  encoded   = (const float*)d_in[i]; break;
            case 8192:        init_char = (const int*)d_in[i];   break;
            case 128 * 128:   emb_table = (const float*)d_in[i]; break;
            case 1536 * 640:  W_ih      = (const float*)d_in[i]; break;
            case 1536 * 512:  W_hh      = (const float*)d_in[i]; break;
            case 1536:        if (!b_ih) b_ih = (const float*)d_in[i];
                              else       b_hh = (const float*)d_in[i]; break;
            case 128 * 1152:  fc_W      = (const float*)d_in[i]; break;
            case 128:         fc_b      = (const float*)d_in[i]; break;
            default: break;
        }
    }
    float* out = (float*)d_out;

    cudaFuncSetAttribute(ctx_mma_kernel, cudaFuncAttributeMaxDynamicSharedMemorySize, SMEM_TOT);
    cudaFuncSetAttribute(decode_kernel, cudaFuncAttributeMaxDynamicSharedMemorySize, SMEM_TOT);

    pack_w_kernel<<<(G3 * HHD + 255) / 256, 256>>>(W_hh);
    pack_fc_kernel<<<(VV * HHD + 255) / 256, 256>>>(fc_W);
    pack_ctx_kernel<<<(1664 * 512 + 255) / 256, 256>>>(W_ih, fc_W);
    emb_kernel<<<dim3(13, 128), 128>>>(emb_table, W_ih, fc_W);
    ctx_mma_kernel<<<NCTA, 256, SMEM_TOT>>>(encoded, b_ih, b_hh, fc_b);
    decode_kernel<<<NCTA, 512, SMEM_TOT>>>(encoded, init_char, b_hh, out);
}

// round 16
// speedup vs baseline: 1.5743x; 1.0130x over previous
#include <cuda_runtime.h>
#include <cuda_fp16.h>
#include <math.h>
#include <stdint.h>

#define NS 8192
#define HHD 512
#define G3 1536
#define EE 128
#define VV 128
#define SSTEPS 32
#define NCTA 128
#define CROWS 64

// smem byte offsets
#define SM_A 0
#define A_SPLIT 66560
#define A_BYTES 133120
#define SM_B 133120            // B region (73728 B): 6 gate stages of 10240, or 2 fc stages of 18432
#define G_STG 10240
#define B_BUF 36864
#define B_SPL 18432
#define SM_BHN 206848
#define SM_SCH 208896
#define SM_ARGV 209152
#define SM_ARGI 210176
#define SMEM_TOT 211200

// ---------------- persistent device scratch ----------------
__device__ __align__(128) __half g_gctxP[(size_t)NS * 256 * 8];   // packed {r0,r1,z0,z1,n0,n1,_,_}
__device__ __align__(128) __half g_embgiP[VV * 256 * 8];
__device__ float g_fcctx[(size_t)NS * VV];
__device__ float g_fcemb[VV * VV];
__device__ __align__(128) char g_hsplit[(size_t)NCTA * A_BYTES];
__device__ __align__(128) __half g_wpack[4 * 16 * 3 * 4096];      // [jt][kc32][gate][n128][k32]
__device__ __align__(128) __half g_fcpack[8 * 2 * 8192];
__device__ __align__(128) __half g_ctxpack[13 * 8 * 2 * 8192];

// ---------------- small helpers ----------------
__device__ __forceinline__ uint32_t smem_u32(const void* p) {
    uint32_t a;
    asm("{ .reg .u64 t; cvta.to.shared.u64 t, %1; cvt.u32.u64 %0, t; }" : "=r"(a) : "l"(p));
    return a;
}
__device__ __forceinline__ void ldsm4(uint32_t addr, uint32_t r[4]) {
    asm volatile("ldmatrix.sync.aligned.m8n8.x4.shared.b16 {%0,%1,%2,%3}, [%4];"
        : "=r"(r[0]), "=r"(r[1]), "=r"(r[2]), "=r"(r[3]) : "r"(addr));
}
__device__ __forceinline__ void mma16816(float* c, const uint32_t a[4], const uint32_t b[2]) {
    asm volatile("mma.sync.aligned.m16n8k16.row.col.f32.f16.f16.f32 "
        "{%0,%1,%2,%3}, {%4,%5,%6,%7}, {%8,%9}, {%0,%1,%2,%3};"
        : "+f"(c[0]), "+f"(c[1]), "+f"(c[2]), "+f"(c[3])
        : "r"(a[0]), "r"(a[1]), "r"(a[2]), "r"(a[3]), "r"(b[0]), "r"(b[1]));
}
__device__ __forceinline__ void cp16(uint32_t dst, const void* src) {
    asm volatile("cp.async.cg.shared.global [%0], [%1], 16;" :: "r"(dst), "l"(src));
}
__device__ __forceinline__ void hsplit(float v, unsigned short& h, unsigned short& l) {
    __half hh = __float2half(v);
    __half hl = __float2half(v - __half2float(hh));
    h = __half_as_ushort(hh);
    l = __half_as_ushort(hl);
}
__device__ __forceinline__ float fast_sigmoid(float x) {
    return __fdividef(1.f, 1.f + __expf(-x));
}
__device__ __forceinline__ float fast_tanh(float y) {
    float a = fabsf(y);
    float e = __expf(-2.f * a);
    return copysignf(__fdividef(1.f - e, 1.f + e), y);
}

// ---------------- prep kernels ----------------
// W_hh -> [jt][kc32][gate][n][k32] panels (4096 halves each)
__global__ void pack_w_kernel(const float* __restrict__ W_hh) {
    int idx = blockIdx.x * 256 + threadIdx.x;
    if (idx >= G3 * HHD) return;
    int R = idx >> 9, C = idx & 511;
    int g = R >> 9, jt = (R & 511) >> 7, n = R & 127;
    int kc = C >> 5, k = C & 31;
    size_t dst = (((size_t)(jt * 16 + kc) * 3 + g) * 4096) + n * 32 + k;
    g_wpack[dst] = __float2half(W_hh[idx]);
}

__global__ void pack_fc_kernel(const float* __restrict__ fc_W) {
    int idx = blockIdx.x * 256 + threadIdx.x;
    if (idx >= VV * HHD) return;
    int v = idx >> 9, C = idx & 511;
    int kc = C >> 6, k = C & 63;
    unsigned short h, l;
    hsplit(fc_W[(size_t)v * 1152 + 640 + C], h, l);
    size_t base = ((size_t)kc * 2) * 8192 + v * 64 + k;
    g_fcpack[base] = __ushort_as_half(h);
    g_fcpack[base + 8192] = __ushort_as_half(l);
}

__global__ void pack_ctx_kernel(const float* __restrict__ W_ih,
                                const float* __restrict__ fc_W) {
    int idx = blockIdx.x * 256 + threadIdx.x;
    if (idx >= 1664 * 512) return;
    int r = idx >> 9, k = idx & 511;
    float w = (r < G3) ? W_ih[(size_t)r * 640 + 128 + k]
                       : fc_W[(size_t)(r - G3) * 1152 + 128 + k];
    int tl = r >> 7, n = r & 127, kc = k >> 6, kk = k & 63;
    unsigned short h, l;
    hsplit(w, h, l);
    size_t base = ((size_t)(tl * 8 + kc) * 2) * 8192 + n * 64 + kk;
    g_ctxpack[base] = __ushort_as_half(h);
    g_ctxpack[base + 8192] = __ushort_as_half(l);
}

__global__ __launch_bounds__(128)
void emb_kernel(const float* __restrict__ emb_table,
                const float* __restrict__ W_ih,
                const float* __restrict__ fc_W) {
    __shared__ float er[EE];
    int c = blockIdx.y;
    int tx = threadIdx.x;
    er[tx] = emb_table[c * EE + tx];
    __syncthreads();
    int col = blockIdx.x * 128 + tx;
    const float* brow = (col < G3) ? (W_ih + (size_t)col * 640)
                                   : (fc_W + (size_t)(col - G3) * 1152);
    float acc = 0.f;
#pragma unroll 8
    for (int e = 0; e < EE; e += 4) {
        float4 b = *reinterpret_cast<const float4*>(brow + e);
        acc += er[e] * b.x + er[e + 1] * b.y + er[e + 2] * b.z + er[e + 3] * b.w;
    }
    if (col < G3) {
        int g = col >> 9, j = col & 511;
        g_embgiP[((size_t)c * 256 + (j >> 1)) * 8 + g * 2 + (j & 1)] = __float2half(acc);
    } else {
        g_fcemb[c * VV + (col - G3)] = acc;
    }
}

// ---------------- copy helpers ----------------
template<int NT>
__device__ __forceinline__ void copy_16k(uint32_t dbase, const char* s, int t) {
#pragma unroll
    for (int i = 0; i < 1024 / NT; ++i) {
        int u = t + i * NT;
        int n = u >> 3, c = u & 7;
        cp16(dbase + n * 144 + c * 16, s + (size_t)u * 16);
    }
}
template<int NT>
__device__ __forceinline__ void copy_chunk2(uint32_t smb, int buf, const __half* src, int t) {
    copy_16k<NT>(smb + SM_B + buf * B_BUF, (const char*)src, t);
    copy_16k<NT>(smb + SM_B + buf * B_BUF + B_SPL, (const char*)(src + 8192), t);
}
// one 8KB gate panel (512 quanta, 80B rows) into stage
__device__ __forceinline__ void copy_panel512(uint32_t smb, int stage, const __half* src, int t) {
    if (t < 512) {
        int n = t >> 2, c = t & 3;
        cp16(smb + SM_B + stage * G_STG + n * 80 + c * 16,
             (const char*)src + (size_t)t * 16);
    }
}
// one chunk = 3 gate panels (indices c*3+g), stage = panel % 6
__device__ __forceinline__ void copy_chunk3(uint32_t smb, int c, int t) {
#pragma unroll
    for (int g = 0; g < 3; ++g) {
        int p = c * 3 + g;
        copy_panel512(smb, p % 6, g_wpack + (size_t)p * 4096, t);
    }
}
template<int NT>
__device__ __forceinline__ void copyA_async(uint32_t smb, const char* src, int t) {
#pragma unroll
    for (int i = 0; i <= 8320 / NT; ++i) {
        int u = t + i * NT;
        if (u < 8320) cp16(smb + SM_A + u * 16, src + (size_t)u * 16);
    }
}
template<int NT>
__device__ __forceinline__ void packA(char* sm, const float* __restrict__ src, int t) {
#pragma unroll 4
    for (int i = 0; i < 8192 / NT; ++i) {
        int idx = t + i * NT;
        int r = idx >> 7, kq = (idx & 127) * 4;
        float4 v = *(const float4*)(src + (size_t)r * HHD + kq);
        unsigned short h0, l0, h1, l1, h2, l2, h3, l3;
        hsplit(v.x, h0, l0); hsplit(v.y, h1, l1);
        hsplit(v.z, h2, l2); hsplit(v.w, h3, l3);
        char* d = sm + SM_A + (r * 520 + kq) * 2;
        *(uint32_t*)d = (uint32_t)h0 | ((uint32_t)h1 << 16);
        *(uint32_t*)(d + 4) = (uint32_t)h2 | ((uint32_t)h3 << 16);
        *(uint32_t*)(d + A_SPLIT) = (uint32_t)l0 | ((uint32_t)l1 << 16);
        *(uint32_t*)(d + A_SPLIT + 4) = (uint32_t)l2 | ((uint32_t)l3 << 16);
    }
}

// ---------------- 256-thread mma (ctx kernel, unchanged) ----------------
__device__ __forceinline__ void mma_chunk_f256(uint32_t smb, int buf, int kc,
                                               int wy, int wx, int lane, float* acc) {
    uint32_t abase = smb + SM_A;
    uint32_t bbase = smb + SM_B + buf * B_BUF;
    int arow = wy * 32 + (lane & 7) + ((lane >> 3) & 1) * 8;
    int akoff = ((lane >> 4) & 1) * 8;
    int brow = wx * 32 + ((lane >> 4) & 1) * 8 + (lane & 7);
    int bkoff = ((lane >> 3) & 1) * 8;
#pragma unroll
    for (int ks = 0; ks < 4; ++ks) {
        int kA = kc * 64 + ks * 16 + akoff;
        uint32_t ahi[2][4], alo[2][4];
#pragma unroll
        for (int mt = 0; mt < 2; ++mt) {
            uint32_t ad = abase + ((arow + mt * 16) * 520 + kA) * 2;
            ldsm4(ad, ahi[mt]);
            ldsm4(ad + A_SPLIT, alo[mt]);
        }
        uint32_t bhi[4][2], blo[4][2];
#pragma unroll
        for (int p = 0; p < 2; ++p) {
            uint32_t bd = bbase + ((brow + p * 16) * 72 + ks * 16 + bkoff) * 2;
            uint32_t r4[4];
            ldsm4(bd, r4);
            bhi[2 * p][0] = r4[0]; bhi[2 * p][1] = r4[1];
            bhi[2 * p + 1][0] = r4[2]; bhi[2 * p + 1][1] = r4[3];
            ldsm4(bd + B_SPL, r4);
            blo[2 * p][0] = r4[0]; blo[2 * p][1] = r4[1];
            blo[2 * p + 1][0] = r4[2]; blo[2 * p + 1][1] = r4[3];
        }
#pragma unroll
        for (int mt = 0; mt < 2; ++mt)
#pragma unroll
            for (int nt = 0; nt < 4; ++nt)
                mma16816(acc + (mt * 4 + nt) * 4, ahi[mt], bhi[nt]);
#pragma unroll
        for (int mt = 0; mt < 2; ++mt)
#pragma unroll
            for (int nt = 0; nt < 4; ++nt)
                mma16816(acc + (mt * 4 + nt) * 4, ahi[mt], blo[nt]);
#pragma unroll
        for (int mt = 0; mt < 2; ++mt)
#pragma unroll
            for (int nt = 0; nt < 4; ++nt)
                mma16816(acc + (mt * 4 + nt) * 4, alo[mt], bhi[nt]);
    }
}

__device__ __forceinline__ void compute_tile_f256(const __half* Bsrc, float* acc,
                                                  uint32_t smb, int wy, int wx, int lane, int t) {
#pragma unroll
    for (int i = 0; i < 32; ++i) acc[i] = 0.f;
    copy_chunk2<256>(smb, 0, Bsrc, t);
    asm volatile("cp.async.commit_group;" ::: "memory");
#pragma unroll 1
    for (int kc = 0; kc < 8; ++kc) {
        if (kc < 7) {
            copy_chunk2<256>(smb, (kc + 1) & 1, Bsrc + (size_t)(kc + 1) * 16384, t);
            asm volatile("cp.async.commit_group;" ::: "memory");
            asm volatile("cp.async.wait_group 1;" ::: "memory");
        } else {
            asm volatile("cp.async.wait_group 0;" ::: "memory");
        }
        __syncthreads();
        mma_chunk_f256(smb, kc & 1, kc, wy, wx, lane, acc);
        __syncthreads();
    }
}

// ---------------- 512-thread fused gate mma ----------------
// inner: 2 B-ldsm + 4 HMMA into one statically-bound acc
__device__ __forceinline__ void gate_bmma(uint32_t bbase, int brow, int koff,
                                          const uint32_t ahi[4], float* acc) {
    uint32_t b[4][2];
#pragma unroll
    for (int p = 0; p < 2; ++p) {
        uint32_t bd = bbase + (brow + p * 16) * 80 + koff * 2;
        uint32_t r4[4];
        ldsm4(bd, r4);
        b[2 * p][0] = r4[0]; b[2 * p][1] = r4[1];
        b[2 * p + 1][0] = r4[2]; b[2 * p + 1][1] = r4[3];
    }
#pragma unroll
    for (int nt = 0; nt < 4; ++nt)
        mma16816(acc + nt * 4, ahi, b[nt]);
}

// one 32-K chunk: A loaded once per ks, 3 gate B panels
__device__ __forceinline__ void mma_fused_chunk(uint32_t smb, int uc, int kc,
                                                int wy, int wx, int lane,
                                                float* accr, float* accz, float* accn) {
    uint32_t abase = smb + SM_A;
    int arow = wy * 16 + (lane & 7) + ((lane >> 3) & 1) * 8;
    int akoff = ((lane >> 4) & 1) * 8;
    int brow = wx * 32 + ((lane >> 4) & 1) * 8 + (lane & 7);
    int bkoff = ((lane >> 3) & 1) * 8;
    uint32_t b0 = smb + SM_B + ((uc * 3    ) % 6) * G_STG;
    uint32_t b1 = smb + SM_B + ((uc * 3 + 1) % 6) * G_STG;
    uint32_t b2 = smb + SM_B + ((uc * 3 + 2) % 6) * G_STG;
#pragma unroll
    for (int ks = 0; ks < 2; ++ks) {
        int kA = kc * 32 + ks * 16 + akoff;
        int koff = ks * 16 + bkoff;
        uint32_t ahi[4];
        ldsm4(abase + (arow * 520 + kA) * 2, ahi);
        gate_bmma(b0, brow, koff, ahi, accr);
        gate_bmma(b1, brow, koff, ahi, accz);
        gate_bmma(b2, brow, koff, ahi, accn);
    }
}

// fc: full 3-product (argmax-critical)
__device__ __forceinline__ void mma_chunk_f512(uint32_t smb, int buf, int kc,
                                               int wy, int wx, int lane, float* acc) {
    uint32_t abase = smb + SM_A;
    uint32_t bbase = smb + SM_B + buf * B_BUF;
    int arow = wy * 16 + (lane & 7) + ((lane >> 3) & 1) * 8;
    int akoff = ((lane >> 4) & 1) * 8;
    int brow = wx * 32 + ((lane >> 4) & 1) * 8 + (lane & 7);
    int bkoff = ((lane >> 3) & 1) * 8;
#pragma unroll
    for (int ks = 0; ks < 4; ++ks) {
        int kA = kc * 64 + ks * 16 + akoff;
        uint32_t ahi[4], alo[4];
        uint32_t ad = abase + (arow * 520 + kA) * 2;
        ldsm4(ad, ahi);
        ldsm4(ad + A_SPLIT, alo);
        uint32_t bhi[4][2], blo[4][2];
#pragma unroll
        for (int p = 0; p < 2; ++p) {
            uint32_t bd = bbase + ((brow + p * 16) * 72 + ks * 16 + bkoff) * 2;
            uint32_t r4[4];
            ldsm4(bd, r4);
            bhi[2 * p][0] = r4[0]; bhi[2 * p][1] = r4[1];
            bhi[2 * p + 1][0] = r4[2]; bhi[2 * p + 1][1] = r4[3];
            ldsm4(bd + B_SPL, r4);
            blo[2 * p][0] = r4[0]; blo[2 * p][1] = r4[1];
            blo[2 * p + 1][0] = r4[2]; blo[2 * p + 1][1] = r4[3];
        }
#pragma unroll
        for (int nt = 0; nt < 4; ++nt)
            mma16816(acc + nt * 4, ahi, bhi[nt]);
#pragma unroll
        for (int nt = 0; nt < 4; ++nt)
            mma16816(acc + nt * 4, ahi, blo[nt]);
#pragma unroll
        for (int nt = 0; nt < 4; ++nt)
            mma16816(acc + nt * 4, alo, bhi[nt]);
    }
}

// ---------------- ctx via HMMA (writes packed gctx) ----------------
__global__ __launch_bounds__(256, 1)
void ctx_mma_kernel(const float* __restrict__ enc, const float* __restrict__ b_ih,
                    const float* __restrict__ b_hh, const float* __restrict__ fc_b) {
    extern __shared__ char smraw[];
    char* sm = smraw;
    uint32_t smb = smem_u32(sm);
    const int t = threadIdx.x, lane = t & 31, warp = t >> 5;
    const int wy = warp >> 2, wx = warp & 3;
    const int cta = blockIdx.x;

    packA<256>(sm, enc + (size_t)cta * CROWS * HHD, t);
    __syncthreads();
    float acc[32];
#pragma unroll 1
    for (int tl = 0; tl < 13; ++tl) {
        compute_tile_f256(g_ctxpack + (size_t)tl * 8 * 16384, acc, smb, wy, wx, lane, t);
#pragma unroll
        for (int mt = 0; mt < 2; ++mt)
#pragma unroll
            for (int nt = 0; nt < 4; ++nt)
#pragma unroll
                for (int hh = 0; hh < 2; ++hh) {
                    int row = wy * 32 + mt * 16 + (lane >> 2) + hh * 8;
                    int ng = cta * CROWS + row;
                    int jcol = wx * 32 + nt * 8 + (lane & 3) * 2;
                    int base = (mt * 4 + nt) * 4 + hh * 2;
                    if (tl < 12) {
                        int j = tl * 128 + jcol;
                        float2 bi = *(const float2*)(b_ih + j);
                        float b0 = bi.x, b1 = bi.y;
                        if (j < 1024) {
                            float2 bh = *(const float2*)(b_hh + j);
                            b0 += bh.x; b1 += bh.y;
                        }
                        float v0 = acc[base] + b0;
                        float v1 = acc[base + 1] + b1;
                        int g = j >> 9, jj = j & 511;
                        uint32_t pk = (uint32_t)__half_as_ushort(__float2half(v0))
                                    | ((uint32_t)__half_as_ushort(__float2half(v1)) << 16);
                        *(uint32_t*)((char*)g_gctxP
                            + ((size_t)ng * 256 + (jj >> 1)) * 16 + g * 4) = pk;
                    } else {
                        float2 fb = *(const float2*)(fc_b + jcol);
                        float2 v;
                        v.x = acc[base] + fb.x;
                        v.y = acc[base + 1] + fb.y;
                        *(float2*)(g_fcctx + (size_t)ng * VV + jcol) = v;
                    }
                }
    }
}

// ---------------- persistent decode kernel (512 threads) ----------------
__global__ __launch_bounds__(512, 1)
void decode_kernel(const float* __restrict__ encoded, const int* __restrict__ init_char,
                   const float* __restrict__ b_hh, float* __restrict__ out) {
    extern __shared__ char smraw[];
    char* sm = smraw;
    uint32_t smb = smem_u32(sm);
    const int t = threadIdx.x, lane = t & 31, warp = t >> 5;
    const int wy = warp >> 2, wx = warp & 3;
    const int cta = blockIdx.x;
    int* sch = (int*)(sm + SM_SCH);
    float* sbhn = (float*)(sm + SM_BHN);
    float* sargv = (float*)(sm + SM_ARGV);
    int* sargi = (int*)(sm + SM_ARGI);
    char* ghs = g_hsplit + (size_t)cta * A_BYTES;

    if (t < 512) sbhn[t] = b_hh[1024 + t];
    if (t < CROWS) sch[t] = init_char[cta * CROWS + t];
    packA<512>(sm, encoded + (size_t)cta * CROWS * HHD, t);
    __syncthreads();

    for (int step = 0; step < SSTEPS; ++step) {
        float accr[16], accz[16], accn[16];
        // prologue: chunk 0 (3 panels), one group
        copy_chunk3(smb, 0, t);
        asm volatile("cp.async.commit_group;" ::: "memory");
#pragma unroll 1
        for (int jt = 0; jt < 4; ++jt) {
#pragma unroll
            for (int i = 0; i < 16; ++i) { accr[i] = 0.f; accz[i] = 0.f; accn[i] = 0.f; }
#pragma unroll 1
            for (int kc = 0; kc < 16; ++kc) {
                int uc = jt * 16 + kc;
                asm volatile("cp.async.wait_group 0;" ::: "memory");
                __syncthreads();
                if (uc < 63) {
                    copy_chunk3(smb, uc + 1, t);
                    asm volatile("cp.async.commit_group;" ::: "memory");
                }
                mma_fused_chunk(smb, uc, kc, wy, wx, lane, accr, accz, accn);
            }
            // ---- gate epilogue: packed fp16 operands, split h_new to gmem mirror ----
#pragma unroll
            for (int nt = 0; nt < 4; ++nt)
#pragma unroll
                for (int hh = 0; hh < 2; ++hh) {
                    int row = wy * 16 + (lane >> 2) + hh * 8;
                    int jcol = jt * 128 + wx * 32 + nt * 8 + (lane & 3) * 2;
                    int jp = jcol >> 1;
                    int ng = cta * CROWS + row;
                    int cc = sch[row];
                    uint4 gq = *(const uint4*)(g_gctxP + ((size_t)ng * 256 + jp) * 8);
                    uint4 eq = *(const uint4*)(g_embgiP + ((size_t)cc * 256 + jp) * 8);
                    float2 gr = __half22float2(*(const __half2*)&gq.x);
                    float2 gz = __half22float2(*(const __half2*)&gq.y);
                    float2 gn = __half22float2(*(const __half2*)&gq.z);
                    float2 er = __half22float2(*(const __half2*)&eq.x);
                    float2 ez = __half22float2(*(const __half2*)&eq.y);
                    float2 en = __half22float2(*(const __half2*)&eq.z);
                    const char* ha = sm + SM_A + (row * 520 + jcol) * 2;
                    __half2 hv = *(const __half2*)ha;
                    __half2 lv = *(const __half2*)(ha + A_SPLIT);
                    float ho0 = __half2float(__low2half(hv)) + __half2float(__low2half(lv));
                    float ho1 = __half2float(__high2half(hv)) + __half2float(__high2half(lv));
                    int base2 = nt * 4 + hh * 2;
                    float pr0 = gr.x + er.x + accr[base2];
                    float pr1 = gr.y + er.y + accr[base2 + 1];
                    float pz0 = gz.x + ez.x + accz[base2];
                    float pz1 = gz.y + ez.y + accz[base2 + 1];
                    float hn0 = accn[base2] + sbhn[jcol];
                    float hn1 = accn[base2 + 1] + sbhn[jcol + 1];
                    float r0 = fast_sigmoid(pr0);
                    float r1 = fast_sigmoid(pr1);
                    float z0 = fast_sigmoid(pz0);
                    float z1 = fast_sigmoid(pz1);
                    float n0 = fast_tanh(gn.x + en.x + r0 * hn0);
                    float n1 = fast_tanh(gn.y + en.y + r1 * hn1);
                    float hnew0 = (1.f - z0) * n0 + z0 * ho0;
                    float hnew1 = (1.f - z1) * n1 + z1 * ho1;
                    unsigned short hh0, ll0, hh1, ll1;
                    hsplit(hnew0, hh0, ll0);
                    hsplit(hnew1, hh1, ll1);
                    char* gb = ghs + (row * 520 + jcol) * 2;
                    *(uint32_t*)gb = (uint32_t)hh0 | ((uint32_t)hh1 << 16);
                    *(uint32_t*)(gb + A_SPLIT) = (uint32_t)ll0 | ((uint32_t)ll1 << 16);
                }
        }
        __syncthreads();
        // ---- A refresh fused with fc pipeline ----
        copyA_async<512>(smb, ghs, t);
        copy_chunk2<512>(smb, 0, g_fcpack, t);
        asm volatile("cp.async.commit_group;" ::: "memory");
        float accf[16];
#pragma unroll
        for (int i = 0; i < 16; ++i) accf[i] = 0.f;
#pragma unroll 1
        for (int kc = 0; kc < 8; ++kc) {
            asm volatile("cp.async.wait_group 0;" ::: "memory");
            __syncthreads();
            if (kc < 7) {
                copy_chunk2<512>(smb, (kc + 1) & 1, g_fcpack + (size_t)(kc + 1) * 16384, t);
                asm volatile("cp.async.commit_group;" ::: "memory");
            }
            mma_chunk_f512(smb, kc & 1, kc, wy, wx, lane, accf);
        }

        // ---- fc epilogue: logits, out, argmax ----
        float best[2]; int bidx[2];
#pragma unroll
        for (int s = 0; s < 2; ++s) { best[s] = -1e30f; bidx[s] = 0; }
#pragma unroll
        for (int hh = 0; hh < 2; ++hh) {
            int row = wy * 16 + (lane >> 2) + hh * 8;
            int ng = cta * CROWS + row;
            int cc = sch[row];
#pragma unroll
            for (int nt = 0; nt < 4; ++nt) {
                int v = wx * 32 + nt * 8 + (lane & 3) * 2;
                int base2 = nt * 4 + hh * 2;
                float2 fc = *(const float2*)(g_fcctx + (size_t)ng * VV + v);
                float2 fe = *(const float2*)(g_fcemb + (size_t)cc * VV + v);
                float p0 = accf[base2] + fc.x + fe.x;
                float p1 = accf[base2 + 1] + fc.y + fe.y;
                float2 pv; pv.x = p0; pv.y = p1;
                *(float2*)(out + ((size_t)ng * SSTEPS + step) * VV + v) = pv;
                if (p0 > best[hh]) { best[hh] = p0; bidx[hh] = v; }
                if (p1 > best[hh]) { best[hh] = p1; bidx[hh] = v + 1; }
            }
        }
#pragma unroll
        for (int s = 0; s < 2; ++s) {
#pragma unroll
            for (int off = 1; off <= 2; off <<= 1) {
                float ov = __shfl_xor_sync(0xffffffffu, best[s], off);
                int oi = __shfl_xor_sync(0xffffffffu, bidx[s], off);
                if (ov > best[s] || (ov == best[s] && oi < bidx[s])) { best[s] = ov; bidx[s] = oi; }
            }
        }
        if ((lane & 3) == 0) {
#pragma unroll
            for (int s = 0; s < 2; ++s) {
                int row = wy * 16 + (lane >> 2) + s * 8;
                sargv[row * 4 + wx] = best[s];
                sargi[row * 4 + wx] = bidx[s];
            }
        }
        __syncthreads();
        if (t < CROWS) {
            float bv = sargv[t * 4]; int bi = sargi[t * 4];
#pragma unroll
            for (int wxi = 1; wxi < 4; ++wxi) {
                float ov = sargv[t * 4 + wxi]; int oi = sargi[t * 4 + wxi];
                if (ov > bv || (ov == bv && oi < bi)) { bv = ov; bi = oi; }
            }
            sch[t] = bi;
        }
        __syncthreads();
    }
}

// ---------------------------------------------------------------------------
extern "C" void kernel_launch(void* const* d_in, const int* in_sizes, int n_in,
                              void* d_out, int out_size) {
    const float *encoded = 0, *emb_table = 0, *W_ih = 0, *W_hh = 0,
                *b_ih = 0, *b_hh = 0, *fc_W = 0, *fc_b = 0;
    const int* init_char = 0;
    for (int i = 0; i < n_in; ++i) {
        switch (in_sizes[i]) {
            case 8192 * 512:  encoded   = (const float*)d_in[i]; break;
            case 8192:        init_char = (const int*)d_in[i];   break;
            case 128 * 128:   emb_table = (const float*)d_in[i]; break;
            case 1536 * 640:  W_ih      = (const float*)d_in[i]; break;
            case 1536 * 512:  W_hh      = (const float*)d_in[i]; break;
            case 1536:        if (!b_ih) b_ih = (const float*)d_in[i];
                              else       b_hh = (const float*)d_in[i]; break;
            case 128 * 1152:  fc_W      = (const float*)d_in[i]; break;
            case 128:         fc_b      = (const float*)d_in[i]; break;
            default: break;
        }
    }
    float* out = (float*)d_out;

    cudaFuncSetAttribute(ctx_mma_kernel, cudaFuncAttributeMaxDynamicSharedMemorySize, SMEM_TOT);
    cudaFuncSetAttribute(decode_kernel, cudaFuncAttributeMaxDynamicSharedMemorySize, SMEM_TOT);

    pack_w_kernel<<<(G3 * HHD + 255) / 256, 256>>>(W_hh);
    pack_fc_kernel<<<(VV * HHD + 255) / 256, 256>>>(fc_W);
    pack_ctx_kernel<<<(1664 * 512 + 255) / 256, 256>>>(W_ih, fc_W);
    emb_kernel<<<dim3(13, 128), 128>>>(emb_table, W_ih, fc_W);
    ctx_mma_kernel<<<NCTA, 256, SMEM_TOT>>>(encoded, b_ih, b_hh, fc_b);
    decode_kernel<<<NCTA, 512, SMEM_TOT>>>(encoded, init_char, b_hh, out);
}